// round 7
// baseline (speedup 1.0000x reference)
#include <cuda_runtime.h>
#include <cuda_bf16.h>
#include <cstdint>

#define NB 16384
#define HD 768

// ---------------- scratch (device globals; no allocs allowed) ----------------
__device__ __nv_bfloat16 g_featbf[4 * NB * 768];
__device__ __nv_bfloat16 g_scrAbf[2 * NB * 768];     // cons1 / diff1 outputs (bf16)
__device__ __nv_bfloat16 g_scrCbf[4 * NB * 256];     // disc1 outputs (bf16)
__device__ float g_scrB[4 * NB * 384];               // imp1 / cons2 / diff2 outputs (fp32)
__device__ float g_scrC[2 * NB * 256];               // info1 outputs (fp32)
__device__ float g_scrD[4 * NB * 64];                // disc2 / info2 outputs (fp32)
__device__ float g_norm[2 * NB];
__device__ __nv_bfloat16 g_w_imp1[384 * 768];
__device__ __nv_bfloat16 g_w_disc1[256 * 768];
__device__ __nv_bfloat16 g_w_disc2[64 * 256];
__device__ __nv_bfloat16 g_w_cons1[768 * 1536];
__device__ __nv_bfloat16 g_w_cons2[384 * 768];
__device__ __nv_bfloat16 g_w_diff1[768 * 1536];
__device__ __nv_bfloat16 g_w_diff2[384 * 768];
__device__ float g_w_info1[256 * 768];
__device__ float g_w_info2[64 * 256];

__device__ __forceinline__ float sigf(float x) { return 1.0f / (1.0f + expf(-x)); }
__device__ __forceinline__ float geluf(float x) { return 0.5f * x * (1.0f + erff(x * 0.70710678118654752f)); }

__device__ __forceinline__ uint32_t smem_u32(const void* p) {
    uint32_t a;
    asm("{ .reg .u64 t; cvta.to.shared.u64 t, %1; cvt.u32.u64 %0, t; }" : "=r"(a) : "l"(p));
    return a;
}
__device__ __forceinline__ void mma_tf(float* d, const uint32_t* a, uint32_t b0, uint32_t b1) {
    asm volatile(
        "mma.sync.aligned.m16n8k8.row.col.f32.tf32.tf32.f32 "
        "{%0,%1,%2,%3}, {%4,%5,%6,%7}, {%8,%9}, {%0,%1,%2,%3};"
        : "+f"(d[0]), "+f"(d[1]), "+f"(d[2]), "+f"(d[3])
        : "r"(a[0]), "r"(a[1]), "r"(a[2]), "r"(a[3]), "r"(b0), "r"(b1));
}
__device__ __forceinline__ void mma_bf(float* d, const uint32_t* a, uint32_t b0, uint32_t b1) {
    asm volatile(
        "mma.sync.aligned.m16n8k16.row.col.f32.bf16.bf16.f32 "
        "{%0,%1,%2,%3}, {%4,%5,%6,%7}, {%8,%9}, {%0,%1,%2,%3};"
        : "+f"(d[0]), "+f"(d[1]), "+f"(d[2]), "+f"(d[3])
        : "r"(a[0]), "r"(a[1]), "r"(a[2]), "r"(a[3]), "r"(b0), "r"(b1));
}
#define LDSM4(r, addr) \
    asm volatile("ldmatrix.sync.aligned.m8n8.x4.shared.b16 {%0,%1,%2,%3}, [%4];" \
        : "=r"((r)[0]), "=r"((r)[1]), "=r"((r)[2]), "=r"((r)[3]) : "r"(addr))
#define CP_ASYNC16(dst, src) \
    asm volatile("cp.async.cg.shared.global [%0], [%1], 16;" :: "r"(dst), "l"(src))
#define CP_COMMIT() asm volatile("cp.async.commit_group;" ::: "memory")

__device__ __forceinline__ void split_tf32(uint32_t x, uint32_t& h, uint32_t& l) {
    h = x & 0xFFFFE000u;
    l = __float_as_uint(__uint_as_float(x) - __uint_as_float(h));
}

struct APtrs  { const float* p[4]; };
struct APtrsB { const __nv_bfloat16* p[4]; };

// ============ big-tile bf16 GEMM, two output regions ============
// BM=256, BN=128, 8 warps (4M x 2N), warp tile 64x64.
// Region 0: cols [0,N0)   -> fp32 C0 (ld N0), bias b0
// Region 1: cols [N0,N0+N1) -> bf16 C1 (ld N1), bias b1, weights Wt1
// Each CTA's 128-col span lies fully in one region (N0 % 128 == 0).
__global__ void __launch_bounds__(256, 1) gemm_big(
    APtrsB A, int Khalf, int Ktot,
    const __nv_bfloat16* __restrict__ Wt0, const __nv_bfloat16* __restrict__ Wt1,
    int N0, int N1, const float* __restrict__ b0, const float* __restrict__ b1,
    float* __restrict__ C0, __nv_bfloat16* __restrict__ C1, int act)
{
    constexpr int AW = 40;                   // bf16 elems per smem row (80 B)
    constexpr int ABYTES = 256 * AW * 2;
    constexpr int BBYTES = 128 * AW * 2;
    constexpr int STG = ABYTES + BBYTES;

    extern __shared__ char smem[];
    const int t = threadIdx.x, lane = t & 31, wid = t >> 5;
    const int batch = blockIdx.y >> 6;
    const int m0 = (blockIdx.y & 63) * 256;
    const int n0 = blockIdx.x * 128;
    const int wm = (wid & 3) * 64;
    const int wn = (wid >> 2) * 64;

    const bool r1 = (n0 >= N0);
    const __nv_bfloat16* Wt = r1 ? Wt1 : Wt0;
    const int nloc = n0 - (r1 ? N0 : 0);

    const __nv_bfloat16 *A1, *A2;
    if (Khalf < Ktot) { A1 = A.p[2 * batch]; A2 = A.p[2 * batch + 1]; }
    else              { A1 = A.p[batch];     A2 = A1; }

    const uint32_t sbase = smem_u32(smem);
    const uint32_t a_addr0 = sbase + (uint32_t)((wm + (lane & 15)) * (AW * 2) + (lane >> 4) * 16);
    const int grp = lane >> 3;
    const int b_r = (lane & 7) + ((grp >= 2) ? 8 : 0);
    const uint32_t b_addr0 = sbase + ABYTES + (uint32_t)((wn + b_r) * (AW * 2) + (grp & 1) * 16);

    float acc[4][8][4];
#pragma unroll
    for (int i = 0; i < 4; i++)
#pragma unroll
        for (int j = 0; j < 8; j++)
#pragma unroll
            for (int q = 0; q < 4; q++) acc[i][j][q] = 0.0f;

    auto load_chunk = [&](int c) {
        const int stg = c % 3;
        int kk = c * 32;
        const __nv_bfloat16* Ab = A1;
        if (kk >= Khalf) { Ab = A2; kk -= Khalf; }
        uint32_t sA = sbase + stg * STG;
#pragma unroll
        for (int i = 0; i < 4; i++) {               // A: 256 rows x 32 bf16 = 1024 x16B
            int idx = t + i * 256, r = idx >> 2, c8 = idx & 3;
            CP_ASYNC16(sA + (uint32_t)(r * (AW * 2) + c8 * 16),
                       Ab + (size_t)(m0 + r) * Khalf + kk + c8 * 8);
        }
        uint32_t sB = sA + ABYTES;
#pragma unroll
        for (int i = 0; i < 2; i++) {               // B: 128 rows x 32 bf16 = 512 x16B
            int idx = t + i * 256, r = idx >> 2, c8 = idx & 3;
            CP_ASYNC16(sB + (uint32_t)(r * (AW * 2) + c8 * 16),
                       Wt + (size_t)(nloc + r) * Ktot + c * 32 + c8 * 8);
        }
        CP_COMMIT();
    };

    const int NC = Ktot >> 5;
    load_chunk(0);
    if (NC > 1) load_chunk(1);

    for (int c = 0; c < NC; c++) {
        if (c + 1 < NC) { asm volatile("cp.async.wait_group 1;" ::: "memory"); }
        else            { asm volatile("cp.async.wait_group 0;" ::: "memory"); }
        __syncthreads();
        if (c + 2 < NC) load_chunk(c + 2);

        const uint32_t aa = a_addr0 + (c % 3) * STG;
        const uint32_t bb = b_addr0 + (c % 3) * STG;
#pragma unroll
        for (int kk = 0; kk < 2; kk++) {
            uint32_t Af[4][4];
#pragma unroll
            for (int mt = 0; mt < 4; mt++)
                LDSM4(Af[mt], aa + mt * 16 * (AW * 2) + kk * 32);
#pragma unroll
            for (int np = 0; np < 4; np++) {
                uint32_t B4[4];
                LDSM4(B4, bb + np * 16 * (AW * 2) + kk * 32);
#pragma unroll
                for (int mt = 0; mt < 4; mt++) {
                    mma_bf(acc[mt][2 * np],     Af[mt], B4[0], B4[1]);
                    mma_bf(acc[mt][2 * np + 1], Af[mt], B4[2], B4[3]);
                }
            }
        }
    }

    // epilogue
#pragma unroll
    for (int mt = 0; mt < 4; mt++) {
        size_t row = (size_t)batch * NB + m0 + wm + mt * 16 + (lane >> 2);
#pragma unroll
        for (int nt = 0; nt < 8; nt++) {
            int coll = nloc + wn + nt * 8 + (lane & 3) * 2;
            float bv0 = r1 ? __ldg(b1 + coll)     : __ldg(b0 + coll);
            float bv1 = r1 ? __ldg(b1 + coll + 1) : __ldg(b0 + coll + 1);
            float x0 = acc[mt][nt][0] + bv0, x1 = acc[mt][nt][1] + bv1;
            float x2 = acc[mt][nt][2] + bv0, x3 = acc[mt][nt][3] + bv1;
            if (act) { x0 = geluf(x0); x1 = geluf(x1); x2 = geluf(x2); x3 = geluf(x3); }
            if (r1) {
                *reinterpret_cast<__nv_bfloat162*>(C1 + row * N1 + coll) =
                    __floats2bfloat162_rn(x0, x1);
                *reinterpret_cast<__nv_bfloat162*>(C1 + (row + 8) * N1 + coll) =
                    __floats2bfloat162_rn(x2, x3);
            } else {
                *reinterpret_cast<float2*>(C0 + row * N0 + coll)       = make_float2(x0, x1);
                *reinterpret_cast<float2*>(C0 + (row + 8) * N0 + coll) = make_float2(x2, x3);
            }
        }
    }
}

// ============ small bf16 GEMM (disc2): BM=128, BN=64, fp32 out ============
__global__ void __launch_bounds__(256, 2) gemm_sm(
    APtrsB A, int Ktot, const __nv_bfloat16* __restrict__ Wt, int N,
    const float* __restrict__ bias, float* __restrict__ C, int act)
{
    constexpr int AW = 40;
    constexpr int ABYTES = 128 * AW * 2;
    constexpr int BBYTES = 64 * AW * 2;
    constexpr int STG = ABYTES + BBYTES;
    constexpr int NT = 4;

    extern __shared__ char smem[];
    const int t = threadIdx.x, lane = t & 31, wid = t >> 5;
    const int batch = blockIdx.y >> 7;
    const int m0 = (blockIdx.y & 127) * 128;
    const int n0 = blockIdx.x * 64;
    const int wm = (wid & 3) * 32;
    const int wn = (wid >> 2) * 32;

    const __nv_bfloat16* A1 = A.p[batch];
    const uint32_t sbase = smem_u32(smem);
    const uint32_t a_addr0 = sbase + (uint32_t)((wm + (lane & 15)) * (AW * 2) + (lane >> 4) * 16);
    const int grp = lane >> 3;
    const int b_r = (lane & 7) + ((grp >= 2) ? 8 : 0);
    const uint32_t b_addr0 = sbase + ABYTES + (uint32_t)((wn + b_r) * (AW * 2) + (grp & 1) * 16);

    float acc[2][NT][4];
#pragma unroll
    for (int i = 0; i < 2; i++)
#pragma unroll
        for (int j = 0; j < NT; j++)
#pragma unroll
            for (int q = 0; q < 4; q++) acc[i][j][q] = 0.0f;

    auto load_chunk = [&](int c) {
        const int stg = c % 3;
        uint32_t sA = sbase + stg * STG;
#pragma unroll
        for (int i = 0; i < 2; i++) {
            int idx = t + i * 256, r = idx >> 2, c8 = idx & 3;
            CP_ASYNC16(sA + (uint32_t)(r * (AW * 2) + c8 * 16),
                       A1 + (size_t)(m0 + r) * Ktot + c * 32 + c8 * 8);
        }
        uint32_t sB = sA + ABYTES;
        {
            int r = t >> 2, c8 = t & 3;
            if (r < 64)
                CP_ASYNC16(sB + (uint32_t)(r * (AW * 2) + c8 * 16),
                           Wt + (size_t)(n0 + r) * Ktot + c * 32 + c8 * 8);
        }
        CP_COMMIT();
    };

    const int NC = Ktot >> 5;
    load_chunk(0);
    if (NC > 1) load_chunk(1);

    for (int c = 0; c < NC; c++) {
        if (c + 1 < NC) { asm volatile("cp.async.wait_group 1;" ::: "memory"); }
        else            { asm volatile("cp.async.wait_group 0;" ::: "memory"); }
        __syncthreads();
        if (c + 2 < NC) load_chunk(c + 2);

        const uint32_t aa = a_addr0 + (c % 3) * STG;
        const uint32_t bb = b_addr0 + (c % 3) * STG;
#pragma unroll
        for (int kk = 0; kk < 2; kk++) {
            uint32_t Af[2][4];
            LDSM4(Af[0], aa + kk * 32);
            LDSM4(Af[1], aa + 16 * (AW * 2) + kk * 32);
#pragma unroll
            for (int np = 0; np < NT / 2; np++) {
                uint32_t B4[4];
                LDSM4(B4, bb + np * 16 * (AW * 2) + kk * 32);
#pragma unroll
                for (int mt = 0; mt < 2; mt++) {
                    mma_bf(acc[mt][2 * np],     Af[mt], B4[0], B4[1]);
                    mma_bf(acc[mt][2 * np + 1], Af[mt], B4[2], B4[3]);
                }
            }
        }
    }

#pragma unroll
    for (int mt = 0; mt < 2; mt++) {
        size_t row = (size_t)batch * NB + m0 + wm + mt * 16 + (lane >> 2);
#pragma unroll
        for (int nt = 0; nt < NT; nt++) {
            int col = n0 + wn + nt * 8 + (lane & 3) * 2;
            float bv0 = bias[col], bv1 = bias[col + 1];
            float x0 = acc[mt][nt][0] + bv0, x1 = acc[mt][nt][1] + bv1;
            float x2 = acc[mt][nt][2] + bv0, x3 = acc[mt][nt][3] + bv1;
            if (act) { x0 = geluf(x0); x1 = geluf(x1); x2 = geluf(x2); x3 = geluf(x3); }
            *reinterpret_cast<float2*>(C + row * N + col)       = make_float2(x0, x1);
            *reinterpret_cast<float2*>(C + (row + 8) * N + col) = make_float2(x2, x3);
        }
    }
}

// ============ precise 3xTF32 GEMM (info path) ============
template<int BN>
__global__ void __launch_bounds__(256, 2) gemm_tf32p(
    APtrs A, int Ktot, const float* __restrict__ Wt, int N,
    const float* __restrict__ bias, float* __restrict__ C, int act)
{
    constexpr int AW = 36;
    constexpr int ABYTES = 128 * AW * 4;
    constexpr int BBYTES = BN * AW * 4;
    constexpr int STG = ABYTES + BBYTES;
    constexpr int NT = BN / 16;

    extern __shared__ char smem[];
    const int t = threadIdx.x, lane = t & 31, wid = t >> 5;
    const int batch = blockIdx.y >> 7;
    const int m0 = (blockIdx.y & 127) * 128;
    const int n0 = blockIdx.x * BN;
    const int wm = (wid & 3) * 32;
    const int wn = (wid >> 2) * (BN / 2);

    const float* A1 = A.p[batch];
    C += (size_t)batch * NB * N;

    const uint32_t sbase = smem_u32(smem);
    const uint32_t a_addr0 = sbase + (uint32_t)(((wm + (lane & 15)) * AW + (lane >> 4) * 4) * 4);
    const int grp = lane >> 3;
    const int b_r = (lane & 7) + ((grp >= 2) ? 8 : 0);
    const uint32_t b_addr0 = sbase + ABYTES + (uint32_t)(((wn + b_r) * AW + (grp & 1) * 4) * 4);

    float acc[2][NT][4];
#pragma unroll
    for (int i = 0; i < 2; i++)
#pragma unroll
        for (int j = 0; j < NT; j++)
#pragma unroll
            for (int q = 0; q < 4; q++) acc[i][j][q] = 0.0f;

    auto load_chunk = [&](int c) {
        const int stg = c % 3;
        uint32_t sA = sbase + stg * STG;
#pragma unroll
        for (int i = 0; i < 4; i++) {
            int idx = t + i * 256, r = idx >> 3, c4 = idx & 7;
            CP_ASYNC16(sA + (uint32_t)(r * AW + c4 * 4) * 4,
                       A1 + (size_t)(m0 + r) * Ktot + c * 32 + c4 * 4);
        }
        uint32_t sB = sA + ABYTES;
#pragma unroll
        for (int i = 0; i < BN / 32; i++) {
            int idx = t + i * 256, r = idx >> 3, c4 = idx & 7;
            CP_ASYNC16(sB + (uint32_t)(r * AW + c4 * 4) * 4,
                       Wt + (size_t)(n0 + r) * Ktot + c * 32 + c4 * 4);
        }
        CP_COMMIT();
    };

    const int NC = Ktot >> 5;
    load_chunk(0);
    if (NC > 1) load_chunk(1);

    for (int c = 0; c < NC; c++) {
        if (c + 1 < NC) { asm volatile("cp.async.wait_group 1;" ::: "memory"); }
        else            { asm volatile("cp.async.wait_group 0;" ::: "memory"); }
        __syncthreads();
        if (c + 2 < NC) load_chunk(c + 2);

        const uint32_t aa = a_addr0 + (c % 3) * STG;
        const uint32_t bb = b_addr0 + (c % 3) * STG;
#pragma unroll
        for (int kk = 0; kk < 4; kk++) {
            uint32_t Ah[2][4], Al[2][4];
            LDSM4(Ah[0], aa + kk * 32);
            LDSM4(Ah[1], aa + 16 * AW * 4 + kk * 32);
#pragma unroll
            for (int mt = 0; mt < 2; mt++)
#pragma unroll
                for (int q = 0; q < 4; q++) split_tf32(Ah[mt][q], Ah[mt][q], Al[mt][q]);
#pragma unroll
            for (int np = 0; np < NT / 2; np++) {
                uint32_t B4[4], Bh[4], Bl[4];
                LDSM4(B4, bb + np * 16 * AW * 4 + kk * 32);
#pragma unroll
                for (int q = 0; q < 4; q++) split_tf32(B4[q], Bh[q], Bl[q]);
#pragma unroll
                for (int mt = 0; mt < 2; mt++) {
                    mma_tf(acc[mt][2 * np],     Ah[mt], Bh[0], Bh[1]);
                    mma_tf(acc[mt][2 * np],     Ah[mt], Bl[0], Bl[1]);
                    mma_tf(acc[mt][2 * np],     Al[mt], Bh[0], Bh[1]);
                    mma_tf(acc[mt][2 * np + 1], Ah[mt], Bh[2], Bh[3]);
                    mma_tf(acc[mt][2 * np + 1], Ah[mt], Bl[2], Bl[3]);
                    mma_tf(acc[mt][2 * np + 1], Al[mt], Bh[2], Bh[3]);
                }
            }
        }
    }

#pragma unroll
    for (int mt = 0; mt < 2; mt++) {
        int row = m0 + wm + mt * 16 + (lane >> 2);
#pragma unroll
        for (int nt = 0; nt < NT; nt++) {
            int col = n0 + wn + nt * 8 + (lane & 3) * 2;
            float bv0 = bias[col], bv1 = bias[col + 1];
            float x0 = acc[mt][nt][0] + bv0, x1 = acc[mt][nt][1] + bv1;
            float x2 = acc[mt][nt][2] + bv0, x3 = acc[mt][nt][3] + bv1;
            if (act) { x0 = geluf(x0); x1 = geluf(x1); x2 = geluf(x2); x3 = geluf(x3); }
            *reinterpret_cast<float2*>(C + (size_t)row * N + col)       = make_float2(x0, x1);
            *reinterpret_cast<float2*>(C + (size_t)(row + 8) * N + col) = make_float2(x2, x3);
        }
    }
}

// ---------------- feature fp32 -> bf16 ----------------
__global__ void cvt_bf_k(const float4* __restrict__ s0, const float4* __restrict__ s1,
                         const float4* __restrict__ s2, const float4* __restrict__ s3,
                         __nv_bfloat16* __restrict__ d)
{
    int i = blockIdx.x * blockDim.x + threadIdx.x;
    const int per = NB * 768 / 4;
    if (i >= 4 * per) return;
    int f = i / per, j = i - f * per;
    const float4* s = (f == 0 ? s0 : f == 1 ? s1 : f == 2 ? s2 : s3);
    float4 v = s[j];
    __nv_bfloat162* o = reinterpret_cast<__nv_bfloat162*>(d + (size_t)f * NB * 768 + (size_t)j * 4);
    o[0] = __floats2bfloat162_rn(v.x, v.y);
    o[1] = __floats2bfloat162_rn(v.z, v.w);
}

// ---------------- combined transpose: 9 jobs in one launch ----------------
struct TJobs {
    const float* s[9];
    void* d[9];
    int K[9], N[9], t0[9];
    unsigned bfmask;
    int njobs;
};
__global__ void transpose_combo_k(TJobs J) {
    __shared__ float tile[32][33];
    int bx = blockIdx.x;
    int j = 0;
#pragma unroll
    for (int q = 1; q < 9; q++) if (q < J.njobs && bx >= J.t0[q]) j = q;
    int local = bx - J.t0[j];
    int tilesx = J.N[j] / 32;
    int txb = local % tilesx, tyb = local / tilesx;
    const float* s = J.s[j];
    int K = J.K[j], N = J.N[j];
    int n = txb * 32 + threadIdx.x;
    int k = tyb * 32 + threadIdx.y;
#pragma unroll
    for (int i = 0; i < 32; i += 8) tile[threadIdx.y + i][threadIdx.x] = s[(size_t)(k + i) * N + n];
    __syncthreads();
    int n2 = txb * 32 + threadIdx.y;
    int k2 = tyb * 32 + threadIdx.x;
    if (J.bfmask & (1u << j)) {
        __nv_bfloat16* d = (__nv_bfloat16*)J.d[j];
#pragma unroll
        for (int i = 0; i < 32; i += 8)
            d[(size_t)(n2 + i) * K + k2] = __float2bfloat16(tile[threadIdx.x][threadIdx.y + i]);
    } else {
        float* d = (float*)J.d[j];
#pragma unroll
        for (int i = 0; i < 32; i += 8)
            d[(size_t)(n2 + i) * K + k2] = tile[threadIdx.x][threadIdx.y + i];
    }
}

// ---------------- final dot head with batch->output-row map ----------------
__global__ void dot_head_k(const float* __restrict__ Hin, int K, int rows,
                           const float* __restrict__ w, const float* __restrict__ b,
                           float* __restrict__ out, int baseRow, int4 map)
{
    int gw = (blockIdx.x * blockDim.x + threadIdx.x) >> 5;
    int lane = threadIdx.x & 31;
    if (gw >= rows) return;
    const float* row = Hin + (size_t)gw * K;
    float s = 0.f;
    for (int k = lane * 4; k < K; k += 128) {
        float4 v = *reinterpret_cast<const float4*>(row + k);
        float4 wv = *reinterpret_cast<const float4*>(w + k);
        s += v.x * wv.x + v.y * wv.y + v.z * wv.z + v.w * wv.w;
    }
#pragma unroll
    for (int o = 16; o; o >>= 1) s += __shfl_xor_sync(0xffffffffu, s, o);
    if (lane == 0) {
        int batch = gw >> 14, m = gw & (NB - 1);
        int r = batch == 0 ? map.x : batch == 1 ? map.y : batch == 2 ? map.z : map.w;
        out[(size_t)(baseRow + r) * NB + m] = sigf(s + b[0]);
    }
}

// ---------------- geometric quality + norms ----------------
__global__ void rowstats_k(const float* __restrict__ f0, const float* __restrict__ f1,
                           const float* __restrict__ f2, const float* __restrict__ f3,
                           float* __restrict__ out)
{
    int gw = (blockIdx.x * blockDim.x + threadIdx.x) >> 5;
    int lane = threadIdx.x & 31;
    if (gw >= 4 * NB) return;
    int feat = gw >> 14;
    int m = gw & (NB - 1);
    const float* f = (feat == 0 ? f0 : feat == 1 ? f1 : feat == 2 ? f2 : f3) + (size_t)m * HD;
    double sum = 0.0, ssq = 0.0;
    int cnt = 0;
    for (int k = lane * 4; k < HD; k += 128) {
        float4 v = *reinterpret_cast<const float4*>(f + k);
        sum += (double)v.x + v.y + v.z + v.w;
        ssq += (double)v.x * v.x + (double)v.y * v.y + (double)v.z * v.z + (double)v.w * v.w;
        cnt += (fabsf(v.x) > 0.01f) + (fabsf(v.y) > 0.01f) + (fabsf(v.z) > 0.01f) + (fabsf(v.w) > 0.01f);
    }
#pragma unroll
    for (int o = 16; o; o >>= 1) {
        sum += __shfl_xor_sync(0xffffffffu, sum, o);
        ssq += __shfl_xor_sync(0xffffffffu, ssq, o);
        cnt += __shfl_xor_sync(0xffffffffu, cnt, o);
    }
    if (lane == 0) {
        float n = (float)sqrt(ssq);
        float nq = sigf((n - 1.0f) * 2.0f);
        float sp = cnt * (1.0f / 768.0f);
        double var = (ssq - sum * sum / 768.0) / 767.0;
        if (var < 0.0) var = 0.0;
        float sq = sigf((float)sqrt(var) * 10.0f - 1.0f);
        out[feat * NB + m] = (nq + sp + sq) * (1.0f / 3.0f);
        if (feat < 2) g_norm[feat * NB + m] = n;
    }
}

// ---------------- information quality final (2*NB rows) ----------------
__global__ void info_final_k(const float* __restrict__ enc, float* __restrict__ outrow)
{
    int gw = (blockIdx.x * blockDim.x + threadIdx.x) >> 5;
    int lane = threadIdx.x & 31;
    if (gw >= 2 * NB) return;
    const float* e = enc + (size_t)gw * 64;
    float x0 = e[lane], x1 = e[lane + 32];
    int d0 = (int)rintf(sigf(x0) * 10.0f);
    int d1 = (int)rintf(sigf(x1) * 10.0f);
    float ent = 0.f;
#pragma unroll
    for (int b = 0; b < 11; b++) {
        int c = __popc(__ballot_sync(0xffffffffu, d0 == b)) +
                __popc(__ballot_sync(0xffffffffu, d1 == b));
        if (c > 0) {
            float p = c * (1.0f / 64.0f);
            ent -= p * logf(p + 1e-8f);
        }
    }
    if (lane == 0) {
        float eq = sigf(ent - 2.0f);
        float n = g_norm[gw];
        float cq = (n > 0.01f) ? (1.0f / 768.0f) : 0.0f;
        float t = n / fmaxf(n, 1e-12f);
        float dq = sigf(t * t - 0.5f);
        outrow[gw] = (eq + cq + dq) * (1.0f / 3.0f);
    }
}

__global__ void overall_k(float* __restrict__ out)
{
    int i = blockIdx.x * blockDim.x + threadIdx.x;
    if (i >= NB) return;
    float v = out[0 * NB + i] + out[1 * NB + i] + out[4 * NB + i] + out[5 * NB + i] +
              out[7 * NB + i] + 0.5f * (out[8 * NB + i] + out[9 * NB + i]);
    out[17 * NB + i] = v * (1.0f / 6.0f);
}

// ---------------- host ----------------
static void launch_big(APtrsB A, int nb, int Khalf, int Ktot,
                       const __nv_bfloat16* Wt0, const __nv_bfloat16* Wt1,
                       int N0, int N1, const float* b0, const float* b1,
                       float* C0, __nv_bfloat16* C1, int act)
{
    int smemB = 3 * (256 + 128) * 40 * 2;   // 92160
    cudaFuncSetAttribute(gemm_big, cudaFuncAttributeMaxDynamicSharedMemorySize, smemB);
    dim3 g((N0 + N1) / 128, nb * 64);
    gemm_big<<<g, 256, smemB>>>(A, Khalf, Ktot, Wt0, Wt1, N0, N1, b0, b1, C0, C1, act);
}
static void launch_sm(APtrsB A, int nb, int Ktot, const __nv_bfloat16* Wt, int N,
                      const float* bias, float* C, int act)
{
    int smemB = 3 * (128 + 64) * 40 * 2;
    cudaFuncSetAttribute(gemm_sm, cudaFuncAttributeMaxDynamicSharedMemorySize, smemB);
    dim3 g(N / 64, nb * 128);
    gemm_sm<<<g, 256, smemB>>>(A, Ktot, Wt, N, bias, C, act);
}
template<int BN>
static void launch_tp(APtrs A, int nb, int Ktot, const float* Wt, int N,
                      const float* bias, float* C, int act)
{
    int smemB = 3 * (128 + BN) * 36 * 4;
    cudaFuncSetAttribute(gemm_tf32p<BN>, cudaFuncAttributeMaxDynamicSharedMemorySize, smemB);
    dim3 g(N / BN, nb * 128);
    gemm_tf32p<BN><<<g, 256, smemB>>>(A, Ktot, Wt, N, bias, C, act);
}

extern "C" void kernel_launch(void* const* d_in, const int* in_sizes, int n_in,
                              void* d_out, int out_size)
{
    const float* img  = (const float*)d_in[0];
    const float* txt  = (const float*)d_in[1];
    const float* eimg = (const float*)d_in[2];
    const float* etxt = (const float*)d_in[3];
    const float* info_w1 = (const float*)d_in[5];
    const float* info_b1 = (const float*)d_in[6];
    const float* info_w2 = (const float*)d_in[7];
    const float* info_b2 = (const float*)d_in[8];
    const float* imp_w1  = (const float*)d_in[9];
    const float* imp_b1  = (const float*)d_in[10];
    const float* imp_w2  = (const float*)d_in[11];
    const float* imp_b2  = (const float*)d_in[12];
    const float* disc_w1 = (const float*)d_in[13];
    const float* disc_b1 = (const float*)d_in[14];
    const float* disc_w2 = (const float*)d_in[15];
    const float* disc_b2 = (const float*)d_in[16];
    const float* disc_w3 = (const float*)d_in[17];
    const float* disc_b3 = (const float*)d_in[18];
    const float* cons_w1 = (const float*)d_in[19];
    const float* cons_b1 = (const float*)d_in[20];
    const float* cons_w2 = (const float*)d_in[21];
    const float* cons_b2 = (const float*)d_in[22];
    const float* cons_w3 = (const float*)d_in[23];
    const float* cons_b3 = (const float*)d_in[24];
    const float* diff_w1 = (const float*)d_in[25];
    const float* diff_b1 = (const float*)d_in[26];
    const float* diff_w2 = (const float*)d_in[27];
    const float* diff_b2 = (const float*)d_in[28];
    const float* diff_w3 = (const float*)d_in[29];
    const float* diff_b3 = (const float*)d_in[30];

    float* out = (float*)d_out;

    __nv_bfloat16 *featbf, *scrAbf, *scrCbf;
    __nv_bfloat16 *w_imp1, *w_disc1, *w_disc2, *w_cons1, *w_cons2, *w_diff1, *w_diff2;
    float *scrB, *scrC, *scrD, *w_i1, *w_i2;
    cudaGetSymbolAddress((void**)&featbf, g_featbf);
    cudaGetSymbolAddress((void**)&scrAbf, g_scrAbf);
    cudaGetSymbolAddress((void**)&scrCbf, g_scrCbf);
    cudaGetSymbolAddress((void**)&scrB, g_scrB);
    cudaGetSymbolAddress((void**)&scrC, g_scrC);
    cudaGetSymbolAddress((void**)&scrD, g_scrD);
    cudaGetSymbolAddress((void**)&w_imp1, g_w_imp1);
    cudaGetSymbolAddress((void**)&w_disc1, g_w_disc1);
    cudaGetSymbolAddress((void**)&w_disc2, g_w_disc2);
    cudaGetSymbolAddress((void**)&w_cons1, g_w_cons1);
    cudaGetSymbolAddress((void**)&w_cons2, g_w_cons2);
    cudaGetSymbolAddress((void**)&w_diff1, g_w_diff1);
    cudaGetSymbolAddress((void**)&w_diff2, g_w_diff2);
    cudaGetSymbolAddress((void**)&w_i1, g_w_info1);
    cudaGetSymbolAddress((void**)&w_i2, g_w_info2);

    const __nv_bfloat16* bimg  = featbf;
    const __nv_bfloat16* btxt  = featbf + (size_t)NB * 768;
    const __nv_bfloat16* beimg = featbf + (size_t)2 * NB * 768;
    const __nv_bfloat16* betxt = featbf + (size_t)3 * NB * 768;

    // feature conversion
    cvt_bf_k<<<(4 * NB * 768 / 4 + 255) / 256, 256>>>(
        (const float4*)img, (const float4*)txt, (const float4*)eimg, (const float4*)etxt, featbf);

    // all 9 weight transposes in one launch
    {
        TJobs J;
        const float* srcs[9] = { imp_w1, disc_w1, disc_w2, cons_w1, cons_w2, diff_w1, diff_w2,
                                 info_w1, info_w2 };
        void* dsts[9] = { w_imp1, w_disc1, w_disc2, w_cons1, w_cons2, w_diff1, w_diff2,
                          w_i1, w_i2 };
        int Ks[9] = { 768, 768, 256, 1536, 768, 1536, 768, 768, 256 };
        int Ns[9] = { 384, 256, 64, 768, 384, 768, 384, 256, 64 };
        int tot = 0;
        for (int j = 0; j < 9; j++) {
            J.s[j] = srcs[j]; J.d[j] = dsts[j]; J.K[j] = Ks[j]; J.N[j] = Ns[j];
            J.t0[j] = tot;
            tot += (Ks[j] / 32) * (Ns[j] / 32);
        }
        J.bfmask = 0x7F;   // jobs 0-6 bf16, 7-8 fp32
        J.njobs = 9;
        dim3 b(32, 8);
        transpose_combo_k<<<tot, b>>>(J);
    }

    // geometric (rows 0..3) + norms
    rowstats_k<<<(4 * NB) / 8, 256>>>(img, txt, eimg, etxt, out);

    // information (rows 4,5) — 3xTF32 precise
    {
        APtrs a = {{ img, txt, nullptr, nullptr }};
        launch_tp<128>(a, 2, 768, w_i1, 256, info_b1, scrC, 1);
        APtrs a2 = {{ scrC, scrC + (size_t)NB * 256, nullptr, nullptr }};
        launch_tp<64>(a2, 2, 256, w_i2, 64, info_b2, scrD, 0);
        info_final_k<<<(2 * NB) / 8, 256>>>(scrD, out + 4 * NB);
    }

    // merged importance + disc layer1 (batched 4: img, txt, eimg, etxt)
    {
        APtrsB a = {{ bimg, btxt, beimg, betxt }};
        launch_big(a, 4, 768, 768, w_imp1, w_disc1, 384, 256, imp_b1, disc_b1,
                   scrB, scrCbf, 1);
        // importance rows 8..11 (identity batch order)
        dot_head_k<<<(4 * NB) / 8, 256>>>(scrB, 384, 4 * NB, imp_w2, imp_b2,
                                          out, 8, make_int4(0, 1, 2, 3));
        // disc layer2 + head; storage order img,txt,eimg,etxt -> rows 12,14,13,15
        APtrsB a2 = {{ scrCbf, scrCbf + (size_t)NB * 256, scrCbf + (size_t)2 * NB * 256,
                       scrCbf + (size_t)3 * NB * 256 }};
        launch_sm(a2, 4, 256, w_disc2, 64, disc_b2, scrD, 1);
        dot_head_k<<<(4 * NB) / 8, 256>>>(scrD, 64, 4 * NB, disc_w3, disc_b3,
                                          out, 12, make_int4(0, 2, 1, 3));
    }

    // consistency (rows 6,7) — batched 2 concat pairs
    {
        APtrsB a = {{ bimg, btxt, beimg, betxt }};
        launch_big(a, 2, 768, 1536, nullptr, w_cons1, 0, 768, nullptr, cons_b1,
                   nullptr, scrAbf, 1);
        APtrsB a2 = {{ scrAbf, scrAbf + (size_t)NB * 768, nullptr, nullptr }};
        launch_big(a2, 2, 768, 768, w_cons2, nullptr, 384, 0, cons_b2, nullptr,
                   scrB, nullptr, 1);
        dot_head_k<<<(2 * NB) / 8, 256>>>(scrB, 384, 2 * NB, cons_w3, cons_b3,
                                          out, 6, make_int4(0, 1, 0, 0));
    }

    // difficulty (row 16)
    {
        APtrsB a = {{ beimg, betxt, nullptr, nullptr }};
        launch_big(a, 1, 768, 1536, nullptr, w_diff1, 0, 768, nullptr, diff_b1,
                   nullptr, scrAbf, 1);
        APtrsB a2 = {{ scrAbf, nullptr, nullptr, nullptr }};
        launch_big(a2, 1, 768, 768, w_diff2, nullptr, 384, 0, diff_b2, nullptr,
                   scrB, nullptr, 1);
        dot_head_k<<<NB / 8, 256>>>(scrB, 384, NB, diff_w3, diff_b3,
                                    out, 16, make_int4(0, 0, 0, 0));
    }

    // overall (row 17)
    overall_k<<<NB / 256, 256>>>(out);
}

// round 8
// speedup vs baseline: 1.2760x; 1.2760x over previous
#include <cuda_runtime.h>
#include <cuda_bf16.h>
#include <cstdint>

#define NB 16384
#define HD 768

// ---------------- scratch (device globals; no allocs allowed) ----------------
__device__ __nv_bfloat16 g_featbf[4 * NB * 768];
__device__ __nv_bfloat16 g_scrAbf[2 * NB * 768];     // cons1 / diff1 outputs (bf16)
__device__ __nv_bfloat16 g_scrCbf[4 * NB * 256];     // disc1 outputs (bf16)
__device__ float g_scrB [4 * NB * 384];              // imp1 outputs (fp32)        [main]
__device__ float g_scrB2[2 * NB * 384];              // cons2 outputs (fp32)       [s2]
__device__ float g_scrB3[1 * NB * 384];              // diff2 outputs (fp32)       [s2]
__device__ float g_scrC [2 * NB * 256];              // info1 outputs (fp32)       [s1]
__device__ float g_scrD [4 * NB * 64];               // disc2 outputs (fp32)       [main]
__device__ float g_scrD2[2 * NB * 64];               // info2 outputs (fp32)       [s1]
__device__ float g_norm[2 * NB];
__device__ __nv_bfloat16 g_w_imp1[384 * 768];
__device__ __nv_bfloat16 g_w_disc1[256 * 768];
__device__ __nv_bfloat16 g_w_disc2[64 * 256];
__device__ __nv_bfloat16 g_w_cons1[768 * 1536];
__device__ __nv_bfloat16 g_w_cons2[384 * 768];
__device__ __nv_bfloat16 g_w_diff1[768 * 1536];
__device__ __nv_bfloat16 g_w_diff2[384 * 768];
__device__ float g_w_info1[256 * 768];
__device__ float g_w_info2[64 * 256];

__device__ __forceinline__ float sigf(float x) { return 1.0f / (1.0f + expf(-x)); }
__device__ __forceinline__ float geluf(float x) { return 0.5f * x * (1.0f + erff(x * 0.70710678118654752f)); }

__device__ __forceinline__ uint32_t smem_u32(const void* p) {
    uint32_t a;
    asm("{ .reg .u64 t; cvta.to.shared.u64 t, %1; cvt.u32.u64 %0, t; }" : "=r"(a) : "l"(p));
    return a;
}
__device__ __forceinline__ void mma_tf(float* d, const uint32_t* a, uint32_t b0, uint32_t b1) {
    asm volatile(
        "mma.sync.aligned.m16n8k8.row.col.f32.tf32.tf32.f32 "
        "{%0,%1,%2,%3}, {%4,%5,%6,%7}, {%8,%9}, {%0,%1,%2,%3};"
        : "+f"(d[0]), "+f"(d[1]), "+f"(d[2]), "+f"(d[3])
        : "r"(a[0]), "r"(a[1]), "r"(a[2]), "r"(a[3]), "r"(b0), "r"(b1));
}
__device__ __forceinline__ void mma_bf(float* d, const uint32_t* a, uint32_t b0, uint32_t b1) {
    asm volatile(
        "mma.sync.aligned.m16n8k16.row.col.f32.bf16.bf16.f32 "
        "{%0,%1,%2,%3}, {%4,%5,%6,%7}, {%8,%9}, {%0,%1,%2,%3};"
        : "+f"(d[0]), "+f"(d[1]), "+f"(d[2]), "+f"(d[3])
        : "r"(a[0]), "r"(a[1]), "r"(a[2]), "r"(a[3]), "r"(b0), "r"(b1));
}
#define LDSM4(r, addr) \
    asm volatile("ldmatrix.sync.aligned.m8n8.x4.shared.b16 {%0,%1,%2,%3}, [%4];" \
        : "=r"((r)[0]), "=r"((r)[1]), "=r"((r)[2]), "=r"((r)[3]) : "r"(addr))
#define CP_ASYNC16(dst, src) \
    asm volatile("cp.async.cg.shared.global [%0], [%1], 16;" :: "r"(dst), "l"(src))
#define CP_COMMIT() asm volatile("cp.async.commit_group;" ::: "memory")

__device__ __forceinline__ void split_tf32(uint32_t x, uint32_t& h, uint32_t& l) {
    h = x & 0xFFFFE000u;
    l = __float_as_uint(__uint_as_float(x) - __uint_as_float(h));
}

struct APtrs  { const float* p[4]; };
struct APtrsB { const __nv_bfloat16* p[4]; };

// ================= bf16 GEMM (R6-proven): BM=128, BK=32, 3-stage, occ 2 =================
template<int BN, bool OUTBF>
__global__ void __launch_bounds__(256, 2) gemm_bf16(
    APtrsB A, int Khalf, int Ktot, const __nv_bfloat16* __restrict__ Wt, int N,
    const float* __restrict__ bias, void* __restrict__ Cv, int act)
{
    constexpr int AW = 40;
    constexpr int ABYTES = 128 * AW * 2;
    constexpr int BBYTES = BN * AW * 2;
    constexpr int STG = ABYTES + BBYTES;
    constexpr int NT = BN / 16;

    extern __shared__ char smem[];
    const int t = threadIdx.x, lane = t & 31, wid = t >> 5;
    const int batch = blockIdx.y >> 7;
    const int m0 = (blockIdx.y & 127) * 128;
    const int n0 = blockIdx.x * BN;
    const int wm = (wid & 3) * 32;
    const int wn = (wid >> 2) * (BN / 2);

    const __nv_bfloat16 *A1, *A2;
    if (Khalf < Ktot) { A1 = A.p[2 * batch]; A2 = A.p[2 * batch + 1]; }
    else              { A1 = A.p[batch];     A2 = A1; }

    const uint32_t sbase = smem_u32(smem);
    const uint32_t a_addr0 = sbase + (uint32_t)((wm + (lane & 15)) * AW * 2 + (lane >> 4) * 16);
    const int grp = lane >> 3;
    const int b_r = (lane & 7) + ((grp >= 2) ? 8 : 0);
    const uint32_t b_addr0 = sbase + ABYTES + (uint32_t)((wn + b_r) * AW * 2 + (grp & 1) * 16);

    float acc[2][NT][4];
#pragma unroll
    for (int i = 0; i < 2; i++)
#pragma unroll
        for (int j = 0; j < NT; j++)
#pragma unroll
            for (int q = 0; q < 4; q++) acc[i][j][q] = 0.0f;

    auto load_chunk = [&](int c) {
        const int stg = c % 3;
        int kk = c * 32;
        const __nv_bfloat16* Ab = A1;
        if (kk >= Khalf) { Ab = A2; kk -= Khalf; }
        uint32_t sA = sbase + stg * STG;
#pragma unroll
        for (int i = 0; i < 2; i++) {
            int idx = t + i * 256, r = idx >> 2, c8 = idx & 3;
            CP_ASYNC16(sA + (uint32_t)(r * AW * 2 + c8 * 16),
                       Ab + (size_t)(m0 + r) * Khalf + kk + c8 * 8);
        }
        uint32_t sB = sA + ABYTES;
#pragma unroll
        for (int i = 0; i < BN / 64; i++) {
            int idx = t + i * 256, r = idx >> 2, c8 = idx & 3;
            CP_ASYNC16(sB + (uint32_t)(r * AW * 2 + c8 * 16),
                       Wt + (size_t)(n0 + r) * Ktot + c * 32 + c8 * 8);
        }
        CP_COMMIT();
    };

    const int NC = Ktot >> 5;
    load_chunk(0);
    if (NC > 1) load_chunk(1);

    for (int c = 0; c < NC; c++) {
        if (c + 1 < NC) { asm volatile("cp.async.wait_group 1;" ::: "memory"); }
        else            { asm volatile("cp.async.wait_group 0;" ::: "memory"); }
        __syncthreads();
        if (c + 2 < NC) load_chunk(c + 2);

        const uint32_t aa = a_addr0 + (c % 3) * STG;
        const uint32_t bb = b_addr0 + (c % 3) * STG;
#pragma unroll
        for (int kk = 0; kk < 2; kk++) {
            uint32_t Af[2][4];
            LDSM4(Af[0], aa + kk * 32);
            LDSM4(Af[1], aa + 16 * AW * 2 + kk * 32);
#pragma unroll
            for (int np = 0; np < NT / 2; np++) {
                uint32_t B4[4];
                LDSM4(B4, bb + np * 16 * AW * 2 + kk * 32);
#pragma unroll
                for (int mt = 0; mt < 2; mt++) {
                    mma_bf(acc[mt][2 * np],     Af[mt], B4[0], B4[1]);
                    mma_bf(acc[mt][2 * np + 1], Af[mt], B4[2], B4[3]);
                }
            }
        }
    }

#pragma unroll
    for (int mt = 0; mt < 2; mt++) {
        int row = batch * NB + m0 + wm + mt * 16 + (lane >> 2);
#pragma unroll
        for (int nt = 0; nt < NT; nt++) {
            int col = n0 + wn + nt * 8 + (lane & 3) * 2;
            float b0v = bias[col], b1v = bias[col + 1];
            float x0 = acc[mt][nt][0] + b0v, x1 = acc[mt][nt][1] + b1v;
            float x2 = acc[mt][nt][2] + b0v, x3 = acc[mt][nt][3] + b1v;
            if (act) { x0 = geluf(x0); x1 = geluf(x1); x2 = geluf(x2); x3 = geluf(x3); }
            if (OUTBF) {
                __nv_bfloat16* C = (__nv_bfloat16*)Cv;
                *reinterpret_cast<__nv_bfloat162*>(C + (size_t)row * N + col) =
                    __floats2bfloat162_rn(x0, x1);
                *reinterpret_cast<__nv_bfloat162*>(C + (size_t)(row + 8) * N + col) =
                    __floats2bfloat162_rn(x2, x3);
            } else {
                float* C = (float*)Cv;
                *reinterpret_cast<float2*>(C + (size_t)row * N + col)       = make_float2(x0, x1);
                *reinterpret_cast<float2*>(C + (size_t)(row + 8) * N + col) = make_float2(x2, x3);
            }
        }
    }
}

// ================= precise 3xTF32 GEMM (info path) =================
template<int BN>
__global__ void __launch_bounds__(256, 2) gemm_tf32p(
    APtrs A, int Ktot, const float* __restrict__ Wt, int N,
    const float* __restrict__ bias, float* __restrict__ C, int act)
{
    constexpr int AW = 36;
    constexpr int ABYTES = 128 * AW * 4;
    constexpr int BBYTES = BN * AW * 4;
    constexpr int STG = ABYTES + BBYTES;
    constexpr int NT = BN / 16;

    extern __shared__ char smem[];
    const int t = threadIdx.x, lane = t & 31, wid = t >> 5;
    const int batch = blockIdx.y >> 7;
    const int m0 = (blockIdx.y & 127) * 128;
    const int n0 = blockIdx.x * BN;
    const int wm = (wid & 3) * 32;
    const int wn = (wid >> 2) * (BN / 2);

    const float* A1 = A.p[batch];
    C += (size_t)batch * NB * N;

    const uint32_t sbase = smem_u32(smem);
    const uint32_t a_addr0 = sbase + (uint32_t)(((wm + (lane & 15)) * AW + (lane >> 4) * 4) * 4);
    const int grp = lane >> 3;
    const int b_r = (lane & 7) + ((grp >= 2) ? 8 : 0);
    const uint32_t b_addr0 = sbase + ABYTES + (uint32_t)(((wn + b_r) * AW + (grp & 1) * 4) * 4);

    float acc[2][NT][4];
#pragma unroll
    for (int i = 0; i < 2; i++)
#pragma unroll
        for (int j = 0; j < NT; j++)
#pragma unroll
            for (int q = 0; q < 4; q++) acc[i][j][q] = 0.0f;

    auto load_chunk = [&](int c) {
        const int stg = c % 3;
        uint32_t sA = sbase + stg * STG;
#pragma unroll
        for (int i = 0; i < 4; i++) {
            int idx = t + i * 256, r = idx >> 3, c4 = idx & 7;
            CP_ASYNC16(sA + (uint32_t)(r * AW + c4 * 4) * 4,
                       A1 + (size_t)(m0 + r) * Ktot + c * 32 + c4 * 4);
        }
        uint32_t sB = sA + ABYTES;
#pragma unroll
        for (int i = 0; i < BN / 32; i++) {
            int idx = t + i * 256, r = idx >> 3, c4 = idx & 7;
            CP_ASYNC16(sB + (uint32_t)(r * AW + c4 * 4) * 4,
                       Wt + (size_t)(n0 + r) * Ktot + c * 32 + c4 * 4);
        }
        CP_COMMIT();
    };

    const int NC = Ktot >> 5;
    load_chunk(0);
    if (NC > 1) load_chunk(1);

    for (int c = 0; c < NC; c++) {
        if (c + 1 < NC) { asm volatile("cp.async.wait_group 1;" ::: "memory"); }
        else            { asm volatile("cp.async.wait_group 0;" ::: "memory"); }
        __syncthreads();
        if (c + 2 < NC) load_chunk(c + 2);

        const uint32_t aa = a_addr0 + (c % 3) * STG;
        const uint32_t bb = b_addr0 + (c % 3) * STG;
#pragma unroll
        for (int kk = 0; kk < 4; kk++) {
            uint32_t Ah[2][4], Al[2][4];
            LDSM4(Ah[0], aa + kk * 32);
            LDSM4(Ah[1], aa + 16 * AW * 4 + kk * 32);
#pragma unroll
            for (int mt = 0; mt < 2; mt++)
#pragma unroll
                for (int q = 0; q < 4; q++) split_tf32(Ah[mt][q], Ah[mt][q], Al[mt][q]);
#pragma unroll
            for (int np = 0; np < NT / 2; np++) {
                uint32_t B4[4], Bh[4], Bl[4];
                LDSM4(B4, bb + np * 16 * AW * 4 + kk * 32);
#pragma unroll
                for (int q = 0; q < 4; q++) split_tf32(B4[q], Bh[q], Bl[q]);
#pragma unroll
                for (int mt = 0; mt < 2; mt++) {
                    mma_tf(acc[mt][2 * np],     Ah[mt], Bh[0], Bh[1]);
                    mma_tf(acc[mt][2 * np],     Ah[mt], Bl[0], Bl[1]);
                    mma_tf(acc[mt][2 * np],     Al[mt], Bh[0], Bh[1]);
                    mma_tf(acc[mt][2 * np + 1], Ah[mt], Bh[2], Bh[3]);
                    mma_tf(acc[mt][2 * np + 1], Ah[mt], Bl[2], Bl[3]);
                    mma_tf(acc[mt][2 * np + 1], Al[mt], Bh[2], Bh[3]);
                }
            }
        }
    }

#pragma unroll
    for (int mt = 0; mt < 2; mt++) {
        int row = m0 + wm + mt * 16 + (lane >> 2);
#pragma unroll
        for (int nt = 0; nt < NT; nt++) {
            int col = n0 + wn + nt * 8 + (lane & 3) * 2;
            float b0v = bias[col], b1v = bias[col + 1];
            float x0 = acc[mt][nt][0] + b0v, x1 = acc[mt][nt][1] + b1v;
            float x2 = acc[mt][nt][2] + b0v, x3 = acc[mt][nt][3] + b1v;
            if (act) { x0 = geluf(x0); x1 = geluf(x1); x2 = geluf(x2); x3 = geluf(x3); }
            *reinterpret_cast<float2*>(C + (size_t)row * N + col)       = make_float2(x0, x1);
            *reinterpret_cast<float2*>(C + (size_t)(row + 8) * N + col) = make_float2(x2, x3);
        }
    }
}

// ---------------- feature fp32 -> bf16 ----------------
__global__ void cvt_bf_k(const float4* __restrict__ s0, const float4* __restrict__ s1,
                         const float4* __restrict__ s2, const float4* __restrict__ s3,
                         __nv_bfloat16* __restrict__ d)
{
    int i = blockIdx.x * blockDim.x + threadIdx.x;
    const int per = NB * 768 / 4;
    if (i >= 4 * per) return;
    int f = i / per, j = i - f * per;
    const float4* s = (f == 0 ? s0 : f == 1 ? s1 : f == 2 ? s2 : s3);
    float4 v = s[j];
    __nv_bfloat162* o = reinterpret_cast<__nv_bfloat162*>(d + (size_t)f * NB * 768 + (size_t)j * 4);
    o[0] = __floats2bfloat162_rn(v.x, v.y);
    o[1] = __floats2bfloat162_rn(v.z, v.w);
}

// ---------------- combined transpose: 9 jobs, one launch ----------------
struct TJobs {
    const float* s[9];
    void* d[9];
    int K[9], N[9], t0[9];
    unsigned bfmask;
    int njobs;
};
__global__ void transpose_combo_k(TJobs J) {
    __shared__ float tile[32][33];
    int bx = blockIdx.x;
    int j = 0;
#pragma unroll
    for (int q = 1; q < 9; q++) if (q < J.njobs && bx >= J.t0[q]) j = q;
    int local = bx - J.t0[j];
    int tilesx = J.N[j] / 32;
    int txb = local % tilesx, tyb = local / tilesx;
    const float* s = J.s[j];
    int K = J.K[j], N = J.N[j];
    int n = txb * 32 + threadIdx.x;
    int k = tyb * 32 + threadIdx.y;
#pragma unroll
    for (int i = 0; i < 32; i += 8) tile[threadIdx.y + i][threadIdx.x] = s[(size_t)(k + i) * N + n];
    __syncthreads();
    int n2 = txb * 32 + threadIdx.y;
    int k2 = tyb * 32 + threadIdx.x;
    if (J.bfmask & (1u << j)) {
        __nv_bfloat16* d = (__nv_bfloat16*)J.d[j];
#pragma unroll
        for (int i = 0; i < 32; i += 8)
            d[(size_t)(n2 + i) * K + k2] = __float2bfloat16(tile[threadIdx.x][threadIdx.y + i]);
    } else {
        float* d = (float*)J.d[j];
#pragma unroll
        for (int i = 0; i < 32; i += 8)
            d[(size_t)(n2 + i) * K + k2] = tile[threadIdx.x][threadIdx.y + i];
    }
}

// ---------------- final dot head ----------------
__global__ void dot_head_k(const float* __restrict__ Hin, int K, int rows,
                           const float* __restrict__ w, const float* __restrict__ b,
                           float* __restrict__ outrow)
{
    int gw = (blockIdx.x * blockDim.x + threadIdx.x) >> 5;
    int lane = threadIdx.x & 31;
    if (gw >= rows) return;
    const float* row = Hin + (size_t)gw * K;
    float s = 0.f;
    for (int k = lane * 4; k < K; k += 128) {
        float4 v = *reinterpret_cast<const float4*>(row + k);
        float4 wv = *reinterpret_cast<const float4*>(w + k);
        s += v.x * wv.x + v.y * wv.y + v.z * wv.z + v.w * wv.w;
    }
#pragma unroll
    for (int o = 16; o; o >>= 1) s += __shfl_xor_sync(0xffffffffu, s, o);
    if (lane == 0) outrow[gw] = sigf(s + b[0]);
}

// ---------------- geometric quality + norms ----------------
__global__ void rowstats_k(const float* __restrict__ f0, const float* __restrict__ f1,
                           const float* __restrict__ f2, const float* __restrict__ f3,
                           float* __restrict__ out)
{
    int gw = (blockIdx.x * blockDim.x + threadIdx.x) >> 5;
    int lane = threadIdx.x & 31;
    if (gw >= 4 * NB) return;
    int feat = gw >> 14;
    int m = gw & (NB - 1);
    const float* f = (feat == 0 ? f0 : feat == 1 ? f1 : feat == 2 ? f2 : f3) + (size_t)m * HD;
    double sum = 0.0, ssq = 0.0;
    int cnt = 0;
    for (int k = lane * 4; k < HD; k += 128) {
        float4 v = *reinterpret_cast<const float4*>(f + k);
        sum += (double)v.x + v.y + v.z + v.w;
        ssq += (double)v.x * v.x + (double)v.y * v.y + (double)v.z * v.z + (double)v.w * v.w;
        cnt += (fabsf(v.x) > 0.01f) + (fabsf(v.y) > 0.01f) + (fabsf(v.z) > 0.01f) + (fabsf(v.w) > 0.01f);
    }
#pragma unroll
    for (int o = 16; o; o >>= 1) {
        sum += __shfl_xor_sync(0xffffffffu, sum, o);
        ssq += __shfl_xor_sync(0xffffffffu, ssq, o);
        cnt += __shfl_xor_sync(0xffffffffu, cnt, o);
    }
    if (lane == 0) {
        float n = (float)sqrt(ssq);
        float nq = sigf((n - 1.0f) * 2.0f);
        float sp = cnt * (1.0f / 768.0f);
        double var = (ssq - sum * sum / 768.0) / 767.0;
        if (var < 0.0) var = 0.0;
        float sq = sigf((float)sqrt(var) * 10.0f - 1.0f);
        out[feat * NB + m] = (nq + sp + sq) * (1.0f / 3.0f);
        if (feat < 2) g_norm[feat * NB + m] = n;
    }
}

// ---------------- info final (2*NB rows) ----------------
__global__ void info_final_k(const float* __restrict__ enc, float* __restrict__ outrow)
{
    int gw = (blockIdx.x * blockDim.x + threadIdx.x) >> 5;
    int lane = threadIdx.x & 31;
    if (gw >= 2 * NB) return;
    const float* e = enc + (size_t)gw * 64;
    float x0 = e[lane], x1 = e[lane + 32];
    int d0 = (int)rintf(sigf(x0) * 10.0f);
    int d1 = (int)rintf(sigf(x1) * 10.0f);
    float ent = 0.f;
#pragma unroll
    for (int b = 0; b < 11; b++) {
        int c = __popc(__ballot_sync(0xffffffffu, d0 == b)) +
                __popc(__ballot_sync(0xffffffffu, d1 == b));
        if (c > 0) {
            float p = c * (1.0f / 64.0f);
            ent -= p * logf(p + 1e-8f);
        }
    }
    if (lane == 0) {
        float eq = sigf(ent - 2.0f);
        float n = g_norm[gw];
        float cq = (n > 0.01f) ? (1.0f / 768.0f) : 0.0f;
        float t = n / fmaxf(n, 1e-12f);
        float dq = sigf(t * t - 0.5f);
        outrow[gw] = (eq + cq + dq) * (1.0f / 3.0f);
    }
}

__global__ void overall_k(float* __restrict__ out)
{
    int i = blockIdx.x * blockDim.x + threadIdx.x;
    if (i >= NB) return;
    float v = out[0 * NB + i] + out[1 * NB + i] + out[4 * NB + i] + out[5 * NB + i] +
              out[7 * NB + i] + 0.5f * (out[8 * NB + i] + out[9 * NB + i]);
    out[17 * NB + i] = v * (1.0f / 6.0f);
}

// ---------------- host ----------------
template<int BN, bool OUTBF>
static void launch_bf(cudaStream_t st, APtrsB A, int nb, int Khalf, int Ktot,
                      const __nv_bfloat16* Wt, int N, const float* bias, void* C, int act)
{
    int smemB = 3 * (128 + BN) * 40 * 2;
    cudaFuncSetAttribute(gemm_bf16<BN, OUTBF>, cudaFuncAttributeMaxDynamicSharedMemorySize, smemB);
    dim3 g(N / BN, nb * 128);
    gemm_bf16<BN, OUTBF><<<g, 256, smemB, st>>>(A, Khalf, Ktot, Wt, N, bias, C, act);
}
template<int BN>
static void launch_tp(cudaStream_t st, APtrs A, int nb, int Ktot, const float* Wt, int N,
                      const float* bias, float* C, int act)
{
    int smemB = 3 * (128 + BN) * 36 * 4;
    cudaFuncSetAttribute(gemm_tf32p<BN>, cudaFuncAttributeMaxDynamicSharedMemorySize, smemB);
    dim3 g(N / BN, nb * 128);
    gemm_tf32p<BN><<<g, 256, smemB, st>>>(A, Ktot, Wt, N, bias, C, act);
}

extern "C" void kernel_launch(void* const* d_in, const int* in_sizes, int n_in,
                              void* d_out, int out_size)
{
    const float* img  = (const float*)d_in[0];
    const float* txt  = (const float*)d_in[1];
    const float* eimg = (const float*)d_in[2];
    const float* etxt = (const float*)d_in[3];
    const float* info_w1 = (const float*)d_in[5];
    const float* info_b1 = (const float*)d_in[6];
    const float* info_w2 = (const float*)d_in[7];
    const float* info_b2 = (const float*)d_in[8];
    const float* imp_w1  = (const float*)d_in[9];
    const float* imp_b1  = (const float*)d_in[10];
    const float* imp_w2  = (const float*)d_in[11];
    const float* imp_b2  = (const float*)d_in[12];
    const float* disc_w1 = (const float*)d_in[13];
    const float* disc_b1 = (const float*)d_in[14];
    const float* disc_w2 = (const float*)d_in[15];
    const float* disc_b2 = (const float*)d_in[16];
    const float* disc_w3 = (const float*)d_in[17];
    const float* disc_b3 = (const float*)d_in[18];
    const float* cons_w1 = (const float*)d_in[19];
    const float* cons_b1 = (const float*)d_in[20];
    const float* cons_w2 = (const float*)d_in[21];
    const float* cons_b2 = (const float*)d_in[22];
    const float* cons_w3 = (const float*)d_in[23];
    const float* cons_b3 = (const float*)d_in[24];
    const float* diff_w1 = (const float*)d_in[25];
    const float* diff_b1 = (const float*)d_in[26];
    const float* diff_w2 = (const float*)d_in[27];
    const float* diff_b2 = (const float*)d_in[28];
    const float* diff_w3 = (const float*)d_in[29];
    const float* diff_b3 = (const float*)d_in[30];

    float* out = (float*)d_out;

    __nv_bfloat16 *featbf, *scrAbf, *scrCbf;
    __nv_bfloat16 *w_imp1, *w_disc1, *w_disc2, *w_cons1, *w_cons2, *w_diff1, *w_diff2;
    float *scrB, *scrB2, *scrB3, *scrC, *scrD, *scrD2, *w_i1, *w_i2;
    cudaGetSymbolAddress((void**)&featbf, g_featbf);
    cudaGetSymbolAddress((void**)&scrAbf, g_scrAbf);
    cudaGetSymbolAddress((void**)&scrCbf, g_scrCbf);
    cudaGetSymbolAddress((void**)&scrB, g_scrB);
    cudaGetSymbolAddress((void**)&scrB2, g_scrB2);
    cudaGetSymbolAddress((void**)&scrB3, g_scrB3);
    cudaGetSymbolAddress((void**)&scrC, g_scrC);
    cudaGetSymbolAddress((void**)&scrD, g_scrD);
    cudaGetSymbolAddress((void**)&scrD2, g_scrD2);
    cudaGetSymbolAddress((void**)&w_imp1, g_w_imp1);
    cudaGetSymbolAddress((void**)&w_disc1, g_w_disc1);
    cudaGetSymbolAddress((void**)&w_disc2, g_w_disc2);
    cudaGetSymbolAddress((void**)&w_cons1, g_w_cons1);
    cudaGetSymbolAddress((void**)&w_cons2, g_w_cons2);
    cudaGetSymbolAddress((void**)&w_diff1, g_w_diff1);
    cudaGetSymbolAddress((void**)&w_diff2, g_w_diff2);
    cudaGetSymbolAddress((void**)&w_i1, g_w_info1);
    cudaGetSymbolAddress((void**)&w_i2, g_w_info2);

    const __nv_bfloat16* bimg  = featbf;
    const __nv_bfloat16* btxt  = featbf + (size_t)NB * 768;
    const __nv_bfloat16* beimg = featbf + (size_t)2 * NB * 768;
    const __nv_bfloat16* betxt = featbf + (size_t)3 * NB * 768;

    // streams + events: created once (before graph capture on first call)
    static cudaStream_t s1 = nullptr, s2 = nullptr;
    static cudaEvent_t e0 = nullptr, eT = nullptr, e1 = nullptr, e2 = nullptr;
    if (!s1) {
        cudaStreamCreateWithFlags(&s1, cudaStreamNonBlocking);
        cudaStreamCreateWithFlags(&s2, cudaStreamNonBlocking);
        cudaEventCreateWithFlags(&e0, cudaEventDisableTiming);
        cudaEventCreateWithFlags(&eT, cudaEventDisableTiming);
        cudaEventCreateWithFlags(&e1, cudaEventDisableTiming);
        cudaEventCreateWithFlags(&e2, cudaEventDisableTiming);
    }

    // fork point
    cudaEventRecord(e0, 0);
    cudaStreamWaitEvent(s1, e0, 0);
    cudaStreamWaitEvent(s2, e0, 0);

    // s1: rowstats immediately (needs only inputs)
    rowstats_k<<<(4 * NB) / 8, 256, 0, s1>>>(img, txt, eimg, etxt, out);

    // main: feature conversion + all weight transposes
    cvt_bf_k<<<(4 * NB * 768 / 4 + 255) / 256, 256>>>(
        (const float4*)img, (const float4*)txt, (const float4*)eimg, (const float4*)etxt, featbf);
    {
        TJobs J;
        const float* srcs[9] = { imp_w1, disc_w1, disc_w2, cons_w1, cons_w2, diff_w1, diff_w2,
                                 info_w1, info_w2 };
        void* dsts[9] = { w_imp1, w_disc1, w_disc2, w_cons1, w_cons2, w_diff1, w_diff2,
                          w_i1, w_i2 };
        int Ks[9] = { 768, 768, 256, 1536, 768, 1536, 768, 768, 256 };
        int Ns[9] = { 384, 256, 64, 768, 384, 768, 384, 256, 64 };
        int tot = 0;
        for (int j = 0; j < 9; j++) {
            J.s[j] = srcs[j]; J.d[j] = dsts[j]; J.K[j] = Ks[j]; J.N[j] = Ns[j];
            J.t0[j] = tot;
            tot += (Ks[j] / 32) * (Ns[j] / 32);
        }
        J.bfmask = 0x7F;
        J.njobs = 9;
        dim3 b(32, 8);
        transpose_combo_k<<<tot, b>>>(J);
    }
    cudaEventRecord(eT, 0);
    cudaStreamWaitEvent(s1, eT, 0);
    cudaStreamWaitEvent(s2, eT, 0);

    // s1: information (rows 4,5) — 3xTF32 precise
    {
        APtrs a = {{ img, txt, nullptr, nullptr }};
        launch_tp<128>(s1, a, 2, 768, w_i1, 256, info_b1, scrC, 1);
        APtrs a2 = {{ scrC, scrC + (size_t)NB * 256, nullptr, nullptr }};
        launch_tp<64>(s1, a2, 2, 256, w_i2, 64, info_b2, scrD2, 0);
        info_final_k<<<(2 * NB) / 8, 256, 0, s1>>>(scrD2, out + 4 * NB);
        cudaEventRecord(e1, s1);
    }

    // main: importance (rows 8..11) + discriminator (rows 12..15)
    {
        APtrsB a = {{ bimg, btxt, beimg, betxt }};
        launch_bf<128, false>(0, a, 4, 768, 768, w_imp1, 384, imp_b1, scrB, 1);
        dot_head_k<<<(4 * NB) / 8, 256>>>(scrB, 384, 4 * NB, imp_w2, imp_b2, out + 8 * NB);

        APtrsB ad = {{ bimg, beimg, btxt, betxt }};   // order matches rows 12..15
        launch_bf<128, true>(0, ad, 4, 768, 768, w_disc1, 256, disc_b1, scrCbf, 1);
        APtrsB ad2 = {{ scrCbf, scrCbf + (size_t)NB * 256, scrCbf + (size_t)2 * NB * 256,
                        scrCbf + (size_t)3 * NB * 256 }};
        launch_bf<64, false>(0, ad2, 4, 256, 256, w_disc2, 64, disc_b2, scrD, 1);
        dot_head_k<<<(4 * NB) / 8, 256>>>(scrD, 64, 4 * NB, disc_w3, disc_b3, out + 12 * NB);
    }

    // s2: consistency (rows 6,7) then difficulty (row 16)
    {
        APtrsB a = {{ bimg, btxt, beimg, betxt }};
        launch_bf<128, true>(s2, a, 2, 768, 1536, w_cons1, 768, cons_b1, scrAbf, 1);
        APtrsB a2 = {{ scrAbf, scrAbf + (size_t)NB * 768, nullptr, nullptr }};
        launch_bf<128, false>(s2, a2, 2, 768, 768, w_cons2, 384, cons_b2, scrB2, 1);
        dot_head_k<<<(2 * NB) / 8, 256, 0, s2>>>(scrB2, 384, 2 * NB, cons_w3, cons_b3, out + 6 * NB);

        APtrsB ad = {{ beimg, betxt, nullptr, nullptr }};
        launch_bf<128, true>(s2, ad, 1, 768, 1536, w_diff1, 768, diff_b1, scrAbf, 1);
        APtrsB ad2 = {{ scrAbf, nullptr, nullptr, nullptr }};
        launch_bf<128, false>(s2, ad2, 1, 768, 768, w_diff2, 384, diff_b2, scrB3, 1);
        dot_head_k<<<NB / 8, 256, 0, s2>>>(scrB3, 384, NB, diff_w3, diff_b3, out + 16 * NB);
        cudaEventRecord(e2, s2);
    }

    // join + overall (row 17)
    cudaStreamWaitEvent(0, e1, 0);
    cudaStreamWaitEvent(0, e2, 0);
    overall_k<<<NB / 256, 256>>>(out);
}

// round 9
// speedup vs baseline: 1.3229x; 1.0367x over previous
#include <cuda_runtime.h>
#include <cuda_bf16.h>
#include <cstdint>

#define NB 16384
#define HD 768

// ---------------- scratch (device globals; no allocs allowed) ----------------
__device__ __nv_bfloat16 g_featbf[4 * NB * 768];     // bf16 hi of the 4 features
__device__ __nv_bfloat16 g_lo1[2 * NB * 768];        // bf16 lo of img, txt (info path)
__device__ __nv_bfloat16 g_h2[2 * NB * 256];         // info layer2 input hi
__device__ __nv_bfloat16 g_l2[2 * NB * 256];         // info layer2 input lo
__device__ __nv_bfloat16 g_scrAbf[2 * NB * 768];     // cons1 / diff1 outputs (bf16)
__device__ __nv_bfloat16 g_scrCbf[4 * NB * 256];     // disc1 outputs (bf16)
__device__ float g_scrB [4 * NB * 384];              // imp1 outputs (fp32)        [main]
__device__ float g_scrB2[2 * NB * 384];              // cons2 outputs (fp32)       [s2]
__device__ float g_scrB3[1 * NB * 384];              // diff2 outputs (fp32)       [s2]
__device__ float g_scrC [2 * NB * 256];              // info1 outputs (fp32)       [s1]
__device__ float g_scrD [4 * NB * 64];               // disc2 outputs (fp32)       [main]
__device__ float g_scrD2[2 * NB * 64];               // info2 outputs (fp32)       [s1]
__device__ float g_norm[2 * NB];
__device__ __nv_bfloat16 g_w_imp1[384 * 768];
__device__ __nv_bfloat16 g_w_disc1[256 * 768];
__device__ __nv_bfloat16 g_w_disc2[64 * 256];
__device__ __nv_bfloat16 g_w_cons1[768 * 1536];
__device__ __nv_bfloat16 g_w_cons2[384 * 768];
__device__ __nv_bfloat16 g_w_diff1[768 * 1536];
__device__ __nv_bfloat16 g_w_diff2[384 * 768];
__device__ __nv_bfloat16 g_wi1h[256 * 768], g_wi1l[256 * 768];
__device__ __nv_bfloat16 g_wi2h[64 * 256],  g_wi2l[64 * 256];

__device__ __forceinline__ float sigf(float x) { return 1.0f / (1.0f + expf(-x)); }
__device__ __forceinline__ float geluf(float x) { return 0.5f * x * (1.0f + erff(x * 0.70710678118654752f)); }

__device__ __forceinline__ uint32_t smem_u32(const void* p) {
    uint32_t a;
    asm("{ .reg .u64 t; cvta.to.shared.u64 t, %1; cvt.u32.u64 %0, t; }" : "=r"(a) : "l"(p));
    return a;
}
__device__ __forceinline__ void mma_bf(float* d, const uint32_t* a, uint32_t b0, uint32_t b1) {
    asm volatile(
        "mma.sync.aligned.m16n8k16.row.col.f32.bf16.bf16.f32 "
        "{%0,%1,%2,%3}, {%4,%5,%6,%7}, {%8,%9}, {%0,%1,%2,%3};"
        : "+f"(d[0]), "+f"(d[1]), "+f"(d[2]), "+f"(d[3])
        : "r"(a[0]), "r"(a[1]), "r"(a[2]), "r"(a[3]), "r"(b0), "r"(b1));
}
#define LDSM4(r, addr) \
    asm volatile("ldmatrix.sync.aligned.m8n8.x4.shared.b16 {%0,%1,%2,%3}, [%4];" \
        : "=r"((r)[0]), "=r"((r)[1]), "=r"((r)[2]), "=r"((r)[3]) : "r"(addr))
#define CP_ASYNC16(dst, src) \
    asm volatile("cp.async.cg.shared.global [%0], [%1], 16;" :: "r"(dst), "l"(src))
#define CP_COMMIT() asm volatile("cp.async.commit_group;" ::: "memory")

struct APtrsB { const __nv_bfloat16* p[4]; };

// ================= bf16 GEMM (R6-proven): BM=128, BK=32, 3-stage, occ 2 =================
template<int BN, bool OUTBF>
__global__ void __launch_bounds__(256, 2) gemm_bf16(
    APtrsB A, int Khalf, int Ktot, const __nv_bfloat16* __restrict__ Wt, int N,
    const float* __restrict__ bias, void* __restrict__ Cv, int act)
{
    constexpr int AW = 40;
    constexpr int ABYTES = 128 * AW * 2;
    constexpr int BBYTES = BN * AW * 2;
    constexpr int STG = ABYTES + BBYTES;
    constexpr int NT = BN / 16;

    extern __shared__ char smem[];
    const int t = threadIdx.x, lane = t & 31, wid = t >> 5;
    const int batch = blockIdx.y >> 7;
    const int m0 = (blockIdx.y & 127) * 128;
    const int n0 = blockIdx.x * BN;
    const int wm = (wid & 3) * 32;
    const int wn = (wid >> 2) * (BN / 2);

    const __nv_bfloat16 *A1, *A2;
    if (Khalf < Ktot) { A1 = A.p[2 * batch]; A2 = A.p[2 * batch + 1]; }
    else              { A1 = A.p[batch];     A2 = A1; }

    const uint32_t sbase = smem_u32(smem);
    const uint32_t a_addr0 = sbase + (uint32_t)((wm + (lane & 15)) * AW * 2 + (lane >> 4) * 16);
    const int grp = lane >> 3;
    const int b_r = (lane & 7) + ((grp >= 2) ? 8 : 0);
    const uint32_t b_addr0 = sbase + ABYTES + (uint32_t)((wn + b_r) * AW * 2 + (grp & 1) * 16);

    float acc[2][NT][4];
#pragma unroll
    for (int i = 0; i < 2; i++)
#pragma unroll
        for (int j = 0; j < NT; j++)
#pragma unroll
            for (int q = 0; q < 4; q++) acc[i][j][q] = 0.0f;

    auto load_chunk = [&](int c) {
        const int stg = c % 3;
        int kk = c * 32;
        const __nv_bfloat16* Ab = A1;
        if (kk >= Khalf) { Ab = A2; kk -= Khalf; }
        uint32_t sA = sbase + stg * STG;
#pragma unroll
        for (int i = 0; i < 2; i++) {
            int idx = t + i * 256, r = idx >> 2, c8 = idx & 3;
            CP_ASYNC16(sA + (uint32_t)(r * AW * 2 + c8 * 16),
                       Ab + (size_t)(m0 + r) * Khalf + kk + c8 * 8);
        }
        uint32_t sB = sA + ABYTES;
#pragma unroll
        for (int i = 0; i < BN / 64; i++) {
            int idx = t + i * 256, r = idx >> 2, c8 = idx & 3;
            CP_ASYNC16(sB + (uint32_t)(r * AW * 2 + c8 * 16),
                       Wt + (size_t)(n0 + r) * Ktot + c * 32 + c8 * 8);
        }
        CP_COMMIT();
    };

    const int NC = Ktot >> 5;
    load_chunk(0);
    if (NC > 1) load_chunk(1);

    for (int c = 0; c < NC; c++) {
        if (c + 1 < NC) { asm volatile("cp.async.wait_group 1;" ::: "memory"); }
        else            { asm volatile("cp.async.wait_group 0;" ::: "memory"); }
        __syncthreads();
        if (c + 2 < NC) load_chunk(c + 2);

        const uint32_t aa = a_addr0 + (c % 3) * STG;
        const uint32_t bb = b_addr0 + (c % 3) * STG;
#pragma unroll
        for (int kk = 0; kk < 2; kk++) {
            uint32_t Af[2][4];
            LDSM4(Af[0], aa + kk * 32);
            LDSM4(Af[1], aa + 16 * AW * 2 + kk * 32);
#pragma unroll
            for (int np = 0; np < NT / 2; np++) {
                uint32_t B4[4];
                LDSM4(B4, bb + np * 16 * AW * 2 + kk * 32);
#pragma unroll
                for (int mt = 0; mt < 2; mt++) {
                    mma_bf(acc[mt][2 * np],     Af[mt], B4[0], B4[1]);
                    mma_bf(acc[mt][2 * np + 1], Af[mt], B4[2], B4[3]);
                }
            }
        }
    }

#pragma unroll
    for (int mt = 0; mt < 2; mt++) {
        int row = batch * NB + m0 + wm + mt * 16 + (lane >> 2);
#pragma unroll
        for (int nt = 0; nt < NT; nt++) {
            int col = n0 + wn + nt * 8 + (lane & 3) * 2;
            float b0v = bias[col], b1v = bias[col + 1];
            float x0 = acc[mt][nt][0] + b0v, x1 = acc[mt][nt][1] + b1v;
            float x2 = acc[mt][nt][2] + b0v, x3 = acc[mt][nt][3] + b1v;
            if (act) { x0 = geluf(x0); x1 = geluf(x1); x2 = geluf(x2); x3 = geluf(x3); }
            if (OUTBF) {
                __nv_bfloat16* C = (__nv_bfloat16*)Cv;
                *reinterpret_cast<__nv_bfloat162*>(C + (size_t)row * N + col) =
                    __floats2bfloat162_rn(x0, x1);
                *reinterpret_cast<__nv_bfloat162*>(C + (size_t)(row + 8) * N + col) =
                    __floats2bfloat162_rn(x2, x3);
            } else {
                float* C = (float*)Cv;
                *reinterpret_cast<float2*>(C + (size_t)row * N + col)       = make_float2(x0, x1);
                *reinterpret_cast<float2*>(C + (size_t)(row + 8) * N + col) = make_float2(x2, x3);
            }
        }
    }
}

// ================= bf16x3 precise GEMM (info path): D = Ah*Bh + Ah*Bl + Al*Bh =================
// 2-stage double buffer, occ 2. Stage layout: [Ah | Al | Bh | Bl].
template<int BN>
__global__ void __launch_bounds__(256, 2) gemm_bf3(
    APtrsB Ah, APtrsB Al, int Ktot,
    const __nv_bfloat16* __restrict__ Wh, const __nv_bfloat16* __restrict__ Wl, int N,
    const float* __restrict__ bias, float* __restrict__ C, int act)
{
    constexpr int AW = 40;
    constexpr int ABYTES = 128 * AW * 2;
    constexpr int BBYTES = BN * AW * 2;
    constexpr int STG = 2 * ABYTES + 2 * BBYTES;
    constexpr int NT = BN / 16;

    extern __shared__ char smem[];
    const int t = threadIdx.x, lane = t & 31, wid = t >> 5;
    const int batch = blockIdx.y >> 7;
    const int m0 = (blockIdx.y & 127) * 128;
    const int n0 = blockIdx.x * BN;
    const int wm = (wid & 3) * 32;
    const int wn = (wid >> 2) * (BN / 2);

    const __nv_bfloat16* A1h = Ah.p[batch];
    const __nv_bfloat16* A1l = Al.p[batch];
    C += (size_t)batch * NB * N;

    const uint32_t sbase = smem_u32(smem);
    const uint32_t a_addr0 = sbase + (uint32_t)((wm + (lane & 15)) * AW * 2 + (lane >> 4) * 16);
    const int grp = lane >> 3;
    const int b_r = (lane & 7) + ((grp >= 2) ? 8 : 0);
    const uint32_t b_addr0 = sbase + 2 * ABYTES + (uint32_t)((wn + b_r) * AW * 2 + (grp & 1) * 16);

    float acc[2][NT][4];
#pragma unroll
    for (int i = 0; i < 2; i++)
#pragma unroll
        for (int j = 0; j < NT; j++)
#pragma unroll
            for (int q = 0; q < 4; q++) acc[i][j][q] = 0.0f;

    auto load_chunk = [&](int c) {
        const int stg = c & 1;
        const int kk = c * 32;
        uint32_t base = sbase + stg * STG;
#pragma unroll
        for (int i = 0; i < 2; i++) {
            int idx = t + i * 256, r = idx >> 2, c8 = idx & 3;
            uint32_t off = (uint32_t)(r * AW * 2 + c8 * 16);
            size_t go = (size_t)(m0 + r) * Ktot + kk + c8 * 8;
            CP_ASYNC16(base + off,           A1h + go);
            CP_ASYNC16(base + ABYTES + off,  A1l + go);
        }
        uint32_t sB = base + 2 * ABYTES;
#pragma unroll
        for (int i = 0; i < BN / 64; i++) {
            int idx = t + i * 256, r = idx >> 2, c8 = idx & 3;
            uint32_t off = (uint32_t)(r * AW * 2 + c8 * 16);
            size_t go = (size_t)(n0 + r) * Ktot + kk + c8 * 8;
            CP_ASYNC16(sB + off,           Wh + go);
            CP_ASYNC16(sB + BBYTES + off,  Wl + go);
        }
        CP_COMMIT();
    };

    const int NC = Ktot >> 5;
    load_chunk(0);
    if (NC > 1) load_chunk(1);

    for (int c = 0; c < NC; c++) {
        if (c + 1 < NC) { asm volatile("cp.async.wait_group 1;" ::: "memory"); }
        else            { asm volatile("cp.async.wait_group 0;" ::: "memory"); }
        __syncthreads();

        const uint32_t aa = a_addr0 + (c & 1) * STG;
        const uint32_t bb = b_addr0 + (c & 1) * STG;
#pragma unroll
        for (int kk = 0; kk < 2; kk++) {
            uint32_t Ahf[2][4], Alf[2][4];
            LDSM4(Ahf[0], aa + kk * 32);
            LDSM4(Ahf[1], aa + 16 * AW * 2 + kk * 32);
            LDSM4(Alf[0], aa + ABYTES + kk * 32);
            LDSM4(Alf[1], aa + ABYTES + 16 * AW * 2 + kk * 32);
#pragma unroll
            for (int np = 0; np < NT / 2; np++) {
                uint32_t Bh4[4], Bl4[4];
                LDSM4(Bh4, bb + np * 16 * AW * 2 + kk * 32);
                LDSM4(Bl4, bb + BBYTES + np * 16 * AW * 2 + kk * 32);
#pragma unroll
                for (int mt = 0; mt < 2; mt++) {
                    mma_bf(acc[mt][2 * np],     Ahf[mt], Bh4[0], Bh4[1]);
                    mma_bf(acc[mt][2 * np],     Ahf[mt], Bl4[0], Bl4[1]);
                    mma_bf(acc[mt][2 * np],     Alf[mt], Bh4[0], Bh4[1]);
                    mma_bf(acc[mt][2 * np + 1], Ahf[mt], Bh4[2], Bh4[3]);
                    mma_bf(acc[mt][2 * np + 1], Ahf[mt], Bl4[2], Bl4[3]);
                    mma_bf(acc[mt][2 * np + 1], Alf[mt], Bh4[2], Bh4[3]);
                }
            }
        }
        __syncthreads();                 // stage c&1 free to overwrite
        if (c + 2 < NC) load_chunk(c + 2);
    }

#pragma unroll
    for (int mt = 0; mt < 2; mt++) {
        int row = m0 + wm + mt * 16 + (lane >> 2);
#pragma unroll
        for (int nt = 0; nt < NT; nt++) {
            int col = n0 + wn + nt * 8 + (lane & 3) * 2;
            float b0v = bias[col], b1v = bias[col + 1];
            float x0 = acc[mt][nt][0] + b0v, x1 = acc[mt][nt][1] + b1v;
            float x2 = acc[mt][nt][2] + b0v, x3 = acc[mt][nt][3] + b1v;
            if (act) { x0 = geluf(x0); x1 = geluf(x1); x2 = geluf(x2); x3 = geluf(x3); }
            *reinterpret_cast<float2*>(C + (size_t)row * N + col)       = make_float2(x0, x1);
            *reinterpret_cast<float2*>(C + (size_t)(row + 8) * N + col) = make_float2(x2, x3);
        }
    }
}

// ---------------- feature fp32 -> bf16 (hi) ----------------
__global__ void cvt_bf_k(const float4* __restrict__ s0, const float4* __restrict__ s1,
                         const float4* __restrict__ s2, const float4* __restrict__ s3,
                         __nv_bfloat16* __restrict__ d)
{
    int i = blockIdx.x * blockDim.x + threadIdx.x;
    const int per = NB * 768 / 4;
    if (i >= 4 * per) return;
    int f = i / per, j = i - f * per;
    const float4* s = (f == 0 ? s0 : f == 1 ? s1 : f == 2 ? s2 : s3);
    float4 v = s[j];
    __nv_bfloat162* o = reinterpret_cast<__nv_bfloat162*>(d + (size_t)f * NB * 768 + (size_t)j * 4);
    o[0] = __floats2bfloat162_rn(v.x, v.y);
    o[1] = __floats2bfloat162_rn(v.z, v.w);
}

// ---------------- lo residual for img/txt (hi already in g_featbf) ----------------
__global__ void lo_feat_k(const float4* __restrict__ x0, const float4* __restrict__ x1,
                          const __nv_bfloat16* __restrict__ hi, __nv_bfloat16* __restrict__ lo)
{
    int i = blockIdx.x * blockDim.x + threadIdx.x;   // over 2*NB*768/4
    const int per = NB * 768 / 4;
    if (i >= 2 * per) return;
    const float4* x = (i < per) ? x0 : x1;
    int j = (i < per) ? i : i - per;
    float4 v = x[j];
    const __nv_bfloat162* hp = reinterpret_cast<const __nv_bfloat162*>(hi + (size_t)i * 4);
    __nv_bfloat162 h0 = hp[0], h1 = hp[1];
    __nv_bfloat162* o = reinterpret_cast<__nv_bfloat162*>(lo + (size_t)i * 4);
    o[0] = __floats2bfloat162_rn(v.x - __bfloat162float(h0.x), v.y - __bfloat162float(h0.y));
    o[1] = __floats2bfloat162_rn(v.z - __bfloat162float(h1.x), v.w - __bfloat162float(h1.y));
}

// ---------------- fp32 -> bf16 hi + lo ----------------
__global__ void split_fp32_k(const float4* __restrict__ x, __nv_bfloat16* __restrict__ h,
                             __nv_bfloat16* __restrict__ l, int n4)
{
    int i = blockIdx.x * blockDim.x + threadIdx.x;
    if (i >= n4) return;
    float4 v = x[i];
    __nv_bfloat162 h0 = __floats2bfloat162_rn(v.x, v.y);
    __nv_bfloat162 h1 = __floats2bfloat162_rn(v.z, v.w);
    reinterpret_cast<__nv_bfloat162*>(h + (size_t)i * 4)[0] = h0;
    reinterpret_cast<__nv_bfloat162*>(h + (size_t)i * 4)[1] = h1;
    __nv_bfloat162 l0 = __floats2bfloat162_rn(v.x - __bfloat162float(h0.x), v.y - __bfloat162float(h0.y));
    __nv_bfloat162 l1 = __floats2bfloat162_rn(v.z - __bfloat162float(h1.x), v.w - __bfloat162float(h1.y));
    reinterpret_cast<__nv_bfloat162*>(l + (size_t)i * 4)[0] = l0;
    reinterpret_cast<__nv_bfloat162*>(l + (size_t)i * 4)[1] = l1;
}

// ---------------- combined transpose: 7 bf16 jobs, one launch ----------------
struct TJobs {
    const float* s[7];
    __nv_bfloat16* d[7];
    int K[7], N[7], t0[7];
    int njobs;
};
__global__ void transpose_combo_k(TJobs J) {
    __shared__ float tile[32][33];
    int bx = blockIdx.x;
    int j = 0;
#pragma unroll
    for (int q = 1; q < 7; q++) if (q < J.njobs && bx >= J.t0[q]) j = q;
    int local = bx - J.t0[j];
    int tilesx = J.N[j] / 32;
    int txb = local % tilesx, tyb = local / tilesx;
    const float* s = J.s[j];
    int K = J.K[j], N = J.N[j];
    int n = txb * 32 + threadIdx.x;
    int k = tyb * 32 + threadIdx.y;
#pragma unroll
    for (int i = 0; i < 32; i += 8) tile[threadIdx.y + i][threadIdx.x] = s[(size_t)(k + i) * N + n];
    __syncthreads();
    int n2 = txb * 32 + threadIdx.y;
    int k2 = tyb * 32 + threadIdx.x;
    __nv_bfloat16* d = J.d[j];
#pragma unroll
    for (int i = 0; i < 32; i += 8)
        d[(size_t)(n2 + i) * K + k2] = __float2bfloat16(tile[threadIdx.x][threadIdx.y + i]);
}

// ---------------- transpose + hi/lo split (info weights) ----------------
__global__ void transpose_split_k(const float* __restrict__ s, __nv_bfloat16* __restrict__ dh,
                                  __nv_bfloat16* __restrict__ dl, int K, int N) {
    __shared__ float tile[32][33];
    int n = blockIdx.x * 32 + threadIdx.x;
    int k = blockIdx.y * 32 + threadIdx.y;
#pragma unroll
    for (int i = 0; i < 32; i += 8) tile[threadIdx.y + i][threadIdx.x] = s[(size_t)(k + i) * N + n];
    __syncthreads();
    int n2 = blockIdx.x * 32 + threadIdx.y;
    int k2 = blockIdx.y * 32 + threadIdx.x;
#pragma unroll
    for (int i = 0; i < 32; i += 8) {
        float v = tile[threadIdx.x][threadIdx.y + i];
        __nv_bfloat16 h = __float2bfloat16(v);
        dh[(size_t)(n2 + i) * K + k2] = h;
        dl[(size_t)(n2 + i) * K + k2] = __float2bfloat16(v - __bfloat162float(h));
    }
}

// ---------------- final dot head ----------------
__global__ void dot_head_k(const float* __restrict__ Hin, int K, int rows,
                           const float* __restrict__ w, const float* __restrict__ b,
                           float* __restrict__ outrow)
{
    int gw = (blockIdx.x * blockDim.x + threadIdx.x) >> 5;
    int lane = threadIdx.x & 31;
    if (gw >= rows) return;
    const float* row = Hin + (size_t)gw * K;
    float s = 0.f;
    for (int k = lane * 4; k < K; k += 128) {
        float4 v = *reinterpret_cast<const float4*>(row + k);
        float4 wv = *reinterpret_cast<const float4*>(w + k);
        s += v.x * wv.x + v.y * wv.y + v.z * wv.z + v.w * wv.w;
    }
#pragma unroll
    for (int o = 16; o; o >>= 1) s += __shfl_xor_sync(0xffffffffu, s, o);
    if (lane == 0) outrow[gw] = sigf(s + b[0]);
}

// ---------------- geometric quality + norms ----------------
__global__ void rowstats_k(const float* __restrict__ f0, const float* __restrict__ f1,
                           const float* __restrict__ f2, const float* __restrict__ f3,
                           float* __restrict__ out)
{
    int gw = (blockIdx.x * blockDim.x + threadIdx.x) >> 5;
    int lane = threadIdx.x & 31;
    if (gw >= 4 * NB) return;
    int feat = gw >> 14;
    int m = gw & (NB - 1);
    const float* f = (feat == 0 ? f0 : feat == 1 ? f1 : feat == 2 ? f2 : f3) + (size_t)m * HD;
    double sum = 0.0, ssq = 0.0;
    int cnt = 0;
    for (int k = lane * 4; k < HD; k += 128) {
        float4 v = *reinterpret_cast<const float4*>(f + k);
        sum += (double)v.x + v.y + v.z + v.w;
        ssq += (double)v.x * v.x + (double)v.y * v.y + (double)v.z * v.z + (double)v.w * v.w;
        cnt += (fabsf(v.x) > 0.01f) + (fabsf(v.y) > 0.01f) + (fabsf(v.z) > 0.01f) + (fabsf(v.w) > 0.01f);
    }
#pragma unroll
    for (int o = 16; o; o >>= 1) {
        sum += __shfl_xor_sync(0xffffffffu, sum, o);
        ssq += __shfl_xor_sync(0xffffffffu, ssq, o);
        cnt += __shfl_xor_sync(0xffffffffu, cnt, o);
    }
    if (lane == 0) {
        float n = (float)sqrt(ssq);
        float nq = sigf((n - 1.0f) * 2.0f);
        float sp = cnt * (1.0f / 768.0f);
        double var = (ssq - sum * sum / 768.0) / 767.0;
        if (var < 0.0) var = 0.0;
        float sq = sigf((float)sqrt(var) * 10.0f - 1.0f);
        out[feat * NB + m] = (nq + sp + sq) * (1.0f / 3.0f);
        if (feat < 2) g_norm[feat * NB + m] = n;
    }
}

// ---------------- info final (2*NB rows) ----------------
__global__ void info_final_k(const float* __restrict__ enc, float* __restrict__ outrow)
{
    int gw = (blockIdx.x * blockDim.x + threadIdx.x) >> 5;
    int lane = threadIdx.x & 31;
    if (gw >= 2 * NB) return;
    const float* e = enc + (size_t)gw * 64;
    float x0 = e[lane], x1 = e[lane + 32];
    int d0 = (int)rintf(sigf(x0) * 10.0f);
    int d1 = (int)rintf(sigf(x1) * 10.0f);
    float ent = 0.f;
#pragma unroll
    for (int b = 0; b < 11; b++) {
        int c = __popc(__ballot_sync(0xffffffffu, d0 == b)) +
                __popc(__ballot_sync(0xffffffffu, d1 == b));
        if (c > 0) {
            float p = c * (1.0f / 64.0f);
            ent -= p * logf(p + 1e-8f);
        }
    }
    if (lane == 0) {
        float eq = sigf(ent - 2.0f);
        float n = g_norm[gw];
        float cq = (n > 0.01f) ? (1.0f / 768.0f) : 0.0f;
        float t = n / fmaxf(n, 1e-12f);
        float dq = sigf(t * t - 0.5f);
        outrow[gw] = (eq + cq + dq) * (1.0f / 3.0f);
    }
}

__global__ void overall_k(float* __restrict__ out)
{
    int i = blockIdx.x * blockDim.x + threadIdx.x;
    if (i >= NB) return;
    float v = out[0 * NB + i] + out[1 * NB + i] + out[4 * NB + i] + out[5 * NB + i] +
              out[7 * NB + i] + 0.5f * (out[8 * NB + i] + out[9 * NB + i]);
    out[17 * NB + i] = v * (1.0f / 6.0f);
}

// ---------------- host ----------------
template<int BN, bool OUTBF>
static void launch_bf(cudaStream_t st, APtrsB A, int nb, int Khalf, int Ktot,
                      const __nv_bfloat16* Wt, int N, const float* bias, void* C, int act)
{
    int smemB = 3 * (128 + BN) * 40 * 2;
    cudaFuncSetAttribute(gemm_bf16<BN, OUTBF>, cudaFuncAttributeMaxDynamicSharedMemorySize, smemB);
    dim3 g(N / BN, nb * 128);
    gemm_bf16<BN, OUTBF><<<g, 256, smemB, st>>>(A, Khalf, Ktot, Wt, N, bias, C, act);
}
template<int BN>
static void launch_bf3(cudaStream_t st, APtrsB Ah, APtrsB Al, int nb, int Ktot,
                       const __nv_bfloat16* Wh, const __nv_bfloat16* Wl, int N,
                       const float* bias, float* C, int act)
{
    int smemB = 2 * (2 * 128 * 40 * 2 + 2 * BN * 40 * 2);
    cudaFuncSetAttribute(gemm_bf3<BN>, cudaFuncAttributeMaxDynamicSharedMemorySize, smemB);
    dim3 g(N / BN, nb * 128);
    gemm_bf3<BN><<<g, 256, smemB, st>>>(Ah, Al, Ktot, Wh, Wl, N, bias, C, act);
}

extern "C" void kernel_launch(void* const* d_in, const int* in_sizes, int n_in,
                              void* d_out, int out_size)
{
    const float* img  = (const float*)d_in[0];
    const float* txt  = (const float*)d_in[1];
    const float* eimg = (const float*)d_in[2];
    const float* etxt = (const float*)d_in[3];
    const float* info_w1 = (const float*)d_in[5];
    const float* info_b1 = (const float*)d_in[6];
    const float* info_w2 = (const float*)d_in[7];
    const float* info_b2 = (const float*)d_in[8];
    const float* imp_w1  = (const float*)d_in[9];
    const float* imp_b1  = (const float*)d_in[10];
    const float* imp_w2  = (const float*)d_in[11];
    const float* imp_b2  = (const float*)d_in[12];
    const float* disc_w1 = (const float*)d_in[13];
    const float* disc_b1 = (const float*)d_in[14];
    const float* disc_w2 = (const float*)d_in[15];
    const float* disc_b2 = (const float*)d_in[16];
    const float* disc_w3 = (const float*)d_in[17];
    const float* disc_b3 = (const float*)d_in[18];
    const float* cons_w1 = (const float*)d_in[19];
    const float* cons_b1 = (const float*)d_in[20];
    const float* cons_w2 = (const float*)d_in[21];
    const float* cons_b2 = (const float*)d_in[22];
    const float* cons_w3 = (const float*)d_in[23];
    const float* cons_b3 = (const float*)d_in[24];
    const float* diff_w1 = (const float*)d_in[25];
    const float* diff_b1 = (const float*)d_in[26];
    const float* diff_w2 = (const float*)d_in[27];
    const float* diff_b2 = (const float*)d_in[28];
    const float* diff_w3 = (const float*)d_in[29];
    const float* diff_b3 = (const float*)d_in[30];

    float* out = (float*)d_out;

    __nv_bfloat16 *featbf, *lo1, *h2, *l2, *scrAbf, *scrCbf;
    __nv_bfloat16 *w_imp1, *w_disc1, *w_disc2, *w_cons1, *w_cons2, *w_diff1, *w_diff2;
    __nv_bfloat16 *wi1h, *wi1l, *wi2h, *wi2l;
    float *scrB, *scrB2, *scrB3, *scrC, *scrD, *scrD2;
    cudaGetSymbolAddress((void**)&featbf, g_featbf);
    cudaGetSymbolAddress((void**)&lo1, g_lo1);
    cudaGetSymbolAddress((void**)&h2, g_h2);
    cudaGetSymbolAddress((void**)&l2, g_l2);
    cudaGetSymbolAddress((void**)&scrAbf, g_scrAbf);
    cudaGetSymbolAddress((void**)&scrCbf, g_scrCbf);
    cudaGetSymbolAddress((void**)&scrB, g_scrB);
    cudaGetSymbolAddress((void**)&scrB2, g_scrB2);
    cudaGetSymbolAddress((void**)&scrB3, g_scrB3);
    cudaGetSymbolAddress((void**)&scrC, g_scrC);
    cudaGetSymbolAddress((void**)&scrD, g_scrD);
    cudaGetSymbolAddress((void**)&scrD2, g_scrD2);
    cudaGetSymbolAddress((void**)&w_imp1, g_w_imp1);
    cudaGetSymbolAddress((void**)&w_disc1, g_w_disc1);
    cudaGetSymbolAddress((void**)&w_disc2, g_w_disc2);
    cudaGetSymbolAddress((void**)&w_cons1, g_w_cons1);
    cudaGetSymbolAddress((void**)&w_cons2, g_w_cons2);
    cudaGetSymbolAddress((void**)&w_diff1, g_w_diff1);
    cudaGetSymbolAddress((void**)&w_diff2, g_w_diff2);
    cudaGetSymbolAddress((void**)&wi1h, g_wi1h);
    cudaGetSymbolAddress((void**)&wi1l, g_wi1l);
    cudaGetSymbolAddress((void**)&wi2h, g_wi2h);
    cudaGetSymbolAddress((void**)&wi2l, g_wi2l);

    const __nv_bfloat16* bimg  = featbf;
    const __nv_bfloat16* btxt  = featbf + (size_t)NB * 768;
    const __nv_bfloat16* beimg = featbf + (size_t)2 * NB * 768;
    const __nv_bfloat16* betxt = featbf + (size_t)3 * NB * 768;

    static cudaStream_t s1 = nullptr, s2 = nullptr;
    static cudaEvent_t e0 = nullptr, eT = nullptr, e1 = nullptr, e2 = nullptr;
    if (!s1) {
        cudaStreamCreateWithFlags(&s1, cudaStreamNonBlocking);
        cudaStreamCreateWithFlags(&s2, cudaStreamNonBlocking);
        cudaEventCreateWithFlags(&e0, cudaEventDisableTiming);
        cudaEventCreateWithFlags(&eT, cudaEventDisableTiming);
        cudaEventCreateWithFlags(&e1, cudaEventDisableTiming);
        cudaEventCreateWithFlags(&e2, cudaEventDisableTiming);
    }

    // fork
    cudaEventRecord(e0, 0);
    cudaStreamWaitEvent(s1, e0, 0);
    cudaStreamWaitEvent(s2, e0, 0);

    // s1: rowstats (inputs only)
    rowstats_k<<<(4 * NB) / 8, 256, 0, s1>>>(img, txt, eimg, etxt, out);

    // main: feature conversion + weight transposes
    cvt_bf_k<<<(4 * NB * 768 / 4 + 255) / 256, 256>>>(
        (const float4*)img, (const float4*)txt, (const float4*)eimg, (const float4*)etxt, featbf);
    {
        TJobs J;
        const float* srcs[7] = { imp_w1, disc_w1, disc_w2, cons_w1, cons_w2, diff_w1, diff_w2 };
        __nv_bfloat16* dsts[7] = { w_imp1, w_disc1, w_disc2, w_cons1, w_cons2, w_diff1, w_diff2 };
        int Ks[7] = { 768, 768, 256, 1536, 768, 1536, 768 };
        int Ns[7] = { 384, 256, 64, 768, 384, 768, 384 };
        int tot = 0;
        for (int j = 0; j < 7; j++) {
            J.s[j] = srcs[j]; J.d[j] = dsts[j]; J.K[j] = Ks[j]; J.N[j] = Ns[j];
            J.t0[j] = tot;
            tot += (Ks[j] / 32) * (Ns[j] / 32);
        }
        J.njobs = 7;
        dim3 b(32, 8);
        transpose_combo_k<<<tot, b>>>(J);
    }
    {
        dim3 b(32, 8);
        transpose_split_k<<<dim3(256 / 32, 768 / 32), b>>>(info_w1, wi1h, wi1l, 768, 256);
        transpose_split_k<<<dim3(64 / 32, 256 / 32), b>>>(info_w2, wi2h, wi2l, 256, 64);
    }
    cudaEventRecord(eT, 0);
    cudaStreamWaitEvent(s1, eT, 0);
    cudaStreamWaitEvent(s2, eT, 0);

    // s1: information (rows 4,5) — bf16x3 precise
    {
        lo_feat_k<<<(2 * NB * 768 / 4 + 255) / 256, 256, 0, s1>>>(
            (const float4*)img, (const float4*)txt, featbf, lo1);
        APtrsB ah = {{ bimg, btxt, nullptr, nullptr }};
        APtrsB al = {{ lo1, lo1 + (size_t)NB * 768, nullptr, nullptr }};
        launch_bf3<128>(s1, ah, al, 2, 768, wi1h, wi1l, 256, info_b1, scrC, 1);
        split_fp32_k<<<(2 * NB * 256 / 4 + 255) / 256, 256, 0, s1>>>(
            (const float4*)scrC, h2, l2, 2 * NB * 256 / 4);
        APtrsB ah2 = {{ h2, h2 + (size_t)NB * 256, nullptr, nullptr }};
        APtrsB al2 = {{ l2, l2 + (size_t)NB * 256, nullptr, nullptr }};
        launch_bf3<64>(s1, ah2, al2, 2, 256, wi2h, wi2l, 64, info_b2, scrD2, 0);
        info_final_k<<<(2 * NB) / 8, 256, 0, s1>>>(scrD2, out + 4 * NB);
        cudaEventRecord(e1, s1);
    }

    // main: importance (rows 8..11) + discriminator (rows 12..15)
    {
        APtrsB a = {{ bimg, btxt, beimg, betxt }};
        launch_bf<128, false>(0, a, 4, 768, 768, w_imp1, 384, imp_b1, scrB, 1);
        dot_head_k<<<(4 * NB) / 8, 256>>>(scrB, 384, 4 * NB, imp_w2, imp_b2, out + 8 * NB);

        APtrsB ad = {{ bimg, beimg, btxt, betxt }};
        launch_bf<128, true>(0, ad, 4, 768, 768, w_disc1, 256, disc_b1, scrCbf, 1);
        APtrsB ad2 = {{ scrCbf, scrCbf + (size_t)NB * 256, scrCbf + (size_t)2 * NB * 256,
                        scrCbf + (size_t)3 * NB * 256 }};
        launch_bf<64, false>(0, ad2, 4, 256, 256, w_disc2, 64, disc_b2, scrD, 1);
        dot_head_k<<<(4 * NB) / 8, 256>>>(scrD, 64, 4 * NB, disc_w3, disc_b3, out + 12 * NB);
    }

    // s2: consistency (rows 6,7) then difficulty (row 16)
    {
        APtrsB a = {{ bimg, btxt, beimg, betxt }};
        launch_bf<128, true>(s2, a, 2, 768, 1536, w_cons1, 768, cons_b1, scrAbf, 1);
        APtrsB a2 = {{ scrAbf, scrAbf + (size_t)NB * 768, nullptr, nullptr }};
        launch_bf<128, false>(s2, a2, 2, 768, 768, w_cons2, 384, cons_b2, scrB2, 1);
        dot_head_k<<<(2 * NB) / 8, 256, 0, s2>>>(scrB2, 384, 2 * NB, cons_w3, cons_b3, out + 6 * NB);

        APtrsB ad = {{ beimg, betxt, nullptr, nullptr }};
        launch_bf<128, true>(s2, ad, 1, 768, 1536, w_diff1, 768, diff_b1, scrAbf, 1);
        APtrsB ad2 = {{ scrAbf, nullptr, nullptr, nullptr }};
        launch_bf<128, false>(s2, ad2, 1, 768, 768, w_diff2, 384, diff_b2, scrB3, 1);
        dot_head_k<<<NB / 8, 256, 0, s2>>>(scrB3, 384, NB, diff_w3, diff_b3, out + 16 * NB);
        cudaEventRecord(e2, s2);
    }

    // join + overall
    cudaStreamWaitEvent(0, e1, 0);
    cudaStreamWaitEvent(0, e2, 0);
    overall_k<<<NB / 256, 256>>>(out);
}

// round 10
// speedup vs baseline: 1.3496x; 1.0202x over previous
#include <cuda_runtime.h>
#include <cuda_bf16.h>
#include <cstdint>

#define NB 16384
#define HD 768

// ---------------- scratch (device globals; no allocs allowed) ----------------
__device__ __nv_bfloat16 g_featbf[4 * NB * 768];     // bf16 hi of the 4 features
__device__ __nv_bfloat16 g_lo1[2 * NB * 768];        // bf16 lo of img, txt (info path)
__device__ __nv_bfloat16 g_h2[2 * NB * 256];
__device__ __nv_bfloat16 g_l2[2 * NB * 256];
__device__ __nv_bfloat16 g_scrAbf[2 * NB * 768];     // cons1 / diff1 outputs (bf16)
__device__ __nv_bfloat16 g_scrCbf[4 * NB * 256];     // disc1 outputs (bf16)
__device__ float g_scrB [4 * NB * 384];              // imp1 outputs (fp32)     [main]
__device__ float g_scrB2[2 * NB * 384];              // cons2 outputs (fp32)    [s2]
__device__ float g_scrB3[1 * NB * 384];              // diff2 outputs (fp32)    [main]
__device__ float g_scrC [2 * NB * 256];              // info1 outputs (fp32)    [s1]
__device__ float g_scrD [4 * NB * 64];               // disc2 outputs (fp32)    [main]
__device__ float g_scrD2[2 * NB * 64];               // info2 outputs (fp32)    [s1]
__device__ __nv_bfloat16 g_scrAbf3[NB * 768];        // diff1 output (bf16)     [main]
__device__ float g_norm[2 * NB];
__device__ __nv_bfloat16 g_w_imp1[384 * 768];
__device__ __nv_bfloat16 g_w_disc1[256 * 768];
__device__ __nv_bfloat16 g_w_disc2[64 * 256];
__device__ __nv_bfloat16 g_w_cons1[768 * 1536];
__device__ __nv_bfloat16 g_w_cons2[384 * 768];
__device__ __nv_bfloat16 g_w_diff1[768 * 1536];
__device__ __nv_bfloat16 g_w_diff2[384 * 768];
__device__ __nv_bfloat16 g_wi1h[256 * 768], g_wi1l[256 * 768];
__device__ __nv_bfloat16 g_wi2h[64 * 256],  g_wi2l[64 * 256];

__device__ __forceinline__ float sigf(float x) { return 1.0f / (1.0f + expf(-x)); }
__device__ __forceinline__ float geluf(float x) { return 0.5f * x * (1.0f + erff(x * 0.70710678118654752f)); }

__device__ __forceinline__ uint32_t smem_u32(const void* p) {
    uint32_t a;
    asm("{ .reg .u64 t; cvta.to.shared.u64 t, %1; cvt.u32.u64 %0, t; }" : "=r"(a) : "l"(p));
    return a;
}
__device__ __forceinline__ void mma_bf(float* d, const uint32_t* a, uint32_t b0, uint32_t b1) {
    asm volatile(
        "mma.sync.aligned.m16n8k16.row.col.f32.bf16.bf16.f32 "
        "{%0,%1,%2,%3}, {%4,%5,%6,%7}, {%8,%9}, {%0,%1,%2,%3};"
        : "+f"(d[0]), "+f"(d[1]), "+f"(d[2]), "+f"(d[3])
        : "r"(a[0]), "r"(a[1]), "r"(a[2]), "r"(a[3]), "r"(b0), "r"(b1));
}
#define LDSM4(r, addr) \
    asm volatile("ldmatrix.sync.aligned.m8n8.x4.shared.b16 {%0,%1,%2,%3}, [%4];" \
        : "=r"((r)[0]), "=r"((r)[1]), "=r"((r)[2]), "=r"((r)[3]) : "r"(addr))
#define CP_ASYNC16(dst, src) \
    asm volatile("cp.async.cg.shared.global [%0], [%1], 16;" :: "r"(dst), "l"(src))
#define CP_COMMIT() asm volatile("cp.async.commit_group;" ::: "memory")

struct APtrsB { const __nv_bfloat16* p[4]; };

// ================= bf16 GEMM: BM=128, BK=64, 3-stage, occ 2 =================
// AW=72 bf16 (144B row stride): 16B aligned, ldmatrix conflict-free.
template<int BN, bool OUTBF>
__global__ void __launch_bounds__(256, 2) gemm_bf16(
    APtrsB A, int Khalf, int Ktot, const __nv_bfloat16* __restrict__ Wt, int N,
    const float* __restrict__ bias, void* __restrict__ Cv, int act)
{
    constexpr int AW = 72;
    constexpr int ABYTES = 128 * AW * 2;     // 18432
    constexpr int BBYTES = BN * AW * 2;
    constexpr int STG = ABYTES + BBYTES;
    constexpr int NT = BN / 16;

    extern __shared__ char smem[];
    const int t = threadIdx.x, lane = t & 31, wid = t >> 5;
    const int batch = blockIdx.y >> 7;
    const int m0 = (blockIdx.y & 127) * 128;
    const int n0 = blockIdx.x * BN;
    const int wm = (wid & 3) * 32;
    const int wn = (wid >> 2) * (BN / 2);

    const __nv_bfloat16 *A1, *A2;
    if (Khalf < Ktot) { A1 = A.p[2 * batch]; A2 = A.p[2 * batch + 1]; }
    else              { A1 = A.p[batch];     A2 = A1; }

    const uint32_t sbase = smem_u32(smem);
    const uint32_t a_addr0 = sbase + (uint32_t)((wm + (lane & 15)) * (AW * 2) + (lane >> 4) * 16);
    const int grp = lane >> 3;
    const int b_r = (lane & 7) + ((grp >= 2) ? 8 : 0);
    const uint32_t b_addr0 = sbase + ABYTES + (uint32_t)((wn + b_r) * (AW * 2) + (grp & 1) * 16);

    float acc[2][NT][4];
#pragma unroll
    for (int i = 0; i < 2; i++)
#pragma unroll
        for (int j = 0; j < NT; j++)
#pragma unroll
            for (int q = 0; q < 4; q++) acc[i][j][q] = 0.0f;

    auto load_chunk = [&](int c) {
        const int stg = c % 3;
        int kk = c * 64;
        const __nv_bfloat16* Ab = A1;
        if (kk >= Khalf) { Ab = A2; kk -= Khalf; }
        uint32_t sA = sbase + stg * STG;
        // A tile: 128 rows x 64 bf16 = 1024 x 16B
#pragma unroll
        for (int i = 0; i < 4; i++) {
            int idx = t + i * 256, r = idx >> 3, c8 = idx & 7;
            CP_ASYNC16(sA + (uint32_t)(r * (AW * 2) + c8 * 16),
                       Ab + (size_t)(m0 + r) * Khalf + kk + c8 * 8);
        }
        uint32_t sB = sA + ABYTES;
#pragma unroll
        for (int i = 0; i < BN / 32; i++) {
            int idx = t + i * 256, r = idx >> 3, c8 = idx & 7;
            CP_ASYNC16(sB + (uint32_t)(r * (AW * 2) + c8 * 16),
                       Wt + (size_t)(n0 + r) * Ktot + c * 64 + c8 * 8);
        }
        CP_COMMIT();
    };

    const int NC = Ktot >> 6;
    load_chunk(0);
    if (NC > 1) load_chunk(1);

    for (int c = 0; c < NC; c++) {
        if (c + 1 < NC) { asm volatile("cp.async.wait_group 1;" ::: "memory"); }
        else            { asm volatile("cp.async.wait_group 0;" ::: "memory"); }
        __syncthreads();     // chunk c visible; stage (c+2)%3==(c-1)%3 drained
        if (c + 2 < NC) load_chunk(c + 2);

        const uint32_t aa = a_addr0 + (c % 3) * STG;
        const uint32_t bb = b_addr0 + (c % 3) * STG;
#pragma unroll
        for (int kk = 0; kk < 4; kk++) {     // four k16 steps per 64-chunk
            uint32_t Af[2][4];
            LDSM4(Af[0], aa + kk * 32);
            LDSM4(Af[1], aa + 16 * (AW * 2) + kk * 32);
#pragma unroll
            for (int np = 0; np < NT / 2; np++) {
                uint32_t B4[4];
                LDSM4(B4, bb + np * 16 * (AW * 2) + kk * 32);
#pragma unroll
                for (int mt = 0; mt < 2; mt++) {
                    mma_bf(acc[mt][2 * np],     Af[mt], B4[0], B4[1]);
                    mma_bf(acc[mt][2 * np + 1], Af[mt], B4[2], B4[3]);
                }
            }
        }
    }

#pragma unroll
    for (int mt = 0; mt < 2; mt++) {
        int row = batch * NB + m0 + wm + mt * 16 + (lane >> 2);
#pragma unroll
        for (int nt = 0; nt < NT; nt++) {
            int col = n0 + wn + nt * 8 + (lane & 3) * 2;
            float b0v = bias[col], b1v = bias[col + 1];
            float x0 = acc[mt][nt][0] + b0v, x1 = acc[mt][nt][1] + b1v;
            float x2 = acc[mt][nt][2] + b0v, x3 = acc[mt][nt][3] + b1v;
            if (act) { x0 = geluf(x0); x1 = geluf(x1); x2 = geluf(x2); x3 = geluf(x3); }
            if (OUTBF) {
                __nv_bfloat16* C = (__nv_bfloat16*)Cv;
                *reinterpret_cast<__nv_bfloat162*>(C + (size_t)row * N + col) =
                    __floats2bfloat162_rn(x0, x1);
                *reinterpret_cast<__nv_bfloat162*>(C + (size_t)(row + 8) * N + col) =
                    __floats2bfloat162_rn(x2, x3);
            } else {
                float* C = (float*)Cv;
                *reinterpret_cast<float2*>(C + (size_t)row * N + col)       = make_float2(x0, x1);
                *reinterpret_cast<float2*>(C + (size_t)(row + 8) * N + col) = make_float2(x2, x3);
            }
        }
    }
}

// ================= bf16x3 precise GEMM (info path, unchanged from R9) =================
template<int BN>
__global__ void __launch_bounds__(256, 2) gemm_bf3(
    APtrsB Ah, APtrsB Al, int Ktot,
    const __nv_bfloat16* __restrict__ Wh, const __nv_bfloat16* __restrict__ Wl, int N,
    const float* __restrict__ bias, float* __restrict__ C, int act)
{
    constexpr int AW = 40;
    constexpr int ABYTES = 128 * AW * 2;
    constexpr int BBYTES = BN * AW * 2;
    constexpr int STG = 2 * ABYTES + 2 * BBYTES;
    constexpr int NT = BN / 16;

    extern __shared__ char smem[];
    const int t = threadIdx.x, lane = t & 31, wid = t >> 5;
    const int batch = blockIdx.y >> 7;
    const int m0 = (blockIdx.y & 127) * 128;
    const int n0 = blockIdx.x * BN;
    const int wm = (wid & 3) * 32;
    const int wn = (wid >> 2) * (BN / 2);

    const __nv_bfloat16* A1h = Ah.p[batch];
    const __nv_bfloat16* A1l = Al.p[batch];
    C += (size_t)batch * NB * N;

    const uint32_t sbase = smem_u32(smem);
    const uint32_t a_addr0 = sbase + (uint32_t)((wm + (lane & 15)) * AW * 2 + (lane >> 4) * 16);
    const int grp = lane >> 3;
    const int b_r = (lane & 7) + ((grp >= 2) ? 8 : 0);
    const uint32_t b_addr0 = sbase + 2 * ABYTES + (uint32_t)((wn + b_r) * AW * 2 + (grp & 1) * 16);

    float acc[2][NT][4];
#pragma unroll
    for (int i = 0; i < 2; i++)
#pragma unroll
        for (int j = 0; j < NT; j++)
#pragma unroll
            for (int q = 0; q < 4; q++) acc[i][j][q] = 0.0f;

    auto load_chunk = [&](int c) {
        const int stg = c & 1;
        const int kk = c * 32;
        uint32_t base = sbase + stg * STG;
#pragma unroll
        for (int i = 0; i < 2; i++) {
            int idx = t + i * 256, r = idx >> 2, c8 = idx & 3;
            uint32_t off = (uint32_t)(r * AW * 2 + c8 * 16);
            size_t go = (size_t)(m0 + r) * Ktot + kk + c8 * 8;
            CP_ASYNC16(base + off,           A1h + go);
            CP_ASYNC16(base + ABYTES + off,  A1l + go);
        }
        uint32_t sB = base + 2 * ABYTES;
#pragma unroll
        for (int i = 0; i < BN / 64; i++) {
            int idx = t + i * 256, r = idx >> 2, c8 = idx & 3;
            uint32_t off = (uint32_t)(r * AW * 2 + c8 * 16);
            size_t go = (size_t)(n0 + r) * Ktot + kk + c8 * 8;
            CP_ASYNC16(sB + off,           Wh + go);
            CP_ASYNC16(sB + BBYTES + off,  Wl + go);
        }
        CP_COMMIT();
    };

    const int NC = Ktot >> 5;
    load_chunk(0);
    if (NC > 1) load_chunk(1);

    for (int c = 0; c < NC; c++) {
        if (c + 1 < NC) { asm volatile("cp.async.wait_group 1;" ::: "memory"); }
        else            { asm volatile("cp.async.wait_group 0;" ::: "memory"); }
        __syncthreads();

        const uint32_t aa = a_addr0 + (c & 1) * STG;
        const uint32_t bb = b_addr0 + (c & 1) * STG;
#pragma unroll
        for (int kk = 0; kk < 2; kk++) {
            uint32_t Ahf[2][4], Alf[2][4];
            LDSM4(Ahf[0], aa + kk * 32);
            LDSM4(Ahf[1], aa + 16 * AW * 2 + kk * 32);
            LDSM4(Alf[0], aa + ABYTES + kk * 32);
            LDSM4(Alf[1], aa + ABYTES + 16 * AW * 2 + kk * 32);
#pragma unroll
            for (int np = 0; np < NT / 2; np++) {
                uint32_t Bh4[4], Bl4[4];
                LDSM4(Bh4, bb + np * 16 * AW * 2 + kk * 32);
                LDSM4(Bl4, bb + BBYTES + np * 16 * AW * 2 + kk * 32);
#pragma unroll
                for (int mt = 0; mt < 2; mt++) {
                    mma_bf(acc[mt][2 * np],     Ahf[mt], Bh4[0], Bh4[1]);
                    mma_bf(acc[mt][2 * np],     Ahf[mt], Bl4[0], Bl4[1]);
                    mma_bf(acc[mt][2 * np],     Alf[mt], Bh4[0], Bh4[1]);
                    mma_bf(acc[mt][2 * np + 1], Ahf[mt], Bh4[2], Bh4[3]);
                    mma_bf(acc[mt][2 * np + 1], Ahf[mt], Bl4[2], Bl4[3]);
                    mma_bf(acc[mt][2 * np + 1], Alf[mt], Bh4[2], Bh4[3]);
                }
            }
        }
        __syncthreads();
        if (c + 2 < NC) load_chunk(c + 2);
    }

#pragma unroll
    for (int mt = 0; mt < 2; mt++) {
        int row = m0 + wm + mt * 16 + (lane >> 2);
#pragma unroll
        for (int nt = 0; nt < NT; nt++) {
            int col = n0 + wn + nt * 8 + (lane & 3) * 2;
            float b0v = bias[col], b1v = bias[col + 1];
            float x0 = acc[mt][nt][0] + b0v, x1 = acc[mt][nt][1] + b1v;
            float x2 = acc[mt][nt][2] + b0v, x3 = acc[mt][nt][3] + b1v;
            if (act) { x0 = geluf(x0); x1 = geluf(x1); x2 = geluf(x2); x3 = geluf(x3); }
            *reinterpret_cast<float2*>(C + (size_t)row * N + col)       = make_float2(x0, x1);
            *reinterpret_cast<float2*>(C + (size_t)(row + 8) * N + col) = make_float2(x2, x3);
        }
    }
}

// ---------------- feature fp32 -> bf16 (hi) ----------------
__global__ void cvt_bf_k(const float4* __restrict__ s0, const float4* __restrict__ s1,
                         const float4* __restrict__ s2, const float4* __restrict__ s3,
                         __nv_bfloat16* __restrict__ d)
{
    int i = blockIdx.x * blockDim.x + threadIdx.x;
    const int per = NB * 768 / 4;
    if (i >= 4 * per) return;
    int f = i / per, j = i - f * per;
    const float4* s = (f == 0 ? s0 : f == 1 ? s1 : f == 2 ? s2 : s3);
    float4 v = s[j];
    __nv_bfloat162* o = reinterpret_cast<__nv_bfloat162*>(d + (size_t)f * NB * 768 + (size_t)j * 4);
    o[0] = __floats2bfloat162_rn(v.x, v.y);
    o[1] = __floats2bfloat162_rn(v.z, v.w);
}

__global__ void lo_feat_k(const float4* __restrict__ x0, const float4* __restrict__ x1,
                          const __nv_bfloat16* __restrict__ hi, __nv_bfloat16* __restrict__ lo)
{
    int i = blockIdx.x * blockDim.x + threadIdx.x;
    const int per = NB * 768 / 4;
    if (i >= 2 * per) return;
    const float4* x = (i < per) ? x0 : x1;
    int j = (i < per) ? i : i - per;
    float4 v = x[j];
    const __nv_bfloat162* hp = reinterpret_cast<const __nv_bfloat162*>(hi + (size_t)i * 4);
    __nv_bfloat162 h0 = hp[0], h1 = hp[1];
    __nv_bfloat162* o = reinterpret_cast<__nv_bfloat162*>(lo + (size_t)i * 4);
    o[0] = __floats2bfloat162_rn(v.x - __bfloat162float(h0.x), v.y - __bfloat162float(h0.y));
    o[1] = __floats2bfloat162_rn(v.z - __bfloat162float(h1.x), v.w - __bfloat162float(h1.y));
}

__global__ void split_fp32_k(const float4* __restrict__ x, __nv_bfloat16* __restrict__ h,
                             __nv_bfloat16* __restrict__ l, int n4)
{
    int i = blockIdx.x * blockDim.x + threadIdx.x;
    if (i >= n4) return;
    float4 v = x[i];
    __nv_bfloat162 h0 = __floats2bfloat162_rn(v.x, v.y);
    __nv_bfloat162 h1 = __floats2bfloat162_rn(v.z, v.w);
    reinterpret_cast<__nv_bfloat162*>(h + (size_t)i * 4)[0] = h0;
    reinterpret_cast<__nv_bfloat162*>(h + (size_t)i * 4)[1] = h1;
    __nv_bfloat162 l0 = __floats2bfloat162_rn(v.x - __bfloat162float(h0.x), v.y - __bfloat162float(h0.y));
    __nv_bfloat162 l1 = __floats2bfloat162_rn(v.z - __bfloat162float(h1.x), v.w - __bfloat162float(h1.y));
    reinterpret_cast<__nv_bfloat162*>(l + (size_t)i * 4)[0] = l0;
    reinterpret_cast<__nv_bfloat162*>(l + (size_t)i * 4)[1] = l1;
}

// ---------------- combined transpose: 7 bf16 jobs, one launch ----------------
struct TJobs {
    const float* s[7];
    __nv_bfloat16* d[7];
    int K[7], N[7], t0[7];
    int njobs;
};
__global__ void transpose_combo_k(TJobs J) {
    __shared__ float tile[32][33];
    int bx = blockIdx.x;
    int j = 0;
#pragma unroll
    for (int q = 1; q < 7; q++) if (q < J.njobs && bx >= J.t0[q]) j = q;
    int local = bx - J.t0[j];
    int tilesx = J.N[j] / 32;
    int txb = local % tilesx, tyb = local / tilesx;
    const float* s = J.s[j];
    int K = J.K[j], N = J.N[j];
    int n = txb * 32 + threadIdx.x;
    int k = tyb * 32 + threadIdx.y;
#pragma unroll
    for (int i = 0; i < 32; i += 8) tile[threadIdx.y + i][threadIdx.x] = s[(size_t)(k + i) * N + n];
    __syncthreads();
    int n2 = txb * 32 + threadIdx.y;
    int k2 = tyb * 32 + threadIdx.x;
    __nv_bfloat16* d = J.d[j];
#pragma unroll
    for (int i = 0; i < 32; i += 8)
        d[(size_t)(n2 + i) * K + k2] = __float2bfloat16(tile[threadIdx.x][threadIdx.y + i]);
}

__global__ void transpose_split_k(const float* __restrict__ s, __nv_bfloat16* __restrict__ dh,
                                  __nv_bfloat16* __restrict__ dl, int K, int N) {
    __shared__ float tile[32][33];
    int n = blockIdx.x * 32 + threadIdx.x;
    int k = blockIdx.y * 32 + threadIdx.y;
#pragma unroll
    for (int i = 0; i < 32; i += 8) tile[threadIdx.y + i][threadIdx.x] = s[(size_t)(k + i) * N + n];
    __syncthreads();
    int n2 = blockIdx.x * 32 + threadIdx.y;
    int k2 = blockIdx.y * 32 + threadIdx.x;
#pragma unroll
    for (int i = 0; i < 32; i += 8) {
        float v = tile[threadIdx.x][threadIdx.y + i];
        __nv_bfloat16 h = __float2bfloat16(v);
        dh[(size_t)(n2 + i) * K + k2] = h;
        dl[(size_t)(n2 + i) * K + k2] = __float2bfloat16(v - __bfloat162float(h));
    }
}

// ---------------- final dot head ----------------
__global__ void dot_head_k(const float* __restrict__ Hin, int K, int rows,
                           const float* __restrict__ w, const float* __restrict__ b,
                           float* __restrict__ outrow)
{
    int gw = (blockIdx.x * blockDim.x + threadIdx.x) >> 5;
    int lane = threadIdx.x & 31;
    if (gw >= rows) return;
    const float* row = Hin + (size_t)gw * K;
    float s = 0.f;
    for (int k = lane * 4; k < K; k += 128) {
        float4 v = *reinterpret_cast<const float4*>(row + k);
        float4 wv = *reinterpret_cast<const float4*>(w + k);
        s += v.x * wv.x + v.y * wv.y + v.z * wv.z + v.w * wv.w;
    }
#pragma unroll
    for (int o = 16; o; o >>= 1) s += __shfl_xor_sync(0xffffffffu, s, o);
    if (lane == 0) outrow[gw] = sigf(s + b[0]);
}

// ---------------- geometric quality + norms ----------------
__global__ void rowstats_k(const float* __restrict__ f0, const float* __restrict__ f1,
                           const float* __restrict__ f2, const float* __restrict__ f3,
                           float* __restrict__ out)
{
    int gw = (blockIdx.x * blockDim.x + threadIdx.x) >> 5;
    int lane = threadIdx.x & 31;
    if (gw >= 4 * NB) return;
    int feat = gw >> 14;
    int m = gw & (NB - 1);
    const float* f = (feat == 0 ? f0 : feat == 1 ? f1 : feat == 2 ? f2 : f3) + (size_t)m * HD;
    double sum = 0.0, ssq = 0.0;
    int cnt = 0;
    for (int k = lane * 4; k < HD; k += 128) {
        float4 v = *reinterpret_cast<const float4*>(f + k);
        sum += (double)v.x + v.y + v.z + v.w;
        ssq += (double)v.x * v.x + (double)v.y * v.y + (double)v.z * v.z + (double)v.w * v.w;
        cnt += (fabsf(v.x) > 0.01f) + (fabsf(v.y) > 0.01f) + (fabsf(v.z) > 0.01f) + (fabsf(v.w) > 0.01f);
    }
#pragma unroll
    for (int o = 16; o; o >>= 1) {
        sum += __shfl_xor_sync(0xffffffffu, sum, o);
        ssq += __shfl_xor_sync(0xffffffffu, ssq, o);
        cnt += __shfl_xor_sync(0xffffffffu, cnt, o);
    }
    if (lane == 0) {
        float n = (float)sqrt(ssq);
        float nq = sigf((n - 1.0f) * 2.0f);
        float sp = cnt * (1.0f / 768.0f);
        double var = (ssq - sum * sum / 768.0) / 767.0;
        if (var < 0.0) var = 0.0;
        float sq = sigf((float)sqrt(var) * 10.0f - 1.0f);
        out[feat * NB + m] = (nq + sp + sq) * (1.0f / 3.0f);
        if (feat < 2) g_norm[feat * NB + m] = n;
    }
}

// ---------------- info final (2*NB rows) ----------------
__global__ void info_final_k(const float* __restrict__ enc, float* __restrict__ outrow)
{
    int gw = (blockIdx.x * blockDim.x + threadIdx.x) >> 5;
    int lane = threadIdx.x & 31;
    if (gw >= 2 * NB) return;
    const float* e = enc + (size_t)gw * 64;
    float x0 = e[lane], x1 = e[lane + 32];
    int d0 = (int)rintf(sigf(x0) * 10.0f);
    int d1 = (int)rintf(sigf(x1) * 10.0f);
    float ent = 0.f;
#pragma unroll
    for (int b = 0; b < 11; b++) {
        int c = __popc(__ballot_sync(0xffffffffu, d0 == b)) +
                __popc(__ballot_sync(0xffffffffu, d1 == b));
        if (c > 0) {
            float p = c * (1.0f / 64.0f);
            ent -= p * logf(p + 1e-8f);
        }
    }
    if (lane == 0) {
        float eq = sigf(ent - 2.0f);
        float n = g_norm[gw];
        float cq = (n > 0.01f) ? (1.0f / 768.0f) : 0.0f;
        float t = n / fmaxf(n, 1e-12f);
        float dq = sigf(t * t - 0.5f);
        outrow[gw] = (eq + cq + dq) * (1.0f / 3.0f);
    }
}

__global__ void overall_k(float* __restrict__ out)
{
    int i = blockIdx.x * blockDim.x + threadIdx.x;
    if (i >= NB) return;
    float v = out[0 * NB + i] + out[1 * NB + i] + out[4 * NB + i] + out[5 * NB + i] +
              out[7 * NB + i] + 0.5f * (out[8 * NB + i] + out[9 * NB + i]);
    out[17 * NB + i] = v * (1.0f / 6.0f);
}

// ---------------- host ----------------
template<int BN, bool OUTBF>
static void launch_bf(cudaStream_t st, APtrsB A, int nb, int Khalf, int Ktot,
                      const __nv_bfloat16* Wt, int N, const float* bias, void* C, int act)
{
    int smemB = 3 * (128 + BN) * 72 * 2;
    cudaFuncSetAttribute(gemm_bf16<BN, OUTBF>, cudaFuncAttributeMaxDynamicSharedMemorySize, smemB);
    dim3 g(N / BN, nb * 128);
    gemm_bf16<BN, OUTBF><<<g, 256, smemB, st>>>(A, Khalf, Ktot, Wt, N, bias, C, act);
}
template<int BN>
static void launch_bf3(cudaStream_t st, APtrsB Ah, APtrsB Al, int nb, int Ktot,
                       const __nv_bfloat16* Wh, const __nv_bfloat16* Wl, int N,
                       const float* bias, float* C, int act)
{
    int smemB = 2 * (2 * 128 * 40 * 2 + 2 * BN * 40 * 2);
    cudaFuncSetAttribute(gemm_bf3<BN>, cudaFuncAttributeMaxDynamicSharedMemorySize, smemB);
    dim3 g(N / BN, nb * 128);
    gemm_bf3<BN><<<g, 256, smemB, st>>>(Ah, Al, Ktot, Wh, Wl, N, bias, C, act);
}

extern "C" void kernel_launch(void* const* d_in, const int* in_sizes, int n_in,
                              void* d_out, int out_size)
{
    const float* img  = (const float*)d_in[0];
    const float* txt  = (const float*)d_in[1];
    const float* eimg = (const float*)d_in[2];
    const float* etxt = (const float*)d_in[3];
    const float* info_w1 = (const float*)d_in[5];
    const float* info_b1 = (const float*)d_in[6];
    const float* info_w2 = (const float*)d_in[7];
    const float* info_b2 = (const float*)d_in[8];
    const float* imp_w1  = (const float*)d_in[9];
    const float* imp_b1  = (const float*)d_in[10];
    const float* imp_w2  = (const float*)d_in[11];
    const float* imp_b2  = (const float*)d_in[12];
    const float* disc_w1 = (const float*)d_in[13];
    const float* disc_b1 = (const float*)d_in[14];
    const float* disc_w2 = (const float*)d_in[15];
    const float* disc_b2 = (const float*)d_in[16];
    const float* disc_w3 = (const float*)d_in[17];
    const float* disc_b3 = (const float*)d_in[18];
    const float* cons_w1 = (const float*)d_in[19];
    const float* cons_b1 = (const float*)d_in[20];
    const float* cons_w2 = (const float*)d_in[21];
    const float* cons_b2 = (const float*)d_in[22];
    const float* cons_w3 = (const float*)d_in[23];
    const float* cons_b3 = (const float*)d_in[24];
    const float* diff_w1 = (const float*)d_in[25];
    const float* diff_b1 = (const float*)d_in[26];
    const float* diff_w2 = (const float*)d_in[27];
    const float* diff_b2 = (const float*)d_in[28];
    const float* diff_w3 = (const float*)d_in[29];
    const float* diff_b3 = (const float*)d_in[30];

    float* out = (float*)d_out;

    __nv_bfloat16 *featbf, *lo1, *h2, *l2, *scrAbf, *scrAbf3, *scrCbf;
    __nv_bfloat16 *w_imp1, *w_disc1, *w_disc2, *w_cons1, *w_cons2, *w_diff1, *w_diff2;
    __nv_bfloat16 *wi1h, *wi1l, *wi2h, *wi2l;
    float *scrB, *scrB2, *scrB3, *scrC, *scrD, *scrD2;
    cudaGetSymbolAddress((void**)&featbf, g_featbf);
    cudaGetSymbolAddress((void**)&lo1, g_lo1);
    cudaGetSymbolAddress((void**)&h2, g_h2);
    cudaGetSymbolAddress((void**)&l2, g_l2);
    cudaGetSymbolAddress((void**)&scrAbf, g_scrAbf);
    cudaGetSymbolAddress((void**)&scrAbf3, g_scrAbf3);
    cudaGetSymbolAddress((void**)&scrCbf, g_scrCbf);
    cudaGetSymbolAddress((void**)&scrB, g_scrB);
    cudaGetSymbolAddress((void**)&scrB2, g_scrB2);
    cudaGetSymbolAddress((void**)&scrB3, g_scrB3);
    cudaGetSymbolAddress((void**)&scrC, g_scrC);
    cudaGetSymbolAddress((void**)&scrD, g_scrD);
    cudaGetSymbolAddress((void**)&scrD2, g_scrD2);
    cudaGetSymbolAddress((void**)&w_imp1, g_w_imp1);
    cudaGetSymbolAddress((void**)&w_disc1, g_w_disc1);
    cudaGetSymbolAddress((void**)&w_disc2, g_w_disc2);
    cudaGetSymbolAddress((void**)&w_cons1, g_w_cons1);
    cudaGetSymbolAddress((void**)&w_cons2, g_w_cons2);
    cudaGetSymbolAddress((void**)&w_diff1, g_w_diff1);
    cudaGetSymbolAddress((void**)&w_diff2, g_w_diff2);
    cudaGetSymbolAddress((void**)&wi1h, g_wi1h);
    cudaGetSymbolAddress((void**)&wi1l, g_wi1l);
    cudaGetSymbolAddress((void**)&wi2h, g_wi2h);
    cudaGetSymbolAddress((void**)&wi2l, g_wi2l);

    const __nv_bfloat16* bimg  = featbf;
    const __nv_bfloat16* btxt  = featbf + (size_t)NB * 768;
    const __nv_bfloat16* beimg = featbf + (size_t)2 * NB * 768;
    const __nv_bfloat16* betxt = featbf + (size_t)3 * NB * 768;

    static cudaStream_t s1 = nullptr, s2 = nullptr;
    static cudaEvent_t e0 = nullptr, eT = nullptr, e1 = nullptr, e2 = nullptr;
    if (!s1) {
        cudaStreamCreateWithFlags(&s1, cudaStreamNonBlocking);
        cudaStreamCreateWithFlags(&s2, cudaStreamNonBlocking);
        cudaEventCreateWithFlags(&e0, cudaEventDisableTiming);
        cudaEventCreateWithFlags(&eT, cudaEventDisableTiming);
        cudaEventCreateWithFlags(&e1, cudaEventDisableTiming);
        cudaEventCreateWithFlags(&e2, cudaEventDisableTiming);
    }

    // fork
    cudaEventRecord(e0, 0);
    cudaStreamWaitEvent(s1, e0, 0);
    cudaStreamWaitEvent(s2, e0, 0);

    // s1: rowstats (inputs only)
    rowstats_k<<<(4 * NB) / 8, 256, 0, s1>>>(img, txt, eimg, etxt, out);

    // main: feature conversion + weight transposes
    cvt_bf_k<<<(4 * NB * 768 / 4 + 255) / 256, 256>>>(
        (const float4*)img, (const float4*)txt, (const float4*)eimg, (const float4*)etxt, featbf);
    {
        TJobs J;
        const float* srcs[7] = { imp_w1, disc_w1, disc_w2, cons_w1, cons_w2, diff_w1, diff_w2 };
        __nv_bfloat16* dsts[7] = { w_imp1, w_disc1, w_disc2, w_cons1, w_cons2, w_diff1, w_diff2 };
        int Ks[7] = { 768, 768, 256, 1536, 768, 1536, 768 };
        int Ns[7] = { 384, 256, 64, 768, 384, 768, 384 };
        int tot = 0;
        for (int j = 0; j < 7; j++) {
            J.s[j] = srcs[j]; J.d[j] = dsts[j]; J.K[j] = Ks[j]; J.N[j] = Ns[j];
            J.t0[j] = tot;
            tot += (Ks[j] / 32) * (Ns[j] / 32);
        }
        J.njobs = 7;
        dim3 b(32, 8);
        transpose_combo_k<<<tot, b>>>(J);
    }
    {
        dim3 b(32, 8);
        transpose_split_k<<<dim3(256 / 32, 768 / 32), b>>>(info_w1, wi1h, wi1l, 768, 256);
        transpose_split_k<<<dim3(64 / 32, 256 / 32), b>>>(info_w2, wi2h, wi2l, 256, 64);
    }
    cudaEventRecord(eT, 0);
    cudaStreamWaitEvent(s1, eT, 0);
    cudaStreamWaitEvent(s2, eT, 0);

    // s1: information (rows 4,5) — bf16x3 precise
    {
        lo_feat_k<<<(2 * NB * 768 / 4 + 255) / 256, 256, 0, s1>>>(
            (const float4*)img, (const float4*)txt, featbf, lo1);
        APtrsB ah = {{ bimg, btxt, nullptr, nullptr }};
        APtrsB al = {{ lo1, lo1 + (size_t)NB * 768, nullptr, nullptr }};
        launch_bf3<128>(s1, ah, al, 2, 768, wi1h, wi1l, 256, info_b1, scrC, 1);
        split_fp32_k<<<(2 * NB * 256 / 4 + 255) / 256, 256, 0, s1>>>(
            (const float4*)scrC, h2, l2, 2 * NB * 256 / 4);
        APtrsB ah2 = {{ h2, h2 + (size_t)NB * 256, nullptr, nullptr }};
        APtrsB al2 = {{ l2, l2 + (size_t)NB * 256, nullptr, nullptr }};
        launch_bf3<64>(s1, ah2, al2, 2, 256, wi2h, wi2l, 64, info_b2, scrD2, 0);
        info_final_k<<<(2 * NB) / 8, 256, 0, s1>>>(scrD2, out + 4 * NB);
        cudaEventRecord(e1, s1);
    }

    // main: importance (rows 8..11) + discriminator (rows 12..15) + difficulty (row 16)
    {
        APtrsB a = {{ bimg, btxt, beimg, betxt }};
        launch_bf<128, false>(0, a, 4, 768, 768, w_imp1, 384, imp_b1, scrB, 1);
        dot_head_k<<<(4 * NB) / 8, 256>>>(scrB, 384, 4 * NB, imp_w2, imp_b2, out + 8 * NB);

        APtrsB ad = {{ bimg, beimg, btxt, betxt }};
        launch_bf<128, true>(0, ad, 4, 768, 768, w_disc1, 256, disc_b1, scrCbf, 1);
        APtrsB ad2 = {{ scrCbf, scrCbf + (size_t)NB * 256, scrCbf + (size_t)2 * NB * 256,
                        scrCbf + (size_t)3 * NB * 256 }};
        launch_bf<64, false>(0, ad2, 4, 256, 256, w_disc2, 64, disc_b2, scrD, 1);
        dot_head_k<<<(4 * NB) / 8, 256>>>(scrD, 64, 4 * NB, disc_w3, disc_b3, out + 12 * NB);

        APtrsB af = {{ beimg, betxt, nullptr, nullptr }};
        launch_bf<128, true>(0, af, 1, 768, 1536, w_diff1, 768, diff_b1, scrAbf3, 1);
        APtrsB af2 = {{ scrAbf3, nullptr, nullptr, nullptr }};
        launch_bf<128, false>(0, af2, 1, 768, 768, w_diff2, 384, diff_b2, scrB3, 1);
        dot_head_k<<<NB / 8, 256>>>(scrB3, 384, NB, diff_w3, diff_b3, out + 16 * NB);
    }

    // s2: consistency (rows 6,7)
    {
        APtrsB a = {{ bimg, btxt, beimg, betxt }};
        launch_bf<128, true>(s2, a, 2, 768, 1536, w_cons1, 768, cons_b1, scrAbf, 1);
        APtrsB a2 = {{ scrAbf, scrAbf + (size_t)NB * 768, nullptr, nullptr }};
        launch_bf<128, false>(s2, a2, 2, 768, 768, w_cons2, 384, cons_b2, scrB2, 1);
        dot_head_k<<<(2 * NB) / 8, 256, 0, s2>>>(scrB2, 384, 2 * NB, cons_w3, cons_b3, out + 6 * NB);
        cudaEventRecord(e2, s2);
    }

    // join + overall
    cudaStreamWaitEvent(0, e1, 0);
    cudaStreamWaitEvent(0, e2, 0);
    overall_k<<<NB / 256, 256>>>(out);
}

// round 11
// speedup vs baseline: 1.3980x; 1.0359x over previous
#include <cuda_runtime.h>
#include <cuda_bf16.h>
#include <cstdint>

#define NB 16384
#define HD 768

// ---------------- scratch ----------------
__device__ __nv_bfloat16 g_featbf[4 * NB * 768];
__device__ __nv_bfloat16 g_lo1[2 * NB * 768];
__device__ __nv_bfloat16 g_h2[2 * NB * 256];
__device__ __nv_bfloat16 g_l2[2 * NB * 256];
__device__ __nv_bfloat16 g_scrAbf[2 * NB * 768];     // cons1 (bf16) [s2]
__device__ __nv_bfloat16 g_scrAbf3[NB * 768];        // diff1 (bf16) [main]
__device__ __nv_bfloat16 g_scrCbf[4 * NB * 256];     // disc1 (bf16) [main]
__device__ float g_scrB [4 * NB * 384];              // imp1 (fp32)  [main]
__device__ float g_scrB2[2 * NB * 384];              // cons2 (fp32) [s2]
__device__ float g_scrB3[1 * NB * 384];              // diff2 (fp32) [main]
__device__ float g_scrC [2 * NB * 256];              // info1 (fp32) [s1]
__device__ float g_scrD [4 * NB * 64];               // disc2 (fp32) [main]
__device__ float g_scrD2[2 * NB * 64];               // info2 (fp32) [s1]
__device__ float g_norm[2 * NB];
__device__ __nv_bfloat16 g_w_imp1[384 * 768];
__device__ __nv_bfloat16 g_w_disc1[256 * 768];
__device__ __nv_bfloat16 g_w_disc2[64 * 256];
__device__ __nv_bfloat16 g_w_cons1[768 * 1536];
__device__ __nv_bfloat16 g_w_cons2[384 * 768];
__device__ __nv_bfloat16 g_w_diff1[768 * 1536];
__device__ __nv_bfloat16 g_w_diff2[384 * 768];
__device__ __nv_bfloat16 g_wi1h[256 * 768], g_wi1l[256 * 768];
__device__ __nv_bfloat16 g_wi2h[64 * 256],  g_wi2l[64 * 256];

__device__ __forceinline__ float sigf(float x) { return 1.0f / (1.0f + expf(-x)); }
__device__ __forceinline__ float geluf(float x) { return 0.5f * x * (1.0f + erff(x * 0.70710678118654752f)); }

__device__ __forceinline__ uint32_t smem_u32(const void* p) {
    uint32_t a;
    asm("{ .reg .u64 t; cvta.to.shared.u64 t, %1; cvt.u32.u64 %0, t; }" : "=r"(a) : "l"(p));
    return a;
}
__device__ __forceinline__ void mma_bf(float* d, const uint32_t* a, uint32_t b0, uint32_t b1) {
    asm volatile(
        "mma.sync.aligned.m16n8k16.row.col.f32.bf16.bf16.f32 "
        "{%0,%1,%2,%3}, {%4,%5,%6,%7}, {%8,%9}, {%0,%1,%2,%3};"
        : "+f"(d[0]), "+f"(d[1]), "+f"(d[2]), "+f"(d[3])
        : "r"(a[0]), "r"(a[1]), "r"(a[2]), "r"(a[3]), "r"(b0), "r"(b1));
}
#define LDSM4(r, addr) \
    asm volatile("ldmatrix.sync.aligned.m8n8.x4.shared.b16 {%0,%1,%2,%3}, [%4];" \
        : "=r"((r)[0]), "=r"((r)[1]), "=r"((r)[2]), "=r"((r)[3]) : "r"(addr))
#define CP_ASYNC16(dst, src) \
    asm volatile("cp.async.cg.shared.global [%0], [%1], 16;" :: "r"(dst), "l"(src))
#define CP_COMMIT() asm volatile("cp.async.commit_group;" ::: "memory")

struct APtrsB { const __nv_bfloat16* p[4]; };

// ================= bf16 GEMM: BM=128, BK=64, 3-stage, occ 2, two-region B =================
// Region 0: CTAs with n0 < N0: weights Wt0 [N0,K], bias b0, output C0 (fp32 or bf16 per OUTBF0)
// Region 1: n0 >= N0: Wt1 [N1,K], b1, C1 (type per OUTBF1). Single-region use: N1=0.
template<int BN, bool OUTBF0, bool OUTBF1>
__global__ void __launch_bounds__(256, 2) gemm_bf16(
    APtrsB A, int Khalf, int Ktot,
    const __nv_bfloat16* __restrict__ Wt0, const __nv_bfloat16* __restrict__ Wt1,
    int N0, int N1, const float* __restrict__ b0, const float* __restrict__ b1,
    void* __restrict__ C0v, void* __restrict__ C1v, int act)
{
    constexpr int AW = 72;
    constexpr int ABYTES = 128 * AW * 2;
    constexpr int BBYTES = BN * AW * 2;
    constexpr int STG = ABYTES + BBYTES;
    constexpr int NT = BN / 16;

    extern __shared__ char smem[];
    const int t = threadIdx.x, lane = t & 31, wid = t >> 5;
    const int batch = blockIdx.y >> 7;
    const int m0 = (blockIdx.y & 127) * 128;
    const int n0g = blockIdx.x * BN;
    const int wm = (wid & 3) * 32;
    const int wn = (wid >> 2) * (BN / 2);

    const bool r1 = (n0g >= N0);
    const __nv_bfloat16* Wt = r1 ? Wt1 : Wt0;
    const float* bias = r1 ? b1 : b0;
    const int N = r1 ? N1 : N0;
    const int n0 = n0g - (r1 ? N0 : 0);

    const __nv_bfloat16 *A1, *A2;
    if (Khalf < Ktot) { A1 = A.p[2 * batch]; A2 = A.p[2 * batch + 1]; }
    else              { A1 = A.p[batch];     A2 = A1; }

    const uint32_t sbase = smem_u32(smem);
    const uint32_t a_addr0 = sbase + (uint32_t)((wm + (lane & 15)) * (AW * 2) + (lane >> 4) * 16);
    const int grp = lane >> 3;
    const int b_r = (lane & 7) + ((grp >= 2) ? 8 : 0);
    const uint32_t b_addr0 = sbase + ABYTES + (uint32_t)((wn + b_r) * (AW * 2) + (grp & 1) * 16);

    float acc[2][NT][4];
#pragma unroll
    for (int i = 0; i < 2; i++)
#pragma unroll
        for (int j = 0; j < NT; j++)
#pragma unroll
            for (int q = 0; q < 4; q++) acc[i][j][q] = 0.0f;

    auto load_chunk = [&](int c) {
        const int stg = c % 3;
        int kk = c * 64;
        const __nv_bfloat16* Ab = A1;
        if (kk >= Khalf) { Ab = A2; kk -= Khalf; }
        uint32_t sA = sbase + stg * STG;
#pragma unroll
        for (int i = 0; i < 4; i++) {
            int idx = t + i * 256, r = idx >> 3, c8 = idx & 7;
            CP_ASYNC16(sA + (uint32_t)(r * (AW * 2) + c8 * 16),
                       Ab + (size_t)(m0 + r) * Khalf + kk + c8 * 8);
        }
        uint32_t sB = sA + ABYTES;
#pragma unroll
        for (int i = 0; i < BN / 32; i++) {
            int idx = t + i * 256, r = idx >> 3, c8 = idx & 7;
            CP_ASYNC16(sB + (uint32_t)(r * (AW * 2) + c8 * 16),
                       Wt + (size_t)(n0 + r) * Ktot + c * 64 + c8 * 8);
        }
        CP_COMMIT();
    };

    const int NC = Ktot >> 6;
    load_chunk(0);
    if (NC > 1) load_chunk(1);

    for (int c = 0; c < NC; c++) {
        if (c + 1 < NC) { asm volatile("cp.async.wait_group 1;" ::: "memory"); }
        else            { asm volatile("cp.async.wait_group 0;" ::: "memory"); }
        __syncthreads();
        if (c + 2 < NC) load_chunk(c + 2);

        const uint32_t aa = a_addr0 + (c % 3) * STG;
        const uint32_t bb = b_addr0 + (c % 3) * STG;
#pragma unroll
        for (int kk = 0; kk < 4; kk++) {
            uint32_t Af[2][4];
            LDSM4(Af[0], aa + kk * 32);
            LDSM4(Af[1], aa + 16 * (AW * 2) + kk * 32);
#pragma unroll
            for (int np = 0; np < NT / 2; np++) {
                uint32_t B4[4];
                LDSM4(B4, bb + np * 16 * (AW * 2) + kk * 32);
#pragma unroll
                for (int mt = 0; mt < 2; mt++) {
                    mma_bf(acc[mt][2 * np],     Af[mt], B4[0], B4[1]);
                    mma_bf(acc[mt][2 * np + 1], Af[mt], B4[2], B4[3]);
                }
            }
        }
    }

    const bool obf = r1 ? OUTBF1 : OUTBF0;
#pragma unroll
    for (int mt = 0; mt < 2; mt++) {
        int row = batch * NB + m0 + wm + mt * 16 + (lane >> 2);
#pragma unroll
        for (int nt = 0; nt < NT; nt++) {
            int col = n0 + wn + nt * 8 + (lane & 3) * 2;
            float bv0 = __ldg(bias + col), bv1 = __ldg(bias + col + 1);
            float x0 = acc[mt][nt][0] + bv0, x1 = acc[mt][nt][1] + bv1;
            float x2 = acc[mt][nt][2] + bv0, x3 = acc[mt][nt][3] + bv1;
            if (act) { x0 = geluf(x0); x1 = geluf(x1); x2 = geluf(x2); x3 = geluf(x3); }
            void* Cv = r1 ? C1v : C0v;
            if (obf) {
                __nv_bfloat16* C = (__nv_bfloat16*)Cv;
                *reinterpret_cast<__nv_bfloat162*>(C + (size_t)row * N + col) =
                    __floats2bfloat162_rn(x0, x1);
                *reinterpret_cast<__nv_bfloat162*>(C + (size_t)(row + 8) * N + col) =
                    __floats2bfloat162_rn(x2, x3);
            } else {
                float* C = (float*)Cv;
                *reinterpret_cast<float2*>(C + (size_t)row * N + col)       = make_float2(x0, x1);
                *reinterpret_cast<float2*>(C + (size_t)(row + 8) * N + col) = make_float2(x2, x3);
            }
        }
    }
}

// ================= bf16x3 precise GEMM (info path) =================
template<int BN>
__global__ void __launch_bounds__(256, 2) gemm_bf3(
    APtrsB Ah, APtrsB Al, int Ktot,
    const __nv_bfloat16* __restrict__ Wh, const __nv_bfloat16* __restrict__ Wl, int N,
    const float* __restrict__ bias, float* __restrict__ C, int act)
{
    constexpr int AW = 40;
    constexpr int ABYTES = 128 * AW * 2;
    constexpr int BBYTES = BN * AW * 2;
    constexpr int STG = 2 * ABYTES + 2 * BBYTES;
    constexpr int NT = BN / 16;

    extern __shared__ char smem[];
    const int t = threadIdx.x, lane = t & 31, wid = t >> 5;
    const int batch = blockIdx.y >> 7;
    const int m0 = (blockIdx.y & 127) * 128;
    const int n0 = blockIdx.x * BN;
    const int wm = (wid & 3) * 32;
    const int wn = (wid >> 2) * (BN / 2);

    const __nv_bfloat16* A1h = Ah.p[batch];
    const __nv_bfloat16* A1l = Al.p[batch];
    C += (size_t)batch * NB * N;

    const uint32_t sbase = smem_u32(smem);
    const uint32_t a_addr0 = sbase + (uint32_t)((wm + (lane & 15)) * AW * 2 + (lane >> 4) * 16);
    const int grp = lane >> 3;
    const int b_r = (lane & 7) + ((grp >= 2) ? 8 : 0);
    const uint32_t b_addr0 = sbase + 2 * ABYTES + (uint32_t)((wn + b_r) * AW * 2 + (grp & 1) * 16);

    float acc[2][NT][4];
#pragma unroll
    for (int i = 0; i < 2; i++)
#pragma unroll
        for (int j = 0; j < NT; j++)
#pragma unroll
            for (int q = 0; q < 4; q++) acc[i][j][q] = 0.0f;

    auto load_chunk = [&](int c) {
        const int stg = c & 1;
        const int kk = c * 32;
        uint32_t base = sbase + stg * STG;
#pragma unroll
        for (int i = 0; i < 2; i++) {
            int idx = t + i * 256, r = idx >> 2, c8 = idx & 3;
            uint32_t off = (uint32_t)(r * AW * 2 + c8 * 16);
            size_t go = (size_t)(m0 + r) * Ktot + kk + c8 * 8;
            CP_ASYNC16(base + off,           A1h + go);
            CP_ASYNC16(base + ABYTES + off,  A1l + go);
        }
        uint32_t sB = base + 2 * ABYTES;
#pragma unroll
        for (int i = 0; i < BN / 64; i++) {
            int idx = t + i * 256, r = idx >> 2, c8 = idx & 3;
            uint32_t off = (uint32_t)(r * AW * 2 + c8 * 16);
            size_t go = (size_t)(n0 + r) * Ktot + kk + c8 * 8;
            CP_ASYNC16(sB + off,           Wh + go);
            CP_ASYNC16(sB + BBYTES + off,  Wl + go);
        }
        CP_COMMIT();
    };

    const int NC = Ktot >> 5;
    load_chunk(0);
    if (NC > 1) load_chunk(1);

    for (int c = 0; c < NC; c++) {
        if (c + 1 < NC) { asm volatile("cp.async.wait_group 1;" ::: "memory"); }
        else            { asm volatile("cp.async.wait_group 0;" ::: "memory"); }
        __syncthreads();

        const uint32_t aa = a_addr0 + (c & 1) * STG;
        const uint32_t bb = b_addr0 + (c & 1) * STG;
#pragma unroll
        for (int kk = 0; kk < 2; kk++) {
            uint32_t Ahf[2][4], Alf[2][4];
            LDSM4(Ahf[0], aa + kk * 32);
            LDSM4(Ahf[1], aa + 16 * AW * 2 + kk * 32);
            LDSM4(Alf[0], aa + ABYTES + kk * 32);
            LDSM4(Alf[1], aa + ABYTES + 16 * AW * 2 + kk * 32);
#pragma unroll
            for (int np = 0; np < NT / 2; np++) {
                uint32_t Bh4[4], Bl4[4];
                LDSM4(Bh4, bb + np * 16 * AW * 2 + kk * 32);
                LDSM4(Bl4, bb + BBYTES + np * 16 * AW * 2 + kk * 32);
#pragma unroll
                for (int mt = 0; mt < 2; mt++) {
                    mma_bf(acc[mt][2 * np],     Ahf[mt], Bh4[0], Bh4[1]);
                    mma_bf(acc[mt][2 * np],     Ahf[mt], Bl4[0], Bl4[1]);
                    mma_bf(acc[mt][2 * np],     Alf[mt], Bh4[0], Bh4[1]);
                    mma_bf(acc[mt][2 * np + 1], Ahf[mt], Bh4[2], Bh4[3]);
                    mma_bf(acc[mt][2 * np + 1], Ahf[mt], Bl4[2], Bl4[3]);
                    mma_bf(acc[mt][2 * np + 1], Alf[mt], Bh4[2], Bh4[3]);
                }
            }
        }
        __syncthreads();
        if (c + 2 < NC) load_chunk(c + 2);
    }

#pragma unroll
    for (int mt = 0; mt < 2; mt++) {
        int row = m0 + wm + mt * 16 + (lane >> 2);
#pragma unroll
        for (int nt = 0; nt < NT; nt++) {
            int col = n0 + wn + nt * 8 + (lane & 3) * 2;
            float bv0 = bias[col], bv1 = bias[col + 1];
            float x0 = acc[mt][nt][0] + bv0, x1 = acc[mt][nt][1] + bv1;
            float x2 = acc[mt][nt][2] + bv0, x3 = acc[mt][nt][3] + bv1;
            if (act) { x0 = geluf(x0); x1 = geluf(x1); x2 = geluf(x2); x3 = geluf(x3); }
            *reinterpret_cast<float2*>(C + (size_t)row * N + col)       = make_float2(x0, x1);
            *reinterpret_cast<float2*>(C + (size_t)(row + 8) * N + col) = make_float2(x2, x3);
        }
    }
}

// ---------------- features: bf16 hi for all 4; lo residual for img/txt ----------------
__global__ void cvt_split_k(const float4* __restrict__ s0, const float4* __restrict__ s1,
                            const float4* __restrict__ s2, const float4* __restrict__ s3,
                            __nv_bfloat16* __restrict__ hi, __nv_bfloat16* __restrict__ lo)
{
    int i = blockIdx.x * blockDim.x + threadIdx.x;
    const int per = NB * 768 / 4;
    if (i >= 4 * per) return;
    int f = i / per, j = i - f * per;
    const float4* s = (f == 0 ? s0 : f == 1 ? s1 : f == 2 ? s2 : s3);
    float4 v = s[j];
    __nv_bfloat162 h0 = __floats2bfloat162_rn(v.x, v.y);
    __nv_bfloat162 h1 = __floats2bfloat162_rn(v.z, v.w);
    __nv_bfloat162* o = reinterpret_cast<__nv_bfloat162*>(hi + (size_t)i * 4);
    o[0] = h0; o[1] = h1;
    if (f < 2) {
        __nv_bfloat162* ol = reinterpret_cast<__nv_bfloat162*>(lo + (size_t)i * 4);
        ol[0] = __floats2bfloat162_rn(v.x - __bfloat162float(h0.x), v.y - __bfloat162float(h0.y));
        ol[1] = __floats2bfloat162_rn(v.z - __bfloat162float(h1.x), v.w - __bfloat162float(h1.y));
    }
}

__global__ void split_fp32_k(const float4* __restrict__ x, __nv_bfloat16* __restrict__ h,
                             __nv_bfloat16* __restrict__ l, int n4)
{
    int i = blockIdx.x * blockDim.x + threadIdx.x;
    if (i >= n4) return;
    float4 v = x[i];
    __nv_bfloat162 h0 = __floats2bfloat162_rn(v.x, v.y);
    __nv_bfloat162 h1 = __floats2bfloat162_rn(v.z, v.w);
    reinterpret_cast<__nv_bfloat162*>(h + (size_t)i * 4)[0] = h0;
    reinterpret_cast<__nv_bfloat162*>(h + (size_t)i * 4)[1] = h1;
    reinterpret_cast<__nv_bfloat162*>(l + (size_t)i * 4)[0] =
        __floats2bfloat162_rn(v.x - __bfloat162float(h0.x), v.y - __bfloat162float(h0.y));
    reinterpret_cast<__nv_bfloat162*>(l + (size_t)i * 4)[1] =
        __floats2bfloat162_rn(v.z - __bfloat162float(h1.x), v.w - __bfloat162float(h1.y));
}

// ---------------- combined transpose: 9 jobs (7 plain bf16 + 2 hi/lo split) ----------------
struct TJobs {
    const float* s[9];
    __nv_bfloat16* d[9];
    __nv_bfloat16* dl[9];   // nullptr => plain
    int K[9], N[9], t0[9];
    int njobs;
};
__global__ void transpose_combo_k(TJobs J) {
    __shared__ float tile[32][33];
    int bx = blockIdx.x;
    int j = 0;
#pragma unroll
    for (int q = 1; q < 9; q++) if (q < J.njobs && bx >= J.t0[q]) j = q;
    int local = bx - J.t0[j];
    int tilesx = J.N[j] / 32;
    int txb = local % tilesx, tyb = local / tilesx;
    const float* s = J.s[j];
    int K = J.K[j], N = J.N[j];
    int n = txb * 32 + threadIdx.x;
    int k = tyb * 32 + threadIdx.y;
#pragma unroll
    for (int i = 0; i < 32; i += 8) tile[threadIdx.y + i][threadIdx.x] = s[(size_t)(k + i) * N + n];
    __syncthreads();
    int n2 = txb * 32 + threadIdx.y;
    int k2 = tyb * 32 + threadIdx.x;
    __nv_bfloat16* d = J.d[j];
    __nv_bfloat16* dl = J.dl[j];
    if (dl == nullptr) {
#pragma unroll
        for (int i = 0; i < 32; i += 8)
            d[(size_t)(n2 + i) * K + k2] = __float2bfloat16(tile[threadIdx.x][threadIdx.y + i]);
    } else {
#pragma unroll
        for (int i = 0; i < 32; i += 8) {
            float v = tile[threadIdx.x][threadIdx.y + i];
            __nv_bfloat16 h = __float2bfloat16(v);
            d[(size_t)(n2 + i) * K + k2] = h;
            dl[(size_t)(n2 + i) * K + k2] = __float2bfloat16(v - __bfloat162float(h));
        }
    }
}

// ---------------- final dot head ----------------
__global__ void dot_head_k(const float* __restrict__ Hin, int K, int rows,
                           const float* __restrict__ w, const float* __restrict__ b,
                           float* __restrict__ outrow)
{
    int gw = (blockIdx.x * blockDim.x + threadIdx.x) >> 5;
    int lane = threadIdx.x & 31;
    if (gw >= rows) return;
    const float* row = Hin + (size_t)gw * K;
    float s = 0.f;
    for (int k = lane * 4; k < K; k += 128) {
        float4 v = *reinterpret_cast<const float4*>(row + k);
        float4 wv = *reinterpret_cast<const float4*>(w + k);
        s += v.x * wv.x + v.y * wv.y + v.z * wv.z + v.w * wv.w;
    }
#pragma unroll
    for (int o = 16; o; o >>= 1) s += __shfl_xor_sync(0xffffffffu, s, o);
    if (lane == 0) outrow[gw] = sigf(s + b[0]);
}

// ---------------- geometric quality + norms ----------------
__global__ void rowstats_k(const float* __restrict__ f0, const float* __restrict__ f1,
                           const float* __restrict__ f2, const float* __restrict__ f3,
                           float* __restrict__ out)
{
    int gw = (blockIdx.x * blockDim.x + threadIdx.x) >> 5;
    int lane = threadIdx.x & 31;
    if (gw >= 4 * NB) return;
    int feat = gw >> 14;
    int m = gw & (NB - 1);
    const float* f = (feat == 0 ? f0 : feat == 1 ? f1 : feat == 2 ? f2 : f3) + (size_t)m * HD;
    double sum = 0.0, ssq = 0.0;
    int cnt = 0;
    for (int k = lane * 4; k < HD; k += 128) {
        float4 v = *reinterpret_cast<const float4*>(f + k);
        sum += (double)v.x + v.y + v.z + v.w;
        ssq += (double)v.x * v.x + (double)v.y * v.y + (double)v.z * v.z + (double)v.w * v.w;
        cnt += (fabsf(v.x) > 0.01f) + (fabsf(v.y) > 0.01f) + (fabsf(v.z) > 0.01f) + (fabsf(v.w) > 0.01f);
    }
#pragma unroll
    for (int o = 16; o; o >>= 1) {
        sum += __shfl_xor_sync(0xffffffffu, sum, o);
        ssq += __shfl_xor_sync(0xffffffffu, ssq, o);
        cnt += __shfl_xor_sync(0xffffffffu, cnt, o);
    }
    if (lane == 0) {
        float n = (float)sqrt(ssq);
        float nq = sigf((n - 1.0f) * 2.0f);
        float sp = cnt * (1.0f / 768.0f);
        double var = (ssq - sum * sum / 768.0) / 767.0;
        if (var < 0.0) var = 0.0;
        float sq = sigf((float)sqrt(var) * 10.0f - 1.0f);
        out[feat * NB + m] = (nq + sp + sq) * (1.0f / 3.0f);
        if (feat < 2) g_norm[feat * NB + m] = n;
    }
}

// ---------------- info final (2*NB rows) ----------------
__global__ void info_final_k(const float* __restrict__ enc, float* __restrict__ outrow)
{
    int gw = (blockIdx.x * blockDim.x + threadIdx.x) >> 5;
    int lane = threadIdx.x & 31;
    if (gw >= 2 * NB) return;
    const float* e = enc + (size_t)gw * 64;
    float x0 = e[lane], x1 = e[lane + 32];
    int d0 = (int)rintf(sigf(x0) * 10.0f);
    int d1 = (int)rintf(sigf(x1) * 10.0f);
    float ent = 0.f;
#pragma unroll
    for (int b = 0; b < 11; b++) {
        int c = __popc(__ballot_sync(0xffffffffu, d0 == b)) +
                __popc(__ballot_sync(0xffffffffu, d1 == b));
        if (c > 0) {
            float p = c * (1.0f / 64.0f);
            ent -= p * logf(p + 1e-8f);
        }
    }
    if (lane == 0) {
        float eq = sigf(ent - 2.0f);
        float n = g_norm[gw];
        float cq = (n > 0.01f) ? (1.0f / 768.0f) : 0.0f;
        float t = n / fmaxf(n, 1e-12f);
        float dq = sigf(t * t - 0.5f);
        outrow[gw] = (eq + cq + dq) * (1.0f / 3.0f);
    }
}

__global__ void overall_k(float* __restrict__ out)
{
    int i = blockIdx.x * blockDim.x + threadIdx.x;
    if (i >= NB) return;
    float v = out[0 * NB + i] + out[1 * NB + i] + out[4 * NB + i] + out[5 * NB + i] +
              out[7 * NB + i] + 0.5f * (out[8 * NB + i] + out[9 * NB + i]);
    out[17 * NB + i] = v * (1.0f / 6.0f);
}

// ---------------- host ----------------
template<int BN, bool OUTBF0, bool OUTBF1>
static void launch_bf2(cudaStream_t st, APtrsB A, int nb, int Khalf, int Ktot,
                       const __nv_bfloat16* Wt0, const __nv_bfloat16* Wt1,
                       int N0, int N1, const float* b0, const float* b1,
                       void* C0, void* C1, int act)
{
    int smemB = 3 * (128 + BN) * 72 * 2;
    cudaFuncSetAttribute(gemm_bf16<BN, OUTBF0, OUTBF1>,
                         cudaFuncAttributeMaxDynamicSharedMemorySize, smemB);
    dim3 g((N0 + N1) / BN, nb * 128);
    gemm_bf16<BN, OUTBF0, OUTBF1><<<g, 256, smemB, st>>>(
        A, Khalf, Ktot, Wt0, Wt1, N0, N1, b0, b1, C0, C1, act);
}
template<int BN, bool OUTBF>
static void launch_bf(cudaStream_t st, APtrsB A, int nb, int Khalf, int Ktot,
                      const __nv_bfloat16* Wt, int N, const float* bias, void* C, int act)
{
    launch_bf2<BN, OUTBF, OUTBF>(st, A, nb, Khalf, Ktot, Wt, nullptr, N, 0, bias, nullptr, C, nullptr, act);
}
template<int BN>
static void launch_bf3(cudaStream_t st, APtrsB Ah, APtrsB Al, int nb, int Ktot,
                       const __nv_bfloat16* Wh, const __nv_bfloat16* Wl, int N,
                       const float* bias, float* C, int act)
{
    int smemB = 2 * (2 * 128 * 40 * 2 + 2 * BN * 40 * 2);
    cudaFuncSetAttribute(gemm_bf3<BN>, cudaFuncAttributeMaxDynamicSharedMemorySize, smemB);
    dim3 g(N / BN, nb * 128);
    gemm_bf3<BN><<<g, 256, smemB, st>>>(Ah, Al, Ktot, Wh, Wl, N, bias, C, act);
}

extern "C" void kernel_launch(void* const* d_in, const int* in_sizes, int n_in,
                              void* d_out, int out_size)
{
    const float* img  = (const float*)d_in[0];
    const float* txt  = (const float*)d_in[1];
    const float* eimg = (const float*)d_in[2];
    const float* etxt = (const float*)d_in[3];
    const float* info_w1 = (const float*)d_in[5];
    const float* info_b1 = (const float*)d_in[6];
    const float* info_w2 = (const float*)d_in[7];
    const float* info_b2 = (const float*)d_in[8];
    const float* imp_w1  = (const float*)d_in[9];
    const float* imp_b1  = (const float*)d_in[10];
    const float* imp_w2  = (const float*)d_in[11];
    const float* imp_b2  = (const float*)d_in[12];
    const float* disc_w1 = (const float*)d_in[13];
    const float* disc_b1 = (const float*)d_in[14];
    const float* disc_w2 = (const float*)d_in[15];
    const float* disc_b2 = (const float*)d_in[16];
    const float* disc_w3 = (const float*)d_in[17];
    const float* disc_b3 = (const float*)d_in[18];
    const float* cons_w1 = (const float*)d_in[19];
    const float* cons_b1 = (const float*)d_in[20];
    const float* cons_w2 = (const float*)d_in[21];
    const float* cons_b2 = (const float*)d_in[22];
    const float* cons_w3 = (const float*)d_in[23];
    const float* cons_b3 = (const float*)d_in[24];
    const float* diff_w1 = (const float*)d_in[25];
    const float* diff_b1 = (const float*)d_in[26];
    const float* diff_w2 = (const float*)d_in[27];
    const float* diff_b2 = (const float*)d_in[28];
    const float* diff_w3 = (const float*)d_in[29];
    const float* diff_b3 = (const float*)d_in[30];

    float* out = (float*)d_out;

    __nv_bfloat16 *featbf, *lo1, *h2, *l2, *scrAbf, *scrAbf3, *scrCbf;
    __nv_bfloat16 *w_imp1, *w_disc1, *w_disc2, *w_cons1, *w_cons2, *w_diff1, *w_diff2;
    __nv_bfloat16 *wi1h, *wi1l, *wi2h, *wi2l;
    float *scrB, *scrB2, *scrB3, *scrC, *scrD, *scrD2;
    cudaGetSymbolAddress((void**)&featbf, g_featbf);
    cudaGetSymbolAddress((void**)&lo1, g_lo1);
    cudaGetSymbolAddress((void**)&h2, g_h2);
    cudaGetSymbolAddress((void**)&l2, g_l2);
    cudaGetSymbolAddress((void**)&scrAbf, g_scrAbf);
    cudaGetSymbolAddress((void**)&scrAbf3, g_scrAbf3);
    cudaGetSymbolAddress((void**)&scrCbf, g_scrCbf);
    cudaGetSymbolAddress((void**)&scrB, g_scrB);
    cudaGetSymbolAddress((void**)&scrB2, g_scrB2);
    cudaGetSymbolAddress((void**)&scrB3, g_scrB3);
    cudaGetSymbolAddress((void**)&scrC, g_scrC);
    cudaGetSymbolAddress((void**)&scrD, g_scrD);
    cudaGetSymbolAddress((void**)&scrD2, g_scrD2);
    cudaGetSymbolAddress((void**)&w_imp1, g_w_imp1);
    cudaGetSymbolAddress((void**)&w_disc1, g_w_disc1);
    cudaGetSymbolAddress((void**)&w_disc2, g_w_disc2);
    cudaGetSymbolAddress((void**)&w_cons1, g_w_cons1);
    cudaGetSymbolAddress((void**)&w_cons2, g_w_cons2);
    cudaGetSymbolAddress((void**)&w_diff1, g_w_diff1);
    cudaGetSymbolAddress((void**)&w_diff2, g_w_diff2);
    cudaGetSymbolAddress((void**)&wi1h, g_wi1h);
    cudaGetSymbolAddress((void**)&wi1l, g_wi1l);
    cudaGetSymbolAddress((void**)&wi2h, g_wi2h);
    cudaGetSymbolAddress((void**)&wi2l, g_wi2l);

    const __nv_bfloat16* bimg  = featbf;
    const __nv_bfloat16* btxt  = featbf + (size_t)NB * 768;
    const __nv_bfloat16* beimg = featbf + (size_t)2 * NB * 768;
    const __nv_bfloat16* betxt = featbf + (size_t)3 * NB * 768;

    static cudaStream_t s1 = nullptr, s2 = nullptr;
    static cudaEvent_t e0 = nullptr, eT = nullptr, e1 = nullptr, e2 = nullptr;
    if (!s1) {
        cudaStreamCreateWithFlags(&s1, cudaStreamNonBlocking);
        cudaStreamCreateWithFlags(&s2, cudaStreamNonBlocking);
        cudaEventCreateWithFlags(&e0, cudaEventDisableTiming);
        cudaEventCreateWithFlags(&eT, cudaEventDisableTiming);
        cudaEventCreateWithFlags(&e1, cudaEventDisableTiming);
        cudaEventCreateWithFlags(&e2, cudaEventDisableTiming);
    }

    // fork
    cudaEventRecord(e0, 0);
    cudaStreamWaitEvent(s1, e0, 0);
    cudaStreamWaitEvent(s2, e0, 0);

    // s1: rowstats (inputs only)
    rowstats_k<<<(4 * NB) / 8, 256, 0, s1>>>(img, txt, eimg, etxt, out);

    // main: features (hi for all 4, lo for img/txt) + all 9 weight transposes in one launch
    cvt_split_k<<<(4 * NB * 768 / 4 + 255) / 256, 256>>>(
        (const float4*)img, (const float4*)txt, (const float4*)eimg, (const float4*)etxt,
        featbf, lo1);
    {
        TJobs J;
        const float* srcs[9] = { imp_w1, disc_w1, disc_w2, cons_w1, cons_w2, diff_w1, diff_w2,
                                 info_w1, info_w2 };
        __nv_bfloat16* dsts[9] = { w_imp1, w_disc1, w_disc2, w_cons1, w_cons2, w_diff1, w_diff2,
                                   wi1h, wi2h };
        __nv_bfloat16* dls[9] = { nullptr, nullptr, nullptr, nullptr, nullptr, nullptr, nullptr,
                                  wi1l, wi2l };
        int Ks[9] = { 768, 768, 256, 1536, 768, 1536, 768, 768, 256 };
        int Ns[9] = { 384, 256, 64, 768, 384, 768, 384, 256, 64 };
        int tot = 0;
        for (int j = 0; j < 9; j++) {
            J.s[j] = srcs[j]; J.d[j] = dsts[j]; J.dl[j] = dls[j];
            J.K[j] = Ks[j]; J.N[j] = Ns[j];
            J.t0[j] = tot;
            tot += (Ks[j] / 32) * (Ns[j] / 32);
        }
        J.njobs = 9;
        dim3 b(32, 8);
        transpose_combo_k<<<tot, b>>>(J);
    }
    cudaEventRecord(eT, 0);
    cudaStreamWaitEvent(s1, eT, 0);
    cudaStreamWaitEvent(s2, eT, 0);

    // s1: information (rows 4,5) — bf16x3 precise
    {
        APtrsB ah = {{ bimg, btxt, nullptr, nullptr }};
        APtrsB al = {{ lo1, lo1 + (size_t)NB * 768, nullptr, nullptr }};
        launch_bf3<128>(s1, ah, al, 2, 768, wi1h, wi1l, 256, info_b1, scrC, 1);
        split_fp32_k<<<(2 * NB * 256 / 4 + 255) / 256, 256, 0, s1>>>(
            (const float4*)scrC, h2, l2, 2 * NB * 256 / 4);
        APtrsB ah2 = {{ h2, h2 + (size_t)NB * 256, nullptr, nullptr }};
        APtrsB al2 = {{ l2, l2 + (size_t)NB * 256, nullptr, nullptr }};
        launch_bf3<64>(s1, ah2, al2, 2, 256, wi2h, wi2l, 64, info_b2, scrD2, 0);
        info_final_k<<<(2 * NB) / 8, 256, 0, s1>>>(scrD2, out + 4 * NB);
        cudaEventRecord(e1, s1);
    }

    // main: merged imp1+disc1 (N=384+256) over 4 batches, then heads + disc2 + diff chain
    {
        APtrsB a = {{ bimg, btxt, beimg, betxt }};
        launch_bf2<128, false, true>(0, a, 4, 768, 768,
                                     w_imp1, w_disc1, 384, 256, imp_b1, disc_b1,
                                     scrB, scrCbf, 1);
        dot_head_k<<<(4 * NB) / 8, 256>>>(scrB, 384, 4 * NB, imp_w2, imp_b2, out + 8 * NB);

        // disc2: batch order must be img,eimg,txt,etxt for rows 12..15
        APtrsB ad2 = {{ scrCbf, scrCbf + (size_t)2 * NB * 256, scrCbf + (size_t)NB * 256,
                        scrCbf + (size_t)3 * NB * 256 }};
        launch_bf<64, false>(0, ad2, 4, 256, 256, w_disc2, 64, disc_b2, scrD, 1);
        dot_head_k<<<(4 * NB) / 8, 256>>>(scrD, 64, 4 * NB, disc_w3, disc_b3, out + 12 * NB);

        APtrsB af = {{ beimg, betxt, nullptr, nullptr }};
        launch_bf<128, true>(0, af, 1, 768, 1536, w_diff1, 768, diff_b1, scrAbf3, 1);
        APtrsB af2 = {{ scrAbf3, nullptr, nullptr, nullptr }};
        launch_bf<128, false>(0, af2, 1, 768, 768, w_diff2, 384, diff_b2, scrB3, 1);
        dot_head_k<<<NB / 8, 256>>>(scrB3, 384, NB, diff_w3, diff_b3, out + 16 * NB);
    }

    // s2: consistency (rows 6,7)
    {
        APtrsB a = {{ bimg, btxt, beimg, betxt }};
        launch_bf<128, true>(s2, a, 2, 768, 1536, w_cons1, 768, cons_b1, scrAbf, 1);
        APtrsB a2 = {{ scrAbf, scrAbf + (size_t)NB * 768, nullptr, nullptr }};
        launch_bf<128, false>(s2, a2, 2, 768, 768, w_cons2, 384, cons_b2, scrB2, 1);
        dot_head_k<<<(2 * NB) / 8, 256, 0, s2>>>(scrB2, 384, 2 * NB, cons_w3, cons_b3, out + 6 * NB);
        cudaEventRecord(e2, s2);
    }

    // join + overall
    cudaStreamWaitEvent(0, e1, 0);
    cudaStreamWaitEvent(0, e2, 0);
    overall_k<<<NB / 256, 256>>>(out);
}

// round 12
// speedup vs baseline: 1.4547x; 1.0405x over previous
#include <cuda_runtime.h>
#include <cuda_bf16.h>
#include <cstdint>

#define NB 16384
#define HD 768

// ---------------- scratch ----------------
__device__ __nv_bfloat16 g_featbf[4 * NB * 768];
__device__ __nv_bfloat16 g_lo1[2 * NB * 768];
__device__ __nv_bfloat16 g_h2[2 * NB * 256];
__device__ __nv_bfloat16 g_l2[2 * NB * 256];
__device__ __nv_bfloat16 g_scrAbf[2 * NB * 768];     // cons1 (bf16) [s2]
__device__ __nv_bfloat16 g_scrAbf3[NB * 768];        // diff1 (bf16) [main]
__device__ __nv_bfloat16 g_scrCbf[4 * NB * 256];     // disc1 (bf16) [main]
__device__ float g_scrD2[2 * NB * 64];               // info2 (fp32) [s1]
__device__ float g_logit[11 * NB];                   // imp 4NB | disc 4NB | cons 2NB | diff NB
__device__ float g_norm[2 * NB];
__device__ __nv_bfloat16 g_w_imp1[384 * 768];
__device__ __nv_bfloat16 g_w_disc1[256 * 768];
__device__ __nv_bfloat16 g_w_disc2[64 * 256];
__device__ __nv_bfloat16 g_w_cons1[768 * 1536];
__device__ __nv_bfloat16 g_w_cons2[384 * 768];
__device__ __nv_bfloat16 g_w_diff1[768 * 1536];
__device__ __nv_bfloat16 g_w_diff2[384 * 768];
__device__ __nv_bfloat16 g_wi1h[256 * 768], g_wi1l[256 * 768];
__device__ __nv_bfloat16 g_wi2h[64 * 256],  g_wi2l[64 * 256];

__device__ __forceinline__ float sigf(float x) { return 1.0f / (1.0f + expf(-x)); }
__device__ __forceinline__ float geluf(float x) { return 0.5f * x * (1.0f + erff(x * 0.70710678118654752f)); }

__device__ __forceinline__ uint32_t smem_u32(const void* p) {
    uint32_t a;
    asm("{ .reg .u64 t; cvta.to.shared.u64 t, %1; cvt.u32.u64 %0, t; }" : "=r"(a) : "l"(p));
    return a;
}
__device__ __forceinline__ void mma_bf(float* d, const uint32_t* a, uint32_t b0, uint32_t b1) {
    asm volatile(
        "mma.sync.aligned.m16n8k16.row.col.f32.bf16.bf16.f32 "
        "{%0,%1,%2,%3}, {%4,%5,%6,%7}, {%8,%9}, {%0,%1,%2,%3};"
        : "+f"(d[0]), "+f"(d[1]), "+f"(d[2]), "+f"(d[3])
        : "r"(a[0]), "r"(a[1]), "r"(a[2]), "r"(a[3]), "r"(b0), "r"(b1));
}
#define LDSM4(r, addr) \
    asm volatile("ldmatrix.sync.aligned.m8n8.x4.shared.b16 {%0,%1,%2,%3}, [%4];" \
        : "=r"((r)[0]), "=r"((r)[1]), "=r"((r)[2]), "=r"((r)[3]) : "r"(addr))
#define CP_ASYNC16(dst, src) \
    asm volatile("cp.async.cg.shared.global [%0], [%1], 16;" :: "r"(dst), "l"(src))
#define CP_COMMIT() asm volatile("cp.async.commit_group;" ::: "memory")

struct APtrsB { const __nv_bfloat16* p[4]; };

// ================= bf16 GEMM: BM=128, BK=64, 3-stage, occ 2, two-region =================
// Per-region epilogue mode: 0 = fp32 store, 1 = bf16 store, 2 = head-fused
// (gelu + dot(head weight w) + atomicAdd into logits C).
template<int BN, int M0, int M1>
__global__ void __launch_bounds__(256, 2) gemm_bf16(
    APtrsB A, int Khalf, int Ktot,
    const __nv_bfloat16* __restrict__ Wt0, const __nv_bfloat16* __restrict__ Wt1,
    int N0, int N1, const float* __restrict__ b0, const float* __restrict__ b1,
    void* __restrict__ C0v, void* __restrict__ C1v,
    const float* __restrict__ w0, const float* __restrict__ w1, int act)
{
    constexpr int AW = 72;
    constexpr int ABYTES = 128 * AW * 2;
    constexpr int BBYTES = BN * AW * 2;
    constexpr int STG = ABYTES + BBYTES;
    constexpr int NT = BN / 16;

    extern __shared__ char smem[];
    const int t = threadIdx.x, lane = t & 31, wid = t >> 5;
    const int batch = blockIdx.y >> 7;
    const int m0 = (blockIdx.y & 127) * 128;
    const int n0g = blockIdx.x * BN;
    const int wm = (wid & 3) * 32;
    const int wn = (wid >> 2) * (BN / 2);

    const bool r1 = (n0g >= N0);
    const __nv_bfloat16* Wt = r1 ? Wt1 : Wt0;
    const float* bias = r1 ? b1 : b0;
    const int N = r1 ? N1 : N0;
    const int n0 = n0g - (r1 ? N0 : 0);

    const __nv_bfloat16 *A1, *A2;
    if (Khalf < Ktot) { A1 = A.p[2 * batch]; A2 = A.p[2 * batch + 1]; }
    else              { A1 = A.p[batch];     A2 = A1; }

    const uint32_t sbase = smem_u32(smem);
    const uint32_t a_addr0 = sbase + (uint32_t)((wm + (lane & 15)) * (AW * 2) + (lane >> 4) * 16);
    const int grp = lane >> 3;
    const int b_r = (lane & 7) + ((grp >= 2) ? 8 : 0);
    const uint32_t b_addr0 = sbase + ABYTES + (uint32_t)((wn + b_r) * (AW * 2) + (grp & 1) * 16);

    float acc[2][NT][4];
#pragma unroll
    for (int i = 0; i < 2; i++)
#pragma unroll
        for (int j = 0; j < NT; j++)
#pragma unroll
            for (int q = 0; q < 4; q++) acc[i][j][q] = 0.0f;

    auto load_chunk = [&](int c) {
        const int stg = c % 3;
        int kk = c * 64;
        const __nv_bfloat16* Ab = A1;
        if (kk >= Khalf) { Ab = A2; kk -= Khalf; }
        uint32_t sA = sbase + stg * STG;
#pragma unroll
        for (int i = 0; i < 4; i++) {
            int idx = t + i * 256, r = idx >> 3, c8 = idx & 7;
            CP_ASYNC16(sA + (uint32_t)(r * (AW * 2) + c8 * 16),
                       Ab + (size_t)(m0 + r) * Khalf + kk + c8 * 8);
        }
        uint32_t sB = sA + ABYTES;
#pragma unroll
        for (int i = 0; i < BN / 32; i++) {
            int idx = t + i * 256, r = idx >> 3, c8 = idx & 7;
            CP_ASYNC16(sB + (uint32_t)(r * (AW * 2) + c8 * 16),
                       Wt + (size_t)(n0 + r) * Ktot + c * 64 + c8 * 8);
        }
        CP_COMMIT();
    };

    const int NC = Ktot >> 6;
    load_chunk(0);
    if (NC > 1) load_chunk(1);

    for (int c = 0; c < NC; c++) {
        if (c + 1 < NC) { asm volatile("cp.async.wait_group 1;" ::: "memory"); }
        else            { asm volatile("cp.async.wait_group 0;" ::: "memory"); }
        __syncthreads();
        if (c + 2 < NC) load_chunk(c + 2);

        const uint32_t aa = a_addr0 + (c % 3) * STG;
        const uint32_t bb = b_addr0 + (c % 3) * STG;
#pragma unroll
        for (int kk = 0; kk < 4; kk++) {
            uint32_t Af[2][4];
            LDSM4(Af[0], aa + kk * 32);
            LDSM4(Af[1], aa + 16 * (AW * 2) + kk * 32);
#pragma unroll
            for (int np = 0; np < NT / 2; np++) {
                uint32_t B4[4];
                LDSM4(B4, bb + np * 16 * (AW * 2) + kk * 32);
#pragma unroll
                for (int mt = 0; mt < 2; mt++) {
                    mma_bf(acc[mt][2 * np],     Af[mt], B4[0], B4[1]);
                    mma_bf(acc[mt][2 * np + 1], Af[mt], B4[2], B4[3]);
                }
            }
        }
    }

    const int mode = r1 ? M1 : M0;
    const float* wv = r1 ? w1 : w0;
    void* Cv = r1 ? C1v : C0v;
#pragma unroll
    for (int mt = 0; mt < 2; mt++) {
        int row = batch * NB + m0 + wm + mt * 16 + (lane >> 2);
        float p0 = 0.f, p1 = 0.f;
#pragma unroll
        for (int nt = 0; nt < NT; nt++) {
            int col = n0 + wn + nt * 8 + (lane & 3) * 2;
            float bv0 = __ldg(bias + col), bv1 = __ldg(bias + col + 1);
            float x0 = acc[mt][nt][0] + bv0, x1 = acc[mt][nt][1] + bv1;
            float x2 = acc[mt][nt][2] + bv0, x3 = acc[mt][nt][3] + bv1;
            if (act) { x0 = geluf(x0); x1 = geluf(x1); x2 = geluf(x2); x3 = geluf(x3); }
            if (mode == 2) {
                float wv0 = __ldg(wv + col), wv1 = __ldg(wv + col + 1);
                p0 += x0 * wv0 + x1 * wv1;
                p1 += x2 * wv0 + x3 * wv1;
            } else if (mode == 1) {
                __nv_bfloat16* C = (__nv_bfloat16*)Cv;
                *reinterpret_cast<__nv_bfloat162*>(C + (size_t)row * N + col) =
                    __floats2bfloat162_rn(x0, x1);
                *reinterpret_cast<__nv_bfloat162*>(C + (size_t)(row + 8) * N + col) =
                    __floats2bfloat162_rn(x2, x3);
            } else {
                float* C = (float*)Cv;
                *reinterpret_cast<float2*>(C + (size_t)row * N + col)       = make_float2(x0, x1);
                *reinterpret_cast<float2*>(C + (size_t)(row + 8) * N + col) = make_float2(x2, x3);
            }
        }
        if (mode == 2) {
            // reduce over the 4 col-lanes (same row: lane>>2 constant, lane&3 varies)
            p0 += __shfl_xor_sync(0xffffffffu, p0, 1);
            p0 += __shfl_xor_sync(0xffffffffu, p0, 2);
            p1 += __shfl_xor_sync(0xffffffffu, p1, 1);
            p1 += __shfl_xor_sync(0xffffffffu, p1, 2);
            if ((lane & 3) == 0) {
                float* L = (float*)Cv;
                atomicAdd(&L[row], p0);
                atomicAdd(&L[row + 8], p1);
            }
        }
    }
}

// ================= bf16x3 precise GEMM (info path); OUTSPLIT writes bf16 hi/lo =================
template<int BN, bool OUTSPLIT>
__global__ void __launch_bounds__(256, 2) gemm_bf3(
    APtrsB Ah, APtrsB Al, int Ktot,
    const __nv_bfloat16* __restrict__ Wh, const __nv_bfloat16* __restrict__ Wl, int N,
    const float* __restrict__ bias, void* __restrict__ Cv, void* __restrict__ Clv, int act)
{
    constexpr int AW = 40;
    constexpr int ABYTES = 128 * AW * 2;
    constexpr int BBYTES = BN * AW * 2;
    constexpr int STG = 2 * ABYTES + 2 * BBYTES;
    constexpr int NT = BN / 16;

    extern __shared__ char smem[];
    const int t = threadIdx.x, lane = t & 31, wid = t >> 5;
    const int batch = blockIdx.y >> 7;
    const int m0 = (blockIdx.y & 127) * 128;
    const int n0 = blockIdx.x * BN;
    const int wm = (wid & 3) * 32;
    const int wn = (wid >> 2) * (BN / 2);

    const __nv_bfloat16* A1h = Ah.p[batch];
    const __nv_bfloat16* A1l = Al.p[batch];

    const uint32_t sbase = smem_u32(smem);
    const uint32_t a_addr0 = sbase + (uint32_t)((wm + (lane & 15)) * AW * 2 + (lane >> 4) * 16);
    const int grp = lane >> 3;
    const int b_r = (lane & 7) + ((grp >= 2) ? 8 : 0);
    const uint32_t b_addr0 = sbase + 2 * ABYTES + (uint32_t)((wn + b_r) * AW * 2 + (grp & 1) * 16);

    float acc[2][NT][4];
#pragma unroll
    for (int i = 0; i < 2; i++)
#pragma unroll
        for (int j = 0; j < NT; j++)
#pragma unroll
            for (int q = 0; q < 4; q++) acc[i][j][q] = 0.0f;

    auto load_chunk = [&](int c) {
        const int stg = c & 1;
        const int kk = c * 32;
        uint32_t base = sbase + stg * STG;
#pragma unroll
        for (int i = 0; i < 2; i++) {
            int idx = t + i * 256, r = idx >> 2, c8 = idx & 3;
            uint32_t off = (uint32_t)(r * AW * 2 + c8 * 16);
            size_t go = (size_t)(m0 + r) * Ktot + kk + c8 * 8;
            CP_ASYNC16(base + off,           A1h + go);
            CP_ASYNC16(base + ABYTES + off,  A1l + go);
        }
        uint32_t sB = base + 2 * ABYTES;
#pragma unroll
        for (int i = 0; i < BN / 64; i++) {
            int idx = t + i * 256, r = idx >> 2, c8 = idx & 3;
            uint32_t off = (uint32_t)(r * AW * 2 + c8 * 16);
            size_t go = (size_t)(n0 + r) * Ktot + kk + c8 * 8;
            CP_ASYNC16(sB + off,           Wh + go);
            CP_ASYNC16(sB + BBYTES + off,  Wl + go);
        }
        CP_COMMIT();
    };

    const int NC = Ktot >> 5;
    load_chunk(0);
    if (NC > 1) load_chunk(1);

    for (int c = 0; c < NC; c++) {
        if (c + 1 < NC) { asm volatile("cp.async.wait_group 1;" ::: "memory"); }
        else            { asm volatile("cp.async.wait_group 0;" ::: "memory"); }
        __syncthreads();

        const uint32_t aa = a_addr0 + (c & 1) * STG;
        const uint32_t bb = b_addr0 + (c & 1) * STG;
#pragma unroll
        for (int kk = 0; kk < 2; kk++) {
            uint32_t Ahf[2][4], Alf[2][4];
            LDSM4(Ahf[0], aa + kk * 32);
            LDSM4(Ahf[1], aa + 16 * AW * 2 + kk * 32);
            LDSM4(Alf[0], aa + ABYTES + kk * 32);
            LDSM4(Alf[1], aa + ABYTES + 16 * AW * 2 + kk * 32);
#pragma unroll
            for (int np = 0; np < NT / 2; np++) {
                uint32_t Bh4[4], Bl4[4];
                LDSM4(Bh4, bb + np * 16 * AW * 2 + kk * 32);
                LDSM4(Bl4, bb + BBYTES + np * 16 * AW * 2 + kk * 32);
#pragma unroll
                for (int mt = 0; mt < 2; mt++) {
                    mma_bf(acc[mt][2 * np],     Ahf[mt], Bh4[0], Bh4[1]);
                    mma_bf(acc[mt][2 * np],     Ahf[mt], Bl4[0], Bl4[1]);
                    mma_bf(acc[mt][2 * np],     Alf[mt], Bh4[0], Bh4[1]);
                    mma_bf(acc[mt][2 * np + 1], Ahf[mt], Bh4[2], Bh4[3]);
                    mma_bf(acc[mt][2 * np + 1], Ahf[mt], Bl4[2], Bl4[3]);
                    mma_bf(acc[mt][2 * np + 1], Alf[mt], Bh4[2], Bh4[3]);
                }
            }
        }
        __syncthreads();
        if (c + 2 < NC) load_chunk(c + 2);
    }

#pragma unroll
    for (int mt = 0; mt < 2; mt++) {
        int row = batch * NB + m0 + wm + mt * 16 + (lane >> 2);
#pragma unroll
        for (int nt = 0; nt < NT; nt++) {
            int col = n0 + wn + nt * 8 + (lane & 3) * 2;
            float bv0 = bias[col], bv1 = bias[col + 1];
            float x0 = acc[mt][nt][0] + bv0, x1 = acc[mt][nt][1] + bv1;
            float x2 = acc[mt][nt][2] + bv0, x3 = acc[mt][nt][3] + bv1;
            if (act) { x0 = geluf(x0); x1 = geluf(x1); x2 = geluf(x2); x3 = geluf(x3); }
            if (OUTSPLIT) {
                __nv_bfloat16* Ch = (__nv_bfloat16*)Cv;
                __nv_bfloat16* Cl = (__nv_bfloat16*)Clv;
                __nv_bfloat162 h0 = __floats2bfloat162_rn(x0, x1);
                __nv_bfloat162 h1 = __floats2bfloat162_rn(x2, x3);
                *reinterpret_cast<__nv_bfloat162*>(Ch + (size_t)row * N + col) = h0;
                *reinterpret_cast<__nv_bfloat162*>(Ch + (size_t)(row + 8) * N + col) = h1;
                *reinterpret_cast<__nv_bfloat162*>(Cl + (size_t)row * N + col) =
                    __floats2bfloat162_rn(x0 - __bfloat162float(h0.x), x1 - __bfloat162float(h0.y));
                *reinterpret_cast<__nv_bfloat162*>(Cl + (size_t)(row + 8) * N + col) =
                    __floats2bfloat162_rn(x2 - __bfloat162float(h1.x), x3 - __bfloat162float(h1.y));
            } else {
                float* C = (float*)Cv;
                *reinterpret_cast<float2*>(C + (size_t)row * N + col)       = make_float2(x0, x1);
                *reinterpret_cast<float2*>(C + (size_t)(row + 8) * N + col) = make_float2(x2, x3);
            }
        }
    }
}

// ---------------- features: bf16 hi for all 4; lo residual for img/txt ----------------
__global__ void cvt_split_k(const float4* __restrict__ s0, const float4* __restrict__ s1,
                            const float4* __restrict__ s2, const float4* __restrict__ s3,
                            __nv_bfloat16* __restrict__ hi, __nv_bfloat16* __restrict__ lo)
{
    int i = blockIdx.x * blockDim.x + threadIdx.x;
    const int per = NB * 768 / 4;
    if (i >= 4 * per) return;
    int f = i / per, j = i - f * per;
    const float4* s = (f == 0 ? s0 : f == 1 ? s1 : f == 2 ? s2 : s3);
    float4 v = s[j];
    __nv_bfloat162 h0 = __floats2bfloat162_rn(v.x, v.y);
    __nv_bfloat162 h1 = __floats2bfloat162_rn(v.z, v.w);
    __nv_bfloat162* o = reinterpret_cast<__nv_bfloat162*>(hi + (size_t)i * 4);
    o[0] = h0; o[1] = h1;
    if (f < 2) {
        __nv_bfloat162* ol = reinterpret_cast<__nv_bfloat162*>(lo + (size_t)i * 4);
        ol[0] = __floats2bfloat162_rn(v.x - __bfloat162float(h0.x), v.y - __bfloat162float(h0.y));
        ol[1] = __floats2bfloat162_rn(v.z - __bfloat162float(h1.x), v.w - __bfloat162float(h1.y));
    }
}

// ---------------- zero logits ----------------
__global__ void zero_k(float4* __restrict__ p, int n4) {
    int i = blockIdx.x * blockDim.x + threadIdx.x;
    if (i < n4) p[i] = make_float4(0.f, 0.f, 0.f, 0.f);
}

// ---------------- sigmoid finisher ----------------
__global__ void sig_k(const float* __restrict__ logits, const float* __restrict__ b,
                      float* __restrict__ outbase, int n) {
    int i = blockIdx.x * blockDim.x + threadIdx.x;
    if (i < n) outbase[i] = sigf(logits[i] + b[0]);
}

// ---------------- combined transpose: 9 jobs (7 plain bf16 + 2 hi/lo split) ----------------
struct TJobs {
    const float* s[9];
    __nv_bfloat16* d[9];
    __nv_bfloat16* dl[9];
    int K[9], N[9], t0[9];
    int njobs;
};
__global__ void transpose_combo_k(TJobs J) {
    __shared__ float tile[32][33];
    int bx = blockIdx.x;
    int j = 0;
#pragma unroll
    for (int q = 1; q < 9; q++) if (q < J.njobs && bx >= J.t0[q]) j = q;
    int local = bx - J.t0[j];
    int tilesx = J.N[j] / 32;
    int txb = local % tilesx, tyb = local / tilesx;
    const float* s = J.s[j];
    int K = J.K[j], N = J.N[j];
    int n = txb * 32 + threadIdx.x;
    int k = tyb * 32 + threadIdx.y;
#pragma unroll
    for (int i = 0; i < 32; i += 8) tile[threadIdx.y + i][threadIdx.x] = s[(size_t)(k + i) * N + n];
    __syncthreads();
    int n2 = txb * 32 + threadIdx.y;
    int k2 = tyb * 32 + threadIdx.x;
    __nv_bfloat16* d = J.d[j];
    __nv_bfloat16* dl = J.dl[j];
    if (dl == nullptr) {
#pragma unroll
        for (int i = 0; i < 32; i += 8)
            d[(size_t)(n2 + i) * K + k2] = __float2bfloat16(tile[threadIdx.x][threadIdx.y + i]);
    } else {
#pragma unroll
        for (int i = 0; i < 32; i += 8) {
            float v = tile[threadIdx.x][threadIdx.y + i];
            __nv_bfloat16 h = __float2bfloat16(v);
            d[(size_t)(n2 + i) * K + k2] = h;
            dl[(size_t)(n2 + i) * K + k2] = __float2bfloat16(v - __bfloat162float(h));
        }
    }
}

// ---------------- geometric quality + norms ----------------
__global__ void rowstats_k(const float* __restrict__ f0, const float* __restrict__ f1,
                           const float* __restrict__ f2, const float* __restrict__ f3,
                           float* __restrict__ out)
{
    int gw = (blockIdx.x * blockDim.x + threadIdx.x) >> 5;
    int lane = threadIdx.x & 31;
    if (gw >= 4 * NB) return;
    int feat = gw >> 14;
    int m = gw & (NB - 1);
    const float* f = (feat == 0 ? f0 : feat == 1 ? f1 : feat == 2 ? f2 : f3) + (size_t)m * HD;
    double sum = 0.0, ssq = 0.0;
    int cnt = 0;
    for (int k = lane * 4; k < HD; k += 128) {
        float4 v = *reinterpret_cast<const float4*>(f + k);
        sum += (double)v.x + v.y + v.z + v.w;
        ssq += (double)v.x * v.x + (double)v.y * v.y + (double)v.z * v.z + (double)v.w * v.w;
        cnt += (fabsf(v.x) > 0.01f) + (fabsf(v.y) > 0.01f) + (fabsf(v.z) > 0.01f) + (fabsf(v.w) > 0.01f);
    }
#pragma unroll
    for (int o = 16; o; o >>= 1) {
        sum += __shfl_xor_sync(0xffffffffu, sum, o);
        ssq += __shfl_xor_sync(0xffffffffu, ssq, o);
        cnt += __shfl_xor_sync(0xffffffffu, cnt, o);
    }
    if (lane == 0) {
        float n = (float)sqrt(ssq);
        float nq = sigf((n - 1.0f) * 2.0f);
        float sp = cnt * (1.0f / 768.0f);
        double var = (ssq - sum * sum / 768.0) / 767.0;
        if (var < 0.0) var = 0.0;
        float sq = sigf((float)sqrt(var) * 10.0f - 1.0f);
        out[feat * NB + m] = (nq + sp + sq) * (1.0f / 3.0f);
        if (feat < 2) g_norm[feat * NB + m] = n;
    }
}

// ---------------- info final (2*NB rows) ----------------
__global__ void info_final_k(const float* __restrict__ enc, float* __restrict__ outrow)
{
    int gw = (blockIdx.x * blockDim.x + threadIdx.x) >> 5;
    int lane = threadIdx.x & 31;
    if (gw >= 2 * NB) return;
    const float* e = enc + (size_t)gw * 64;
    float x0 = e[lane], x1 = e[lane + 32];
    int d0 = (int)rintf(sigf(x0) * 10.0f);
    int d1 = (int)rintf(sigf(x1) * 10.0f);
    float ent = 0.f;
#pragma unroll
    for (int b = 0; b < 11; b++) {
        int c = __popc(__ballot_sync(0xffffffffu, d0 == b)) +
                __popc(__ballot_sync(0xffffffffu, d1 == b));
        if (c > 0) {
            float p = c * (1.0f / 64.0f);
            ent -= p * logf(p + 1e-8f);
        }
    }
    if (lane == 0) {
        float eq = sigf(ent - 2.0f);
        float n = g_norm[gw];
        float cq = (n > 0.01f) ? (1.0f / 768.0f) : 0.0f;
        float t = n / fmaxf(n, 1e-12f);
        float dq = sigf(t * t - 0.5f);
        outrow[gw] = (eq + cq + dq) * (1.0f / 3.0f);
    }
}

__global__ void overall_k(float* __restrict__ out)
{
    int i = blockIdx.x * blockDim.x + threadIdx.x;
    if (i >= NB) return;
    float v = out[0 * NB + i] + out[1 * NB + i] + out[4 * NB + i] + out[5 * NB + i] +
              out[7 * NB + i] + 0.5f * (out[8 * NB + i] + out[9 * NB + i]);
    out[17 * NB + i] = v * (1.0f / 6.0f);
}

// ---------------- host ----------------
template<int BN, int M0, int M1>
static void launch_bf2(cudaStream_t st, APtrsB A, int nb, int Khalf, int Ktot,
                       const __nv_bfloat16* Wt0, const __nv_bfloat16* Wt1,
                       int N0, int N1, const float* b0, const float* b1,
                       void* C0, void* C1, const float* w0, const float* w1, int act)
{
    int smemB = 3 * (128 + BN) * 72 * 2;
    cudaFuncSetAttribute(gemm_bf16<BN, M0, M1>,
                         cudaFuncAttributeMaxDynamicSharedMemorySize, smemB);
    dim3 g((N0 + N1) / BN, nb * 128);
    gemm_bf16<BN, M0, M1><<<g, 256, smemB, st>>>(
        A, Khalf, Ktot, Wt0, Wt1, N0, N1, b0, b1, C0, C1, w0, w1, act);
}
template<int BN, int M>
static void launch_bf(cudaStream_t st, APtrsB A, int nb, int Khalf, int Ktot,
                      const __nv_bfloat16* Wt, int N, const float* bias, void* C,
                      const float* w, int act)
{
    launch_bf2<BN, M, M>(st, A, nb, Khalf, Ktot, Wt, nullptr, N, 0, bias, nullptr,
                         C, nullptr, w, nullptr, act);
}
template<int BN, bool OUTSPLIT>
static void launch_bf3(cudaStream_t st, APtrsB Ah, APtrsB Al, int nb, int Ktot,
                       const __nv_bfloat16* Wh, const __nv_bfloat16* Wl, int N,
                       const float* bias, void* C, void* Cl, int act)
{
    int smemB = 2 * (2 * 128 * 40 * 2 + 2 * BN * 40 * 2);
    cudaFuncSetAttribute(gemm_bf3<BN, OUTSPLIT>, cudaFuncAttributeMaxDynamicSharedMemorySize, smemB);
    dim3 g(N / BN, nb * 128);
    gemm_bf3<BN, OUTSPLIT><<<g, 256, smemB, st>>>(Ah, Al, Ktot, Wh, Wl, N, bias, C, Cl, act);
}

extern "C" void kernel_launch(void* const* d_in, const int* in_sizes, int n_in,
                              void* d_out, int out_size)
{
    const float* img  = (const float*)d_in[0];
    const float* txt  = (const float*)d_in[1];
    const float* eimg = (const float*)d_in[2];
    const float* etxt = (const float*)d_in[3];
    const float* info_w1 = (const float*)d_in[5];
    const float* info_b1 = (const float*)d_in[6];
    const float* info_w2 = (const float*)d_in[7];
    const float* info_b2 = (const float*)d_in[8];
    const float* imp_w1  = (const float*)d_in[9];
    const float* imp_b1  = (const float*)d_in[10];
    const float* imp_w2  = (const float*)d_in[11];
    const float* imp_b2  = (const float*)d_in[12];
    const float* disc_w1 = (const float*)d_in[13];
    const float* disc_b1 = (const float*)d_in[14];
    const float* disc_w2 = (const float*)d_in[15];
    const float* disc_b2 = (const float*)d_in[16];
    const float* disc_w3 = (const float*)d_in[17];
    const float* disc_b3 = (const float*)d_in[18];
    const float* cons_w1 = (const float*)d_in[19];
    const float* cons_b1 = (const float*)d_in[20];
    const float* cons_w2 = (const float*)d_in[21];
    const float* cons_b2 = (const float*)d_in[22];
    const float* cons_w3 = (const float*)d_in[23];
    const float* cons_b3 = (const float*)d_in[24];
    const float* diff_w1 = (const float*)d_in[25];
    const float* diff_b1 = (const float*)d_in[26];
    const float* diff_w2 = (const float*)d_in[27];
    const float* diff_b2 = (const float*)d_in[28];
    const float* diff_w3 = (const float*)d_in[29];
    const float* diff_b3 = (const float*)d_in[30];

    float* out = (float*)d_out;

    __nv_bfloat16 *featbf, *lo1, *h2, *l2, *scrAbf, *scrAbf3, *scrCbf;
    __nv_bfloat16 *w_imp1, *w_disc1, *w_disc2, *w_cons1, *w_cons2, *w_diff1, *w_diff2;
    __nv_bfloat16 *wi1h, *wi1l, *wi2h, *wi2l;
    float *scrD2, *logit;
    cudaGetSymbolAddress((void**)&featbf, g_featbf);
    cudaGetSymbolAddress((void**)&lo1, g_lo1);
    cudaGetSymbolAddress((void**)&h2, g_h2);
    cudaGetSymbolAddress((void**)&l2, g_l2);
    cudaGetSymbolAddress((void**)&scrAbf, g_scrAbf);
    cudaGetSymbolAddress((void**)&scrAbf3, g_scrAbf3);
    cudaGetSymbolAddress((void**)&scrCbf, g_scrCbf);
    cudaGetSymbolAddress((void**)&scrD2, g_scrD2);
    cudaGetSymbolAddress((void**)&logit, g_logit);
    cudaGetSymbolAddress((void**)&w_imp1, g_w_imp1);
    cudaGetSymbolAddress((void**)&w_disc1, g_w_disc1);
    cudaGetSymbolAddress((void**)&w_disc2, g_w_disc2);
    cudaGetSymbolAddress((void**)&w_cons1, g_w_cons1);
    cudaGetSymbolAddress((void**)&w_cons2, g_w_cons2);
    cudaGetSymbolAddress((void**)&w_diff1, g_w_diff1);
    cudaGetSymbolAddress((void**)&w_diff2, g_w_diff2);
    cudaGetSymbolAddress((void**)&wi1h, g_wi1h);
    cudaGetSymbolAddress((void**)&wi1l, g_wi1l);
    cudaGetSymbolAddress((void**)&wi2h, g_wi2h);
    cudaGetSymbolAddress((void**)&wi2l, g_wi2l);

    float* logit_imp  = logit;               // 4*NB
    float* logit_disc = logit + 4 * NB;      // 4*NB
    float* logit_cons = logit + 8 * NB;      // 2*NB
    float* logit_diff = logit + 10 * NB;     // 1*NB

    const __nv_bfloat16* bimg  = featbf;
    const __nv_bfloat16* btxt  = featbf + (size_t)NB * 768;
    const __nv_bfloat16* beimg = featbf + (size_t)2 * NB * 768;
    const __nv_bfloat16* betxt = featbf + (size_t)3 * NB * 768;

    static cudaStream_t s1 = nullptr, s2 = nullptr;
    static cudaEvent_t e0 = nullptr, eT = nullptr, e1 = nullptr, e2 = nullptr;
    if (!s1) {
        cudaStreamCreateWithFlags(&s1, cudaStreamNonBlocking);
        cudaStreamCreateWithFlags(&s2, cudaStreamNonBlocking);
        cudaEventCreateWithFlags(&e0, cudaEventDisableTiming);
        cudaEventCreateWithFlags(&eT, cudaEventDisableTiming);
        cudaEventCreateWithFlags(&e1, cudaEventDisableTiming);
        cudaEventCreateWithFlags(&e2, cudaEventDisableTiming);
    }

    // fork
    cudaEventRecord(e0, 0);
    cudaStreamWaitEvent(s1, e0, 0);
    cudaStreamWaitEvent(s2, e0, 0);

    // s1: rowstats (inputs only)
    rowstats_k<<<(4 * NB) / 8, 256, 0, s1>>>(img, txt, eimg, etxt, out);

    // main: features + transposes + zero logits
    cvt_split_k<<<(4 * NB * 768 / 4 + 255) / 256, 256>>>(
        (const float4*)img, (const float4*)txt, (const float4*)eimg, (const float4*)etxt,
        featbf, lo1);
    {
        TJobs J;
        const float* srcs[9] = { imp_w1, disc_w1, disc_w2, cons_w1, cons_w2, diff_w1, diff_w2,
                                 info_w1, info_w2 };
        __nv_bfloat16* dsts[9] = { w_imp1, w_disc1, w_disc2, w_cons1, w_cons2, w_diff1, w_diff2,
                                   wi1h, wi2h };
        __nv_bfloat16* dls[9] = { nullptr, nullptr, nullptr, nullptr, nullptr, nullptr, nullptr,
                                  wi1l, wi2l };
        int Ks[9] = { 768, 768, 256, 1536, 768, 1536, 768, 768, 256 };
        int Ns[9] = { 384, 256, 64, 768, 384, 768, 384, 256, 64 };
        int tot = 0;
        for (int j = 0; j < 9; j++) {
            J.s[j] = srcs[j]; J.d[j] = dsts[j]; J.dl[j] = dls[j];
            J.K[j] = Ks[j]; J.N[j] = Ns[j];
            J.t0[j] = tot;
            tot += (Ks[j] / 32) * (Ns[j] / 32);
        }
        J.njobs = 9;
        dim3 b(32, 8);
        transpose_combo_k<<<tot, b>>>(J);
    }
    zero_k<<<(11 * NB / 4 + 255) / 256, 256>>>((float4*)logit, 11 * NB / 4);
    cudaEventRecord(eT, 0);
    cudaStreamWaitEvent(s1, eT, 0);
    cudaStreamWaitEvent(s2, eT, 0);

    // s1: information (rows 4,5) — bf16x3; L1 writes h2/l2 directly
    {
        APtrsB ah = {{ bimg, btxt, nullptr, nullptr }};
        APtrsB al = {{ lo1, lo1 + (size_t)NB * 768, nullptr, nullptr }};
        launch_bf3<128, true>(s1, ah, al, 2, 768, wi1h, wi1l, 256, info_b1, h2, l2, 1);
        APtrsB ah2 = {{ h2, h2 + (size_t)NB * 256, nullptr, nullptr }};
        APtrsB al2 = {{ l2, l2 + (size_t)NB * 256, nullptr, nullptr }};
        launch_bf3<64, false>(s1, ah2, al2, 2, 256, wi2h, wi2l, 64, info_b2, scrD2, nullptr, 0);
        info_final_k<<<(2 * NB) / 8, 256, 0, s1>>>(scrD2, out + 4 * NB);
        cudaEventRecord(e1, s1);
    }

    // main: merged imp1(head-fused)+disc1(bf16), disc2(head), diff chain(head)
    {
        APtrsB a = {{ bimg, btxt, beimg, betxt }};
        launch_bf2<128, 2, 1>(0, a, 4, 768, 768,
                              w_imp1, w_disc1, 384, 256, imp_b1, disc_b1,
                              logit_imp, scrCbf, imp_w2, nullptr, 1);
        sig_k<<<(4 * NB + 255) / 256, 256>>>(logit_imp, imp_b2, out + 8 * NB, 4 * NB);

        // disc2: batch order img,eimg,txt,etxt -> rows 12..15
        APtrsB ad2 = {{ scrCbf, scrCbf + (size_t)2 * NB * 256, scrCbf + (size_t)NB * 256,
                        scrCbf + (size_t)3 * NB * 256 }};
        launch_bf<64, 2>(0, ad2, 4, 256, 256, w_disc2, 64, disc_b2, logit_disc, disc_w3, 1);
        sig_k<<<(4 * NB + 255) / 256, 256>>>(logit_disc, disc_b3, out + 12 * NB, 4 * NB);

        APtrsB af = {{ beimg, betxt, nullptr, nullptr }};
        launch_bf<128, 1>(0, af, 1, 768, 1536, w_diff1, 768, diff_b1, scrAbf3, nullptr, 1);
        APtrsB af2 = {{ scrAbf3, nullptr, nullptr, nullptr }};
        launch_bf<128, 2>(0, af2, 1, 768, 768, w_diff2, 384, diff_b2, logit_diff, diff_w3, 1);
        sig_k<<<(NB + 255) / 256, 256>>>(logit_diff, diff_b3, out + 16 * NB, NB);
    }

    // s2: consistency (rows 6,7), head-fused layer 2
    {
        APtrsB a = {{ bimg, btxt, beimg, betxt }};
        launch_bf<128, 1>(s2, a, 2, 768, 1536, w_cons1, 768, cons_b1, scrAbf, nullptr, 1);
        APtrsB a2 = {{ scrAbf, scrAbf + (size_t)NB * 768, nullptr, nullptr }};
        launch_bf<128, 2>(s2, a2, 2, 768, 768, w_cons2, 384, cons_b2, logit_cons, cons_w3, 1);
        sig_k<<<(2 * NB + 255) / 256, 256, 0, s2>>>(logit_cons, cons_b3, out + 6 * NB, 2 * NB);
        cudaEventRecord(e2, s2);
    }

    // join + overall
    cudaStreamWaitEvent(0, e1, 0);
    cudaStreamWaitEvent(0, e2, 0);
    overall_k<<<NB / 256, 256>>>(out);
}

// round 13
// speedup vs baseline: 1.4965x; 1.0287x over previous
#include <cuda_runtime.h>
#include <cuda_bf16.h>
#include <cstdint>

#define NB 16384
#define HD 768

// ---------------- scratch ----------------
__device__ __nv_bfloat16 g_featbf[4 * NB * 768];
__device__ __nv_bfloat16 g_lo1[2 * NB * 768];
__device__ __nv_bfloat16 g_h2[2 * NB * 256];
__device__ __nv_bfloat16 g_l2[2 * NB * 256];
__device__ __nv_bfloat16 g_scrAbf[2 * NB * 768];     // cons1 (bf16) [s2]
__device__ __nv_bfloat16 g_scrAbf3[NB * 768];        // diff1 (bf16) [main]
__device__ __nv_bfloat16 g_scrCbf[4 * NB * 256];     // disc1 (bf16) [main]
__device__ float g_scrD2[2 * NB * 64];               // info2 (fp32) [s1]
__device__ float g_logit[11 * NB];                   // imp 4NB | disc 4NB | cons 2NB | diff NB
__device__ float g_norm[2 * NB];
__device__ __nv_bfloat16 g_w_imp1[384 * 768];
__device__ __nv_bfloat16 g_w_disc1[256 * 768];
__device__ __nv_bfloat16 g_w_disc2[64 * 256];
__device__ __nv_bfloat16 g_w_cons1[768 * 1536];
__device__ __nv_bfloat16 g_w_cons2[384 * 768];
__device__ __nv_bfloat16 g_w_diff1[768 * 1536];
__device__ __nv_bfloat16 g_w_diff2[384 * 768];
__device__ __nv_bfloat16 g_wi1h[256 * 768], g_wi1l[256 * 768];
__device__ __nv_bfloat16 g_wi2h[64 * 256],  g_wi2l[64 * 256];

__device__ __forceinline__ float sigf(float x) { return 1.0f / (1.0f + expf(-x)); }
__device__ __forceinline__ float geluf(float x) { return 0.5f * x * (1.0f + erff(x * 0.70710678118654752f)); }

__device__ __forceinline__ uint32_t smem_u32(const void* p) {
    uint32_t a;
    asm("{ .reg .u64 t; cvta.to.shared.u64 t, %1; cvt.u32.u64 %0, t; }" : "=r"(a) : "l"(p));
    return a;
}
__device__ __forceinline__ void mma_bf(float* d, const uint32_t* a, uint32_t b0, uint32_t b1) {
    asm volatile(
        "mma.sync.aligned.m16n8k16.row.col.f32.bf16.bf16.f32 "
        "{%0,%1,%2,%3}, {%4,%5,%6,%7}, {%8,%9}, {%0,%1,%2,%3};"
        : "+f"(d[0]), "+f"(d[1]), "+f"(d[2]), "+f"(d[3])
        : "r"(a[0]), "r"(a[1]), "r"(a[2]), "r"(a[3]), "r"(b0), "r"(b1));
}
#define LDSM4(r, addr) \
    asm volatile("ldmatrix.sync.aligned.m8n8.x4.shared.b16 {%0,%1,%2,%3}, [%4];" \
        : "=r"((r)[0]), "=r"((r)[1]), "=r"((r)[2]), "=r"((r)[3]) : "r"(addr))
#define CP_ASYNC16(dst, src) \
    asm volatile("cp.async.cg.shared.global [%0], [%1], 16;" :: "r"(dst), "l"(src))
#define CP_COMMIT() asm volatile("cp.async.commit_group;" ::: "memory")

struct APtrsB { const __nv_bfloat16* p[4]; };

// ================= bf16 GEMM: BM=128, BK=64, 3-stage, occ 2, two-region =================
// Per-region epilogue mode: 0 = fp32 store, 1 = bf16 store, 2 = head-fused.
template<int BN, int M0, int M1>
__global__ void __launch_bounds__(256, 2) gemm_bf16(
    APtrsB A, int Khalf, int Ktot,
    const __nv_bfloat16* __restrict__ Wt0, const __nv_bfloat16* __restrict__ Wt1,
    int N0, int N1, const float* __restrict__ b0, const float* __restrict__ b1,
    void* __restrict__ C0v, void* __restrict__ C1v,
    const float* __restrict__ w0, const float* __restrict__ w1, int act)
{
    constexpr int AW = 72;
    constexpr int ABYTES = 128 * AW * 2;
    constexpr int BBYTES = BN * AW * 2;
    constexpr int STG = ABYTES + BBYTES;
    constexpr int NT = BN / 16;

    extern __shared__ char smem[];
    const int t = threadIdx.x, lane = t & 31, wid = t >> 5;
    const int batch = blockIdx.y >> 7;
    const int m0 = (blockIdx.y & 127) * 128;
    const int n0g = blockIdx.x * BN;
    const int wm = (wid & 3) * 32;
    const int wn = (wid >> 2) * (BN / 2);

    const bool r1 = (n0g >= N0);
    const __nv_bfloat16* Wt = r1 ? Wt1 : Wt0;
    const float* bias = r1 ? b1 : b0;
    const int N = r1 ? N1 : N0;
    const int n0 = n0g - (r1 ? N0 : 0);

    const __nv_bfloat16 *A1, *A2;
    if (Khalf < Ktot) { A1 = A.p[2 * batch]; A2 = A.p[2 * batch + 1]; }
    else              { A1 = A.p[batch];     A2 = A1; }

    const uint32_t sbase = smem_u32(smem);
    const uint32_t a_addr0 = sbase + (uint32_t)((wm + (lane & 15)) * (AW * 2) + (lane >> 4) * 16);
    const int grp = lane >> 3;
    const int b_r = (lane & 7) + ((grp >= 2) ? 8 : 0);
    const uint32_t b_addr0 = sbase + ABYTES + (uint32_t)((wn + b_r) * (AW * 2) + (grp & 1) * 16);

    float acc[2][NT][4];
#pragma unroll
    for (int i = 0; i < 2; i++)
#pragma unroll
        for (int j = 0; j < NT; j++)
#pragma unroll
            for (int q = 0; q < 4; q++) acc[i][j][q] = 0.0f;

    auto load_chunk = [&](int c) {
        const int stg = c % 3;
        int kk = c * 64;
        const __nv_bfloat16* Ab = A1;
        if (kk >= Khalf) { Ab = A2; kk -= Khalf; }
        uint32_t sA = sbase + stg * STG;
#pragma unroll
        for (int i = 0; i < 4; i++) {
            int idx = t + i * 256, r = idx >> 3, c8 = idx & 7;
            CP_ASYNC16(sA + (uint32_t)(r * (AW * 2) + c8 * 16),
                       Ab + (size_t)(m0 + r) * Khalf + kk + c8 * 8);
        }
        uint32_t sB = sA + ABYTES;
#pragma unroll
        for (int i = 0; i < BN / 32; i++) {
            int idx = t + i * 256, r = idx >> 3, c8 = idx & 7;
            CP_ASYNC16(sB + (uint32_t)(r * (AW * 2) + c8 * 16),
                       Wt + (size_t)(n0 + r) * Ktot + c * 64 + c8 * 8);
        }
        CP_COMMIT();
    };

    const int NC = Ktot >> 6;
    load_chunk(0);
    if (NC > 1) load_chunk(1);

    for (int c = 0; c < NC; c++) {
        if (c + 1 < NC) { asm volatile("cp.async.wait_group 1;" ::: "memory"); }
        else            { asm volatile("cp.async.wait_group 0;" ::: "memory"); }
        __syncthreads();
        if (c + 2 < NC) load_chunk(c + 2);

        const uint32_t aa = a_addr0 + (c % 3) * STG;
        const uint32_t bb = b_addr0 + (c % 3) * STG;
#pragma unroll
        for (int kk = 0; kk < 4; kk++) {
            uint32_t Af[2][4];
            LDSM4(Af[0], aa + kk * 32);
            LDSM4(Af[1], aa + 16 * (AW * 2) + kk * 32);
#pragma unroll
            for (int np = 0; np < NT / 2; np++) {
                uint32_t B4[4];
                LDSM4(B4, bb + np * 16 * (AW * 2) + kk * 32);
#pragma unroll
                for (int mt = 0; mt < 2; mt++) {
                    mma_bf(acc[mt][2 * np],     Af[mt], B4[0], B4[1]);
                    mma_bf(acc[mt][2 * np + 1], Af[mt], B4[2], B4[3]);
                }
            }
        }
    }

    const int mode = r1 ? M1 : M0;
    const float* wv = r1 ? w1 : w0;
    void* Cv = r1 ? C1v : C0v;
#pragma unroll
    for (int mt = 0; mt < 2; mt++) {
        int row = batch * NB + m0 + wm + mt * 16 + (lane >> 2);
        float p0 = 0.f, p1 = 0.f;
#pragma unroll
        for (int nt = 0; nt < NT; nt++) {
            int col = n0 + wn + nt * 8 + (lane & 3) * 2;
            float bv0 = __ldg(bias + col), bv1 = __ldg(bias + col + 1);
            float x0 = acc[mt][nt][0] + bv0, x1 = acc[mt][nt][1] + bv1;
            float x2 = acc[mt][nt][2] + bv0, x3 = acc[mt][nt][3] + bv1;
            if (act) { x0 = geluf(x0); x1 = geluf(x1); x2 = geluf(x2); x3 = geluf(x3); }
            if (mode == 2) {
                float wv0 = __ldg(wv + col), wv1 = __ldg(wv + col + 1);
                p0 += x0 * wv0 + x1 * wv1;
                p1 += x2 * wv0 + x3 * wv1;
            } else if (mode == 1) {
                __nv_bfloat16* C = (__nv_bfloat16*)Cv;
                *reinterpret_cast<__nv_bfloat162*>(C + (size_t)row * N + col) =
                    __floats2bfloat162_rn(x0, x1);
                *reinterpret_cast<__nv_bfloat162*>(C + (size_t)(row + 8) * N + col) =
                    __floats2bfloat162_rn(x2, x3);
            } else {
                float* C = (float*)Cv;
                *reinterpret_cast<float2*>(C + (size_t)row * N + col)       = make_float2(x0, x1);
                *reinterpret_cast<float2*>(C + (size_t)(row + 8) * N + col) = make_float2(x2, x3);
            }
        }
        if (mode == 2) {
            p0 += __shfl_xor_sync(0xffffffffu, p0, 1);
            p0 += __shfl_xor_sync(0xffffffffu, p0, 2);
            p1 += __shfl_xor_sync(0xffffffffu, p1, 1);
            p1 += __shfl_xor_sync(0xffffffffu, p1, 2);
            if ((lane & 3) == 0) {
                float* L = (float*)Cv;
                atomicAdd(&L[row], p0);
                atomicAdd(&L[row + 8], p1);
            }
        }
    }
}

// ================= bf16x3 precise GEMM (info path); OUTSPLIT writes bf16 hi/lo =================
template<int BN, bool OUTSPLIT>
__global__ void __launch_bounds__(256, 2) gemm_bf3(
    APtrsB Ah, APtrsB Al, int Ktot,
    const __nv_bfloat16* __restrict__ Wh, const __nv_bfloat16* __restrict__ Wl, int N,
    const float* __restrict__ bias, void* __restrict__ Cv, void* __restrict__ Clv, int act)
{
    constexpr int AW = 40;
    constexpr int ABYTES = 128 * AW * 2;
    constexpr int BBYTES = BN * AW * 2;
    constexpr int STG = 2 * ABYTES + 2 * BBYTES;
    constexpr int NT = BN / 16;

    extern __shared__ char smem[];
    const int t = threadIdx.x, lane = t & 31, wid = t >> 5;
    const int batch = blockIdx.y >> 7;
    const int m0 = (blockIdx.y & 127) * 128;
    const int n0 = blockIdx.x * BN;
    const int wm = (wid & 3) * 32;
    const int wn = (wid >> 2) * (BN / 2);

    const __nv_bfloat16* A1h = Ah.p[batch];
    const __nv_bfloat16* A1l = Al.p[batch];

    const uint32_t sbase = smem_u32(smem);
    const uint32_t a_addr0 = sbase + (uint32_t)((wm + (lane & 15)) * AW * 2 + (lane >> 4) * 16);
    const int grp = lane >> 3;
    const int b_r = (lane & 7) + ((grp >= 2) ? 8 : 0);
    const uint32_t b_addr0 = sbase + 2 * ABYTES + (uint32_t)((wn + b_r) * AW * 2 + (grp & 1) * 16);

    float acc[2][NT][4];
#pragma unroll
    for (int i = 0; i < 2; i++)
#pragma unroll
        for (int j = 0; j < NT; j++)
#pragma unroll
            for (int q = 0; q < 4; q++) acc[i][j][q] = 0.0f;

    auto load_chunk = [&](int c) {
        const int stg = c & 1;
        const int kk = c * 32;
        uint32_t base = sbase + stg * STG;
#pragma unroll
        for (int i = 0; i < 2; i++) {
            int idx = t + i * 256, r = idx >> 2, c8 = idx & 3;
            uint32_t off = (uint32_t)(r * AW * 2 + c8 * 16);
            size_t go = (size_t)(m0 + r) * Ktot + kk + c8 * 8;
            CP_ASYNC16(base + off,           A1h + go);
            CP_ASYNC16(base + ABYTES + off,  A1l + go);
        }
        uint32_t sB = base + 2 * ABYTES;
#pragma unroll
        for (int i = 0; i < BN / 64; i++) {
            int idx = t + i * 256, r = idx >> 2, c8 = idx & 3;
            uint32_t off = (uint32_t)(r * AW * 2 + c8 * 16);
            size_t go = (size_t)(n0 + r) * Ktot + kk + c8 * 8;
            CP_ASYNC16(sB + off,           Wh + go);
            CP_ASYNC16(sB + BBYTES + off,  Wl + go);
        }
        CP_COMMIT();
    };

    const int NC = Ktot >> 5;
    load_chunk(0);
    if (NC > 1) load_chunk(1);

    for (int c = 0; c < NC; c++) {
        if (c + 1 < NC) { asm volatile("cp.async.wait_group 1;" ::: "memory"); }
        else            { asm volatile("cp.async.wait_group 0;" ::: "memory"); }
        __syncthreads();

        const uint32_t aa = a_addr0 + (c & 1) * STG;
        const uint32_t bb = b_addr0 + (c & 1) * STG;
#pragma unroll
        for (int kk = 0; kk < 2; kk++) {
            uint32_t Ahf[2][4], Alf[2][4];
            LDSM4(Ahf[0], aa + kk * 32);
            LDSM4(Ahf[1], aa + 16 * AW * 2 + kk * 32);
            LDSM4(Alf[0], aa + ABYTES + kk * 32);
            LDSM4(Alf[1], aa + ABYTES + 16 * AW * 2 + kk * 32);
#pragma unroll
            for (int np = 0; np < NT / 2; np++) {
                uint32_t Bh4[4], Bl4[4];
                LDSM4(Bh4, bb + np * 16 * AW * 2 + kk * 32);
                LDSM4(Bl4, bb + BBYTES + np * 16 * AW * 2 + kk * 32);
#pragma unroll
                for (int mt = 0; mt < 2; mt++) {
                    mma_bf(acc[mt][2 * np],     Ahf[mt], Bh4[0], Bh4[1]);
                    mma_bf(acc[mt][2 * np],     Ahf[mt], Bl4[0], Bl4[1]);
                    mma_bf(acc[mt][2 * np],     Alf[mt], Bh4[0], Bh4[1]);
                    mma_bf(acc[mt][2 * np + 1], Ahf[mt], Bh4[2], Bh4[3]);
                    mma_bf(acc[mt][2 * np + 1], Ahf[mt], Bl4[2], Bl4[3]);
                    mma_bf(acc[mt][2 * np + 1], Alf[mt], Bh4[2], Bh4[3]);
                }
            }
        }
        __syncthreads();
        if (c + 2 < NC) load_chunk(c + 2);
    }

#pragma unroll
    for (int mt = 0; mt < 2; mt++) {
        int row = batch * NB + m0 + wm + mt * 16 + (lane >> 2);
#pragma unroll
        for (int nt = 0; nt < NT; nt++) {
            int col = n0 + wn + nt * 8 + (lane & 3) * 2;
            float bv0 = bias[col], bv1 = bias[col + 1];
            float x0 = acc[mt][nt][0] + bv0, x1 = acc[mt][nt][1] + bv1;
            float x2 = acc[mt][nt][2] + bv0, x3 = acc[mt][nt][3] + bv1;
            if (act) { x0 = geluf(x0); x1 = geluf(x1); x2 = geluf(x2); x3 = geluf(x3); }
            if (OUTSPLIT) {
                __nv_bfloat16* Ch = (__nv_bfloat16*)Cv;
                __nv_bfloat16* Cl = (__nv_bfloat16*)Clv;
                __nv_bfloat162 h0 = __floats2bfloat162_rn(x0, x1);
                __nv_bfloat162 h1 = __floats2bfloat162_rn(x2, x3);
                *reinterpret_cast<__nv_bfloat162*>(Ch + (size_t)row * N + col) = h0;
                *reinterpret_cast<__nv_bfloat162*>(Ch + (size_t)(row + 8) * N + col) = h1;
                *reinterpret_cast<__nv_bfloat162*>(Cl + (size_t)row * N + col) =
                    __floats2bfloat162_rn(x0 - __bfloat162float(h0.x), x1 - __bfloat162float(h0.y));
                *reinterpret_cast<__nv_bfloat162*>(Cl + (size_t)(row + 8) * N + col) =
                    __floats2bfloat162_rn(x2 - __bfloat162float(h1.x), x3 - __bfloat162float(h1.y));
            } else {
                float* C = (float*)Cv;
                *reinterpret_cast<float2*>(C + (size_t)row * N + col)       = make_float2(x0, x1);
                *reinterpret_cast<float2*>(C + (size_t)(row + 8) * N + col) = make_float2(x2, x3);
            }
        }
    }
}

// ---------- fused: rowstats (rows 0..3 + norms) AND fp32->bf16 hi(/lo) conversion ----------
// One warp per (feat, row): single pass over the 192MB of inputs.
__global__ void fused_stats_cvt_k(
    const float* __restrict__ f0, const float* __restrict__ f1,
    const float* __restrict__ f2, const float* __restrict__ f3,
    __nv_bfloat16* __restrict__ hi, __nv_bfloat16* __restrict__ lo,
    float* __restrict__ out)
{
    int gw = (blockIdx.x * blockDim.x + threadIdx.x) >> 5;
    int lane = threadIdx.x & 31;
    if (gw >= 4 * NB) return;
    int feat = gw >> 14;
    int m = gw & (NB - 1);
    const float* f = (feat == 0 ? f0 : feat == 1 ? f1 : feat == 2 ? f2 : f3) + (size_t)m * HD;
    __nv_bfloat16* hrow = hi + ((size_t)feat * NB + m) * HD;
    __nv_bfloat16* lrow = lo + ((size_t)feat * NB + m) * HD;   // valid only feat<2

    double sum = 0.0, ssq = 0.0;
    int cnt = 0;
    for (int k = lane * 4; k < HD; k += 128) {
        float4 v = *reinterpret_cast<const float4*>(f + k);
        sum += (double)v.x + v.y + v.z + v.w;
        ssq += (double)v.x * v.x + (double)v.y * v.y + (double)v.z * v.z + (double)v.w * v.w;
        cnt += (fabsf(v.x) > 0.01f) + (fabsf(v.y) > 0.01f) + (fabsf(v.z) > 0.01f) + (fabsf(v.w) > 0.01f);
        __nv_bfloat162 h0 = __floats2bfloat162_rn(v.x, v.y);
        __nv_bfloat162 h1 = __floats2bfloat162_rn(v.z, v.w);
        reinterpret_cast<__nv_bfloat162*>(hrow + k)[0] = h0;
        reinterpret_cast<__nv_bfloat162*>(hrow + k)[1] = h1;
        if (feat < 2) {
            reinterpret_cast<__nv_bfloat162*>(lrow + k)[0] =
                __floats2bfloat162_rn(v.x - __bfloat162float(h0.x), v.y - __bfloat162float(h0.y));
            reinterpret_cast<__nv_bfloat162*>(lrow + k)[1] =
                __floats2bfloat162_rn(v.z - __bfloat162float(h1.x), v.w - __bfloat162float(h1.y));
        }
    }
#pragma unroll
    for (int o = 16; o; o >>= 1) {
        sum += __shfl_xor_sync(0xffffffffu, sum, o);
        ssq += __shfl_xor_sync(0xffffffffu, ssq, o);
        cnt += __shfl_xor_sync(0xffffffffu, cnt, o);
    }
    if (lane == 0) {
        float n = (float)sqrt(ssq);
        float nq = sigf((n - 1.0f) * 2.0f);
        float sp = cnt * (1.0f / 768.0f);
        double var = (ssq - sum * sum / 768.0) / 767.0;
        if (var < 0.0) var = 0.0;
        float sq = sigf((float)sqrt(var) * 10.0f - 1.0f);
        out[feat * NB + m] = (nq + sp + sq) * (1.0f / 3.0f);
        if (feat < 2) g_norm[feat * NB + m] = n;
    }
}

// ---------------- zero logits ----------------
__global__ void zero_k(float4* __restrict__ p, int n4) {
    int i = blockIdx.x * blockDim.x + threadIdx.x;
    if (i < n4) p[i] = make_float4(0.f, 0.f, 0.f, 0.f);
}

// ---------------- one sigmoid finisher for all heads ----------------
// logits: [imp 4NB][disc 4NB][cons 2NB][diff NB] -> out rows 8..11, 12..15, 6..7, 16
__global__ void sig_all_k(const float* __restrict__ L,
                          const float* __restrict__ b_imp, const float* __restrict__ b_disc,
                          const float* __restrict__ b_cons, const float* __restrict__ b_diff,
                          float* __restrict__ out)
{
    int i = blockIdx.x * blockDim.x + threadIdx.x;
    if (i >= 11 * NB) return;
    float b;
    int o;
    if (i < 4 * NB)        { b = b_imp[0];  o = 8 * NB + i; }
    else if (i < 8 * NB)   { b = b_disc[0]; o = 12 * NB + (i - 4 * NB); }
    else if (i < 10 * NB)  { b = b_cons[0]; o = 6 * NB + (i - 8 * NB); }
    else                   { b = b_diff[0]; o = 16 * NB + (i - 10 * NB); }
    out[o] = sigf(L[i] + b);
}

// ---------------- combined transpose: 9 jobs (7 plain bf16 + 2 hi/lo split) ----------------
struct TJobs {
    const float* s[9];
    __nv_bfloat16* d[9];
    __nv_bfloat16* dl[9];
    int K[9], N[9], t0[9];
    int njobs;
};
__global__ void transpose_combo_k(TJobs J) {
    __shared__ float tile[32][33];
    int bx = blockIdx.x;
    int j = 0;
#pragma unroll
    for (int q = 1; q < 9; q++) if (q < J.njobs && bx >= J.t0[q]) j = q;
    int local = bx - J.t0[j];
    int tilesx = J.N[j] / 32;
    int txb = local % tilesx, tyb = local / tilesx;
    const float* s = J.s[j];
    int K = J.K[j], N = J.N[j];
    int n = txb * 32 + threadIdx.x;
    int k = tyb * 32 + threadIdx.y;
#pragma unroll
    for (int i = 0; i < 32; i += 8) tile[threadIdx.y + i][threadIdx.x] = s[(size_t)(k + i) * N + n];
    __syncthreads();
    int n2 = txb * 32 + threadIdx.y;
    int k2 = tyb * 32 + threadIdx.x;
    __nv_bfloat16* d = J.d[j];
    __nv_bfloat16* dl = J.dl[j];
    if (dl == nullptr) {
#pragma unroll
        for (int i = 0; i < 32; i += 8)
            d[(size_t)(n2 + i) * K + k2] = __float2bfloat16(tile[threadIdx.x][threadIdx.y + i]);
    } else {
#pragma unroll
        for (int i = 0; i < 32; i += 8) {
            float v = tile[threadIdx.x][threadIdx.y + i];
            __nv_bfloat16 h = __float2bfloat16(v);
            d[(size_t)(n2 + i) * K + k2] = h;
            dl[(size_t)(n2 + i) * K + k2] = __float2bfloat16(v - __bfloat162float(h));
        }
    }
}

// ---------------- info final (2*NB rows) ----------------
__global__ void info_final_k(const float* __restrict__ enc, float* __restrict__ outrow)
{
    int gw = (blockIdx.x * blockDim.x + threadIdx.x) >> 5;
    int lane = threadIdx.x & 31;
    if (gw >= 2 * NB) return;
    const float* e = enc + (size_t)gw * 64;
    float x0 = e[lane], x1 = e[lane + 32];
    int d0 = (int)rintf(sigf(x0) * 10.0f);
    int d1 = (int)rintf(sigf(x1) * 10.0f);
    float ent = 0.f;
#pragma unroll
    for (int b = 0; b < 11; b++) {
        int c = __popc(__ballot_sync(0xffffffffu, d0 == b)) +
                __popc(__ballot_sync(0xffffffffu, d1 == b));
        if (c > 0) {
            float p = c * (1.0f / 64.0f);
            ent -= p * logf(p + 1e-8f);
        }
    }
    if (lane == 0) {
        float eq = sigf(ent - 2.0f);
        float n = g_norm[gw];
        float cq = (n > 0.01f) ? (1.0f / 768.0f) : 0.0f;
        float t = n / fmaxf(n, 1e-12f);
        float dq = sigf(t * t - 0.5f);
        outrow[gw] = (eq + cq + dq) * (1.0f / 3.0f);
    }
}

__global__ void overall_k(float* __restrict__ out)
{
    int i = blockIdx.x * blockDim.x + threadIdx.x;
    if (i >= NB) return;
    float v = out[0 * NB + i] + out[1 * NB + i] + out[4 * NB + i] + out[5 * NB + i] +
              out[7 * NB + i] + 0.5f * (out[8 * NB + i] + out[9 * NB + i]);
    out[17 * NB + i] = v * (1.0f / 6.0f);
}

// ---------------- host ----------------
template<int BN, int M0, int M1>
static void launch_bf2(cudaStream_t st, APtrsB A, int nb, int Khalf, int Ktot,
                       const __nv_bfloat16* Wt0, const __nv_bfloat16* Wt1,
                       int N0, int N1, const float* b0, const float* b1,
                       void* C0, void* C1, const float* w0, const float* w1, int act)
{
    int smemB = 3 * (128 + BN) * 72 * 2;
    cudaFuncSetAttribute(gemm_bf16<BN, M0, M1>,
                         cudaFuncAttributeMaxDynamicSharedMemorySize, smemB);
    dim3 g((N0 + N1) / BN, nb * 128);
    gemm_bf16<BN, M0, M1><<<g, 256, smemB, st>>>(
        A, Khalf, Ktot, Wt0, Wt1, N0, N1, b0, b1, C0, C1, w0, w1, act);
}
template<int BN, int M>
static void launch_bf(cudaStream_t st, APtrsB A, int nb, int Khalf, int Ktot,
                      const __nv_bfloat16* Wt, int N, const float* bias, void* C,
                      const float* w, int act)
{
    launch_bf2<BN, M, M>(st, A, nb, Khalf, Ktot, Wt, nullptr, N, 0, bias, nullptr,
                         C, nullptr, w, nullptr, act);
}
template<int BN, bool OUTSPLIT>
static void launch_bf3(cudaStream_t st, APtrsB Ah, APtrsB Al, int nb, int Ktot,
                       const __nv_bfloat16* Wh, const __nv_bfloat16* Wl, int N,
                       const float* bias, void* C, void* Cl, int act)
{
    int smemB = 2 * (2 * 128 * 40 * 2 + 2 * BN * 40 * 2);
    cudaFuncSetAttribute(gemm_bf3<BN, OUTSPLIT>, cudaFuncAttributeMaxDynamicSharedMemorySize, smemB);
    dim3 g(N / BN, nb * 128);
    gemm_bf3<BN, OUTSPLIT><<<g, 256, smemB, st>>>(Ah, Al, Ktot, Wh, Wl, N, bias, C, Cl, act);
}

extern "C" void kernel_launch(void* const* d_in, const int* in_sizes, int n_in,
                              void* d_out, int out_size)
{
    const float* img  = (const float*)d_in[0];
    const float* txt  = (const float*)d_in[1];
    const float* eimg = (const float*)d_in[2];
    const float* etxt = (const float*)d_in[3];
    const float* info_w1 = (const float*)d_in[5];
    const float* info_b1 = (const float*)d_in[6];
    const float* info_w2 = (const float*)d_in[7];
    const float* info_b2 = (const float*)d_in[8];
    const float* imp_w1  = (const float*)d_in[9];
    const float* imp_b1  = (const float*)d_in[10];
    const float* imp_w2  = (const float*)d_in[11];
    const float* imp_b2  = (const float*)d_in[12];
    const float* disc_w1 = (const float*)d_in[13];
    const float* disc_b1 = (const float*)d_in[14];
    const float* disc_w2 = (const float*)d_in[15];
    const float* disc_b2 = (const float*)d_in[16];
    const float* disc_w3 = (const float*)d_in[17];
    const float* disc_b3 = (const float*)d_in[18];
    const float* cons_w1 = (const float*)d_in[19];
    const float* cons_b1 = (const float*)d_in[20];
    const float* cons_w2 = (const float*)d_in[21];
    const float* cons_b2 = (const float*)d_in[22];
    const float* cons_w3 = (const float*)d_in[23];
    const float* cons_b3 = (const float*)d_in[24];
    const float* diff_w1 = (const float*)d_in[25];
    const float* diff_b1 = (const float*)d_in[26];
    const float* diff_w2 = (const float*)d_in[27];
    const float* diff_b2 = (const float*)d_in[28];
    const float* diff_w3 = (const float*)d_in[29];
    const float* diff_b3 = (const float*)d_in[30];

    float* out = (float*)d_out;

    __nv_bfloat16 *featbf, *lo1, *h2, *l2, *scrAbf, *scrAbf3, *scrCbf;
    __nv_bfloat16 *w_imp1, *w_disc1, *w_disc2, *w_cons1, *w_cons2, *w_diff1, *w_diff2;
    __nv_bfloat16 *wi1h, *wi1l, *wi2h, *wi2l;
    float *scrD2, *logit;
    cudaGetSymbolAddress((void**)&featbf, g_featbf);
    cudaGetSymbolAddress((void**)&lo1, g_lo1);
    cudaGetSymbolAddress((void**)&h2, g_h2);
    cudaGetSymbolAddress((void**)&l2, g_l2);
    cudaGetSymbolAddress((void**)&scrAbf, g_scrAbf);
    cudaGetSymbolAddress((void**)&scrAbf3, g_scrAbf3);
    cudaGetSymbolAddress((void**)&scrCbf, g_scrCbf);
    cudaGetSymbolAddress((void**)&scrD2, g_scrD2);
    cudaGetSymbolAddress((void**)&logit, g_logit);
    cudaGetSymbolAddress((void**)&w_imp1, g_w_imp1);
    cudaGetSymbolAddress((void**)&w_disc1, g_w_disc1);
    cudaGetSymbolAddress((void**)&w_disc2, g_w_disc2);
    cudaGetSymbolAddress((void**)&w_cons1, g_w_cons1);
    cudaGetSymbolAddress((void**)&w_cons2, g_w_cons2);
    cudaGetSymbolAddress((void**)&w_diff1, g_w_diff1);
    cudaGetSymbolAddress((void**)&w_diff2, g_w_diff2);
    cudaGetSymbolAddress((void**)&wi1h, g_wi1h);
    cudaGetSymbolAddress((void**)&wi1l, g_wi1l);
    cudaGetSymbolAddress((void**)&wi2h, g_wi2h);
    cudaGetSymbolAddress((void**)&wi2l, g_wi2l);

    float* logit_imp  = logit;
    float* logit_disc = logit + 4 * NB;
    float* logit_cons = logit + 8 * NB;
    float* logit_diff = logit + 10 * NB;

    const __nv_bfloat16* bimg  = featbf;
    const __nv_bfloat16* btxt  = featbf + (size_t)NB * 768;
    const __nv_bfloat16* beimg = featbf + (size_t)2 * NB * 768;
    const __nv_bfloat16* betxt = featbf + (size_t)3 * NB * 768;

    static cudaStream_t s1 = nullptr, s2 = nullptr;
    static cudaEvent_t e0 = nullptr, eF = nullptr, eW = nullptr, e1 = nullptr, e2 = nullptr;
    if (!s1) {
        cudaStreamCreateWithFlags(&s1, cudaStreamNonBlocking);
        cudaStreamCreateWithFlags(&s2, cudaStreamNonBlocking);
        cudaEventCreateWithFlags(&e0, cudaEventDisableTiming);
        cudaEventCreateWithFlags(&eF, cudaEventDisableTiming);
        cudaEventCreateWithFlags(&eW, cudaEventDisableTiming);
        cudaEventCreateWithFlags(&e1, cudaEventDisableTiming);
        cudaEventCreateWithFlags(&e2, cudaEventDisableTiming);
    }

    // fork
    cudaEventRecord(e0, 0);
    cudaStreamWaitEvent(s1, e0, 0);
    cudaStreamWaitEvent(s2, e0, 0);

    // s2: weight transposes + logit zero (weights only, independent of features)
    {
        TJobs J;
        const float* srcs[9] = { imp_w1, disc_w1, disc_w2, cons_w1, cons_w2, diff_w1, diff_w2,
                                 info_w1, info_w2 };
        __nv_bfloat16* dsts[9] = { w_imp1, w_disc1, w_disc2, w_cons1, w_cons2, w_diff1, w_diff2,
                                   wi1h, wi2h };
        __nv_bfloat16* dls[9] = { nullptr, nullptr, nullptr, nullptr, nullptr, nullptr, nullptr,
                                  wi1l, wi2l };
        int Ks[9] = { 768, 768, 256, 1536, 768, 1536, 768, 768, 256 };
        int Ns[9] = { 384, 256, 64, 768, 384, 768, 384, 256, 64 };
        int tot = 0;
        for (int j = 0; j < 9; j++) {
            J.s[j] = srcs[j]; J.d[j] = dsts[j]; J.dl[j] = dls[j];
            J.K[j] = Ks[j]; J.N[j] = Ns[j];
            J.t0[j] = tot;
            tot += (Ks[j] / 32) * (Ns[j] / 32);
        }
        J.njobs = 9;
        dim3 b(32, 8);
        transpose_combo_k<<<tot, b, 0, s2>>>(J);
        zero_k<<<(11 * NB / 4 + 255) / 256, 256, 0, s2>>>((float4*)logit, 11 * NB / 4);
        cudaEventRecord(eW, s2);
    }

    // main: fused input pass (stats rows 0..3 + norms + bf16 hi/lo)
    fused_stats_cvt_k<<<(4 * NB) / 8, 256>>>(img, txt, eimg, etxt, featbf, lo1, out);
    cudaEventRecord(eF, 0);

    // gating: main GEMMs need eW; s1 needs eF(+in-stream via wait) and eW; s2 needs eF.
    cudaStreamWaitEvent(0, eW, 0);
    cudaStreamWaitEvent(s1, eF, 0);
    cudaStreamWaitEvent(s1, eW, 0);
    cudaStreamWaitEvent(s2, eF, 0);

    // s1: information (rows 4,5) — bf16x3
    {
        APtrsB ah = {{ bimg, btxt, nullptr, nullptr }};
        APtrsB al = {{ lo1, lo1 + (size_t)NB * 768, nullptr, nullptr }};
        launch_bf3<128, true>(s1, ah, al, 2, 768, wi1h, wi1l, 256, info_b1, h2, l2, 1);
        APtrsB ah2 = {{ h2, h2 + (size_t)NB * 256, nullptr, nullptr }};
        APtrsB al2 = {{ l2, l2 + (size_t)NB * 256, nullptr, nullptr }};
        launch_bf3<64, false>(s1, ah2, al2, 2, 256, wi2h, wi2l, 64, info_b2, scrD2, nullptr, 0);
        info_final_k<<<(2 * NB) / 8, 256, 0, s1>>>(scrD2, out + 4 * NB);
        cudaEventRecord(e1, s1);
    }

    // main: merged imp1(head)+disc1(bf16), disc2(head), diff chain(head)
    {
        APtrsB a = {{ bimg, btxt, beimg, betxt }};
        launch_bf2<128, 2, 1>(0, a, 4, 768, 768,
                              w_imp1, w_disc1, 384, 256, imp_b1, disc_b1,
                              logit_imp, scrCbf, imp_w2, nullptr, 1);
        // disc2: batch order img,eimg,txt,etxt -> rows 12..15
        APtrsB ad2 = {{ scrCbf, scrCbf + (size_t)2 * NB * 256, scrCbf + (size_t)NB * 256,
                        scrCbf + (size_t)3 * NB * 256 }};
        launch_bf<64, 2>(0, ad2, 4, 256, 256, w_disc2, 64, disc_b2, logit_disc, disc_w3, 1);

        APtrsB af = {{ beimg, betxt, nullptr, nullptr }};
        launch_bf<128, 1>(0, af, 1, 768, 1536, w_diff1, 768, diff_b1, scrAbf3, nullptr, 1);
        APtrsB af2 = {{ scrAbf3, nullptr, nullptr, nullptr }};
        launch_bf<128, 2>(0, af2, 1, 768, 768, w_diff2, 384, diff_b2, logit_diff, diff_w3, 1);
    }

    // s2: consistency (rows 6,7), head-fused layer 2
    {
        APtrsB a = {{ bimg, btxt, beimg, betxt }};
        launch_bf<128, 1>(s2, a, 2, 768, 1536, w_cons1, 768, cons_b1, scrAbf, nullptr, 1);
        APtrsB a2 = {{ scrAbf, scrAbf + (size_t)NB * 768, nullptr, nullptr }};
        launch_bf<128, 2>(s2, a2, 2, 768, 768, w_cons2, 384, cons_b2, logit_cons, cons_w3, 1);
        cudaEventRecord(e2, s2);
    }

    // join: all logits complete -> one sigmoid pass -> overall
    cudaStreamWaitEvent(0, e1, 0);
    cudaStreamWaitEvent(0, e2, 0);
    sig_all_k<<<(11 * NB + 255) / 256, 256>>>(logit, imp_b2, disc_b3, cons_b3, diff_b3, out);
    overall_k<<<NB / 256, 256>>>(out);
}